// round 1
// baseline (speedup 1.0000x reference)
#include <cuda_runtime.h>
#include <math.h>

#define NL 6
#define NB 2
#define NF 16
#define NT 64
#define NS 1024
#define NE 768
#define NH 12
#define DK 64
#define DFF 3072
#define NM (NB*NS)        // 2048 rows
#define EPS 1e-5f

// ---- scratch (allocation-free rule: __device__ globals) ----
__device__ float g_x[NM*NE];
__device__ float g_q[NM*NE];
__device__ float g_k[NM*NE];
__device__ float g_v[NM*NE];
__device__ float g_ctx[NM*NE];
__device__ float g_tmp[NM*NE];
__device__ float g_hid[NM*DFF];
__device__ int   g_pad[NB*NS];

// ---------------------------------------------------------------------------
// x = x_in + t_pos(frame) + s_pos(token)
// ---------------------------------------------------------------------------
__global__ void add_pos_kernel(const float* __restrict__ x,
                               const float* __restrict__ tpos,
                               const float* __restrict__ spos) {
    int i = blockIdx.x * blockDim.x + threadIdx.x;
    if (i >= NM * NE) return;
    int e = i % NE;
    int s = (i / NE) % NS;
    g_x[i] = x[i] + tpos[(s / NT) * NE + e] + spos[(s % NT) * NE + e];
}

__global__ void pad_kernel() {
    int i = blockIdx.x * blockDim.x + threadIdx.x;
    if (i < NB * NS) g_pad[i] = (g_x[(size_t)i * NE] == 0.0f) ? 1 : 0;
}

// ---------------------------------------------------------------------------
// Generic fp32 GEMM: C[M,N] = A[M,K] @ B[K,N]  (row-major, dims mult of 64/16)
// 64x64 block tile, BK=16, 256 threads, 4x4 per thread.
// ---------------------------------------------------------------------------
template <bool RELU>
__global__ void gemm64_kernel(const float* __restrict__ A,
                              const float* __restrict__ Bm,
                              float* __restrict__ C,
                              int M, int N, int K) {
    __shared__ float As[16][68];   // transposed: As[kk][m]
    __shared__ float Bs[16][68];
    int tid = threadIdx.x;
    int tx = tid & 15, ty = tid >> 4;
    int bm = blockIdx.y * 64, bn = blockIdx.x * 64;
    float acc[4][4] = {};

    for (int k0 = 0; k0 < K; k0 += 16) {
        {   // A tile 64x16 -> As[kk][m]
            int r  = tid >> 2;
            int c4 = (tid & 3) * 4;
            float4 v = *(const float4*)(A + (size_t)(bm + r) * K + k0 + c4);
            As[c4 + 0][r] = v.x; As[c4 + 1][r] = v.y;
            As[c4 + 2][r] = v.z; As[c4 + 3][r] = v.w;
        }
        {   // B tile 16x64
            int r  = tid >> 4;
            int c4 = (tid & 15) * 4;
            float4 v = *(const float4*)(Bm + (size_t)(k0 + r) * N + bn + c4);
            Bs[r][c4 + 0] = v.x; Bs[r][c4 + 1] = v.y;
            Bs[r][c4 + 2] = v.z; Bs[r][c4 + 3] = v.w;
        }
        __syncthreads();
#pragma unroll
        for (int kk = 0; kk < 16; kk++) {
            float a[4], b[4];
#pragma unroll
            for (int i = 0; i < 4; i++) a[i] = As[kk][ty * 4 + i];
#pragma unroll
            for (int j = 0; j < 4; j++) b[j] = Bs[kk][tx * 4 + j];
#pragma unroll
            for (int i = 0; i < 4; i++)
#pragma unroll
                for (int j = 0; j < 4; j++)
                    acc[i][j] += a[i] * b[j];
        }
        __syncthreads();
    }
#pragma unroll
    for (int i = 0; i < 4; i++) {
        int r = bm + ty * 4 + i;
        float4 v;
        v.x = acc[i][0]; v.y = acc[i][1]; v.z = acc[i][2]; v.w = acc[i][3];
        if (RELU) {
            v.x = fmaxf(v.x, 0.f); v.y = fmaxf(v.y, 0.f);
            v.z = fmaxf(v.z, 0.f); v.w = fmaxf(v.w, 0.f);
        }
        *(float4*)(C + (size_t)r * N + bn + tx * 4) = v;
    }
}

// ---------------------------------------------------------------------------
// scores[q,k] = (q.k)*scale, masked (-1e9) for k>q or pad[k].
// One block per (kt, qt, bh) 64x64 tile; causal tiles kt<=qt only.
// Writes straight into attn section of d_out.
// ---------------------------------------------------------------------------
__global__ void scores_kernel(const float* __restrict__ q,
                              const float* __restrict__ k,
                              float* __restrict__ attn) {
    int kt = blockIdx.x, qt = blockIdx.y, bh = blockIdx.z;
    if (kt > qt) return;
    int b = bh / NH, h = bh % NH;

    __shared__ float Qs[64][65];
    __shared__ float Ks[64][65];
    int tid = threadIdx.x;
    {
        int r = tid >> 2;
        int c = (tid & 3) * 16;
        const float* qp = q + ((size_t)(b * NS + qt * 64 + r)) * NE + h * DK + c;
        const float* kp = k + ((size_t)(b * NS + kt * 64 + r)) * NE + h * DK + c;
#pragma unroll
        for (int j = 0; j < 16; j += 4) {
            float4 v = *(const float4*)(qp + j);
            Qs[r][c + j] = v.x; Qs[r][c + j + 1] = v.y;
            Qs[r][c + j + 2] = v.z; Qs[r][c + j + 3] = v.w;
            float4 w = *(const float4*)(kp + j);
            Ks[r][c + j] = w.x; Ks[r][c + j + 1] = w.y;
            Ks[r][c + j + 2] = w.z; Ks[r][c + j + 3] = w.w;
        }
    }
    __syncthreads();

    int tx = tid & 15, ty = tid >> 4;
    float acc[4][4] = {};
#pragma unroll
    for (int kk = 0; kk < 64; kk++) {
        float a[4], bb[4];
#pragma unroll
        for (int i = 0; i < 4; i++) a[i] = Qs[ty * 4 + i][kk];
#pragma unroll
        for (int j = 0; j < 4; j++) bb[j] = Ks[tx * 4 + j][kk];
#pragma unroll
        for (int i = 0; i < 4; i++)
#pragma unroll
            for (int j = 0; j < 4; j++)
                acc[i][j] += a[i] * bb[j];
    }

    float* out = attn + (size_t)bh * NS * NS;
    const float scale = 0.125f;   // 1/sqrt(64)
#pragma unroll
    for (int i = 0; i < 4; i++) {
        int qi = qt * 64 + ty * 4 + i;
#pragma unroll
        for (int j = 0; j < 4; j++) {
            int ki = kt * 64 + tx * 4 + j;
            float v = acc[i][j] * scale;
            if (ki > qi || g_pad[b * NS + ki]) v = -1e9f;
            out[(size_t)qi * NS + ki] = v;
        }
    }
}

// ---------------------------------------------------------------------------
// Row softmax over k in [0, q]; zeros written for k > q (causal).
// grid (NS, NB*NH), 256 threads.
// ---------------------------------------------------------------------------
__global__ void softmax_kernel(float* __restrict__ attn) {
    int q  = blockIdx.x;
    int bh = blockIdx.y;
    float* row = attn + (size_t)bh * NS * NS + (size_t)q * NS;
    int n = q + 1;

    __shared__ float buf[NS];
    __shared__ float red[8];
    int tid = threadIdx.x;

    float m = -1e30f;
    for (int i = tid; i < n; i += 256) { float v = row[i]; buf[i] = v; m = fmaxf(m, v); }
#pragma unroll
    for (int o = 16; o; o >>= 1) m = fmaxf(m, __shfl_xor_sync(0xffffffffu, m, o));
    if ((tid & 31) == 0) red[tid >> 5] = m;
    __syncthreads();
    if (tid < 32) {
        float r = (tid < 8) ? red[tid] : -1e30f;
#pragma unroll
        for (int o = 4; o; o >>= 1) r = fmaxf(r, __shfl_xor_sync(0xffffffffu, r, o));
        if (tid == 0) red[0] = r;
    }
    __syncthreads();
    float mx = red[0];
    __syncthreads();

    float s = 0.f;
    for (int i = tid; i < n; i += 256) { float e = expf(buf[i] - mx); buf[i] = e; s += e; }
#pragma unroll
    for (int o = 16; o; o >>= 1) s += __shfl_xor_sync(0xffffffffu, s, o);
    if ((tid & 31) == 0) red[tid >> 5] = s;
    __syncthreads();
    if (tid < 32) {
        float r = (tid < 8) ? red[tid] : 0.f;
#pragma unroll
        for (int o = 4; o; o >>= 1) r += __shfl_xor_sync(0xffffffffu, r, o);
        if (tid == 0) red[0] = r;
    }
    __syncthreads();
    float inv = 1.0f / red[0];

    for (int i = tid; i < n; i += 256) row[i] = buf[i] * inv;
    for (int i = n + tid; i < NS; i += 256) row[i] = 0.0f;
}

// ---------------------------------------------------------------------------
// ctx[b, q, h*64+d] = sum_k attn[bh,q,k] * v[b,k, h*64+d]; k loop stops at
// causal boundary (attn is exactly 0 beyond it).
// grid (16 qtiles, 24 bh), 256 threads, 64x64 tile.
// ---------------------------------------------------------------------------
__global__ void ctx_kernel(const float* __restrict__ attn,
                           const float* __restrict__ v) {
    int qt = blockIdx.x, bh = blockIdx.y;
    int b = bh / NH, h = bh % NH;
    const float* arow = attn + (size_t)bh * NS * NS;

    __shared__ float As[64][65];
    __shared__ float Vs[64][65];
    int tid = threadIdx.x;
    int tx = tid & 15, ty = tid >> 4;
    float acc[4][4] = {};

    for (int kt = 0; kt <= qt; kt++) {
        {
            int r = tid >> 2;
            int c = (tid & 3) * 16;
            const float* ap = arow + (size_t)(qt * 64 + r) * NS + kt * 64 + c;
            const float* vp = v + ((size_t)(b * NS + kt * 64 + r)) * NE + h * DK + c;
#pragma unroll
            for (int j = 0; j < 16; j += 4) {
                float4 a4 = *(const float4*)(ap + j);
                As[r][c + j] = a4.x; As[r][c + j + 1] = a4.y;
                As[r][c + j + 2] = a4.z; As[r][c + j + 3] = a4.w;
                float4 v4 = *(const float4*)(vp + j);
                Vs[r][c + j] = v4.x; Vs[r][c + j + 1] = v4.y;
                Vs[r][c + j + 2] = v4.z; Vs[r][c + j + 3] = v4.w;
            }
        }
        __syncthreads();
#pragma unroll
        for (int kk = 0; kk < 64; kk++) {
            float a[4], bb[4];
#pragma unroll
            for (int i = 0; i < 4; i++) a[i] = As[ty * 4 + i][kk];
#pragma unroll
            for (int j = 0; j < 4; j++) bb[j] = Vs[kk][tx * 4 + j];
#pragma unroll
            for (int i = 0; i < 4; i++)
#pragma unroll
                for (int j = 0; j < 4; j++)
                    acc[i][j] += a[i] * bb[j];
        }
        __syncthreads();
    }
#pragma unroll
    for (int i = 0; i < 4; i++) {
        int qi = qt * 64 + ty * 4 + i;
        float4 o;
        o.x = acc[i][0]; o.y = acc[i][1]; o.z = acc[i][2]; o.w = acc[i][3];
        *(float4*)(g_ctx + ((size_t)(b * NS + qi)) * NE + h * DK + tx * 4) = o;
    }
}

// ---------------------------------------------------------------------------
// x = LayerNorm(y + x) * g + b   (in place on xio). One block per row.
// ---------------------------------------------------------------------------
__global__ void ln_kernel(const float* __restrict__ y,
                          float* __restrict__ xio,
                          const float* __restrict__ gamma,
                          const float* __restrict__ beta) {
    int row = blockIdx.x;
    __shared__ float buf[NE];
    __shared__ float red[8];
    int tid = threadIdx.x;

    float s = 0.f;
    for (int i = tid; i < NE; i += 256) {
        float v = y[(size_t)row * NE + i] + xio[(size_t)row * NE + i];
        buf[i] = v;
        s += v;
    }
#pragma unroll
    for (int o = 16; o; o >>= 1) s += __shfl_xor_sync(0xffffffffu, s, o);
    if ((tid & 31) == 0) red[tid >> 5] = s;
    __syncthreads();
    if (tid < 32) {
        float r = (tid < 8) ? red[tid] : 0.f;
#pragma unroll
        for (int o = 4; o; o >>= 1) r += __shfl_xor_sync(0xffffffffu, r, o);
        if (tid == 0) red[0] = r;
    }
    __syncthreads();
    float mean = red[0] * (1.0f / NE);
    __syncthreads();

    float vs = 0.f;
    for (int i = tid; i < NE; i += 256) {
        float d = buf[i] - mean;
        vs += d * d;
    }
#pragma unroll
    for (int o = 16; o; o >>= 1) vs += __shfl_xor_sync(0xffffffffu, vs, o);
    if ((tid & 31) == 0) red[tid >> 5] = vs;
    __syncthreads();
    if (tid < 32) {
        float r = (tid < 8) ? red[tid] : 0.f;
#pragma unroll
        for (int o = 4; o; o >>= 1) r += __shfl_xor_sync(0xffffffffu, r, o);
        if (tid == 0) red[0] = r;
    }
    __syncthreads();
    float rstd = rsqrtf(red[0] * (1.0f / NE) + EPS);

    for (int i = tid; i < NE; i += 256) {
        xio[(size_t)row * NE + i] = (buf[i] - mean) * rstd * gamma[i] + beta[i];
    }
}

__global__ void copy_x_kernel(float* __restrict__ out) {
    int i = blockIdx.x * blockDim.x + threadIdx.x;
    if (i < NM * NE) out[i] = g_x[i];
}

// ---------------------------------------------------------------------------
extern "C" void kernel_launch(void* const* d_in, const int* in_sizes, int n_in,
                              void* d_out, int out_size) {
    const float* x    = (const float*)d_in[0];
    const float* tpos = (const float*)d_in[1];
    const float* spos = (const float*)d_in[2];
    const float* Wq   = (const float*)d_in[3];
    const float* Wk   = (const float*)d_in[4];
    const float* Wv   = (const float*)d_in[5];
    const float* Wo   = (const float*)d_in[6];
    const float* ln1g = (const float*)d_in[7];
    const float* ln1b = (const float*)d_in[8];
    const float* W1   = (const float*)d_in[9];
    const float* W2   = (const float*)d_in[10];
    const float* ln2g = (const float*)d_in[11];
    const float* ln2b = (const float*)d_in[12];

    float* out      = (float*)d_out;
    float* attn_out = out + (size_t)NM * NE;

    float *px, *pq, *pk, *pv, *pctx, *ptmp, *phid;
    cudaGetSymbolAddress((void**)&px,   g_x);
    cudaGetSymbolAddress((void**)&pq,   g_q);
    cudaGetSymbolAddress((void**)&pk,   g_k);
    cudaGetSymbolAddress((void**)&pv,   g_v);
    cudaGetSymbolAddress((void**)&pctx, g_ctx);
    cudaGetSymbolAddress((void**)&ptmp, g_tmp);
    cudaGetSymbolAddress((void**)&phid, g_hid);

    add_pos_kernel<<<(NM * NE + 255) / 256, 256>>>(x, tpos, spos);
    pad_kernel<<<(NB * NS + 255) / 256, 256>>>();

    dim3 gProj(NE / 64, NM / 64);        // (12, 32)
    dim3 gFF1(DFF / 64, NM / 64);        // (48, 32)
    dim3 gScores(NS / 64, NS / 64, NB * NH);  // (16, 16, 24)
    dim3 gSoft(NS, NB * NH);
    dim3 gCtx(NS / 64, NB * NH);

    for (int l = 0; l < NL; l++) {
        const float* wq = Wq + (size_t)l * NE * (NH * DK);
        const float* wk = Wk + (size_t)l * NE * (NH * DK);
        const float* wv = Wv + (size_t)l * NE * (NH * DK);
        const float* wo = Wo + (size_t)l * (NH * DK) * NE;
        const float* w1 = W1 + (size_t)l * NE * DFF;
        const float* w2 = W2 + (size_t)l * DFF * NE;
        float* attn_l = attn_out + (size_t)l * NB * NH * NS * NS;

        gemm64_kernel<false><<<gProj, 256>>>(px, wq, pq, NM, NE, NE);
        gemm64_kernel<false><<<gProj, 256>>>(px, wk, pk, NM, NE, NE);
        gemm64_kernel<false><<<gProj, 256>>>(px, wv, pv, NM, NE, NE);

        scores_kernel<<<gScores, 256>>>(pq, pk, attn_l);
        softmax_kernel<<<gSoft, 256>>>(attn_l);
        ctx_kernel<<<gCtx, 256>>>(attn_l, pv);

        gemm64_kernel<false><<<gProj, 256>>>(pctx, wo, ptmp, NM, NE, NE);
        ln_kernel<<<NM, 256>>>(ptmp, px, ln1g + (size_t)l * NE, ln1b + (size_t)l * NE);

        gemm64_kernel<true ><<<gFF1, 256>>>(px, w1, phid, NM, DFF, NE);
        gemm64_kernel<false><<<gProj, 256>>>(phid, w2, ptmp, NM, NE, DFF);
        ln_kernel<<<NM, 256>>>(ptmp, px, ln2g + (size_t)l * NE, ln2b + (size_t)l * NE);
    }

    copy_x_kernel<<<(NM * NE + 255) / 256, 256>>>(out);
}

// round 3
// speedup vs baseline: 1.1104x; 1.1104x over previous
#include <cuda_runtime.h>
#include <math.h>
#include <stdint.h>

#define NL 6
#define NB 2
#define NF 16
#define NT 64
#define NS 1024
#define NE 768
#define NH 12
#define DK 64
#define DFF 3072
#define NM (NB*NS)        // 2048 rows
#define EPS 1e-5f

// ---- scratch (allocation-free rule: __device__ globals) ----
__device__ float g_x[NM*NE];
__device__ float g_q[NM*NE];
__device__ float g_k[NM*NE];
__device__ float g_v[NM*NE];
__device__ float g_ctx[NM*NE];
__device__ float g_tmp[NM*NE];
__device__ float g_hid[NM*DFF];
__device__ int   g_pad[NB*NS];
// transposed (K-major) weights (full fp32; split happens in-kernel)
__device__ float g_wqt[NL*NE*NE];
__device__ float g_wkt[NL*NE*NE];
__device__ float g_wvt[NL*NE*NE];
__device__ float g_wot[NL*NE*NE];
__device__ float g_w1t[NL*(size_t)NE*DFF];
__device__ float g_w2t[NL*(size_t)NE*DFF];

// ===========================================================================
// Portable (non-'a') PTX helpers: cp.async + mma.sync tf32
// ===========================================================================
__device__ __forceinline__ uint32_t smem_u32(const void* p) {
    uint32_t a;
    asm("{ .reg .u64 t; cvta.to.shared.u64 t, %1; cvt.u32.u64 %0, t; }"
        : "=r"(a) : "l"(p));
    return a;
}
__device__ __forceinline__ void cp16(uint32_t s, const void* g) {
    asm volatile("cp.async.cg.shared.global [%0], [%1], 16;" :: "r"(s), "l"(g));
}
__device__ __forceinline__ void cp_commit() {
    asm volatile("cp.async.commit_group;" ::: "memory");
}
template <int N>
__device__ __forceinline__ void cp_wait() {
    asm volatile("cp.async.wait_group %0;" :: "n"(N) : "memory");
}
__device__ __forceinline__ void split_tf32(float v, uint32_t& hi, uint32_t& lo) {
    asm("cvt.rna.tf32.f32 %0, %1;" : "=r"(hi) : "f"(v));
    float r = v - __uint_as_float(hi);
    asm("cvt.rna.tf32.f32 %0, %1;" : "=r"(lo) : "f"(r));
}
__device__ __forceinline__ void mma8(float* c, const uint32_t* a, const uint32_t* b) {
    asm volatile(
        "mma.sync.aligned.m16n8k8.row.col.f32.tf32.tf32.f32 "
        "{%0,%1,%2,%3},{%4,%5,%6,%7},{%8,%9},{%0,%1,%2,%3};"
        : "+f"(c[0]), "+f"(c[1]), "+f"(c[2]), "+f"(c[3])
        : "r"(a[0]), "r"(a[1]), "r"(a[2]), "r"(a[3]), "r"(b[0]), "r"(b[1]));
}

// ===========================================================================
// weight transpose: out[c*R + r] = in[r*C + c]   (fp32, no rounding)
// ===========================================================================
__global__ void transpose_kernel(const float* __restrict__ in,
                                 float* __restrict__ out, int R, int C) {
    __shared__ float t[32][33];
    int c0 = blockIdx.x * 32, r0 = blockIdx.y * 32;
    int x = threadIdx.x, y = threadIdx.y;   // 32 x 8
#pragma unroll
    for (int i = 0; i < 32; i += 8)
        t[y + i][x] = in[(size_t)(r0 + y + i) * C + c0 + x];
    __syncthreads();
#pragma unroll
    for (int i = 0; i < 32; i += 8)
        out[(size_t)(c0 + y + i) * R + r0 + x] = t[x][y + i];
}

// ===========================================================================
// 3xTF32 mma.sync GEMM: C[M,N] = A[M,K] @ Bt[N,K]^T
// CTA tile BM x BN, BK=32, 256 threads (8 warps, warp tile WM x WN).
// 3-stage cp.async pipeline. Rows padded to 36 floats (conflict-free frags).
// Split a=ah+al, b=bh+bl; D += ah*bh + al*bh + ah*bl (error ~2^-21).
// ===========================================================================
template <int BM, int BN, int WM, int WN, bool RELU>
__global__ void __launch_bounds__(256)
mma_gemm(const float* __restrict__ A, const float* __restrict__ Bt,
         float* __restrict__ C, int M, int N, int K) {
    constexpr int MI = WM / 16;
    constexpr int NI = WN / 8;
    constexpr int WGN = BN / WN;            // warps along n
    constexpr int STG = (BM + BN) * 36;     // floats per stage
    extern __shared__ float smem[];
    uint32_t sbase = smem_u32(smem);

    int tid  = threadIdx.x;
    int lane = tid & 31, wid = tid >> 5;
    int wn = wid % WGN, wm = wid / WGN;
    int g = lane >> 2, t = lane & 3;
    int m0 = blockIdx.y * BM, n0 = blockIdx.x * BN;
    const int nk = K >> 5;

    // --- stage loader: rows [0,BM) from A, rows [BM,BM+BN) from Bt ---
    auto load_stage = [&](int stage, int k0) {
        uint32_t dst0 = sbase + (uint32_t)stage * (STG * 4);
#pragma unroll 4
        for (int idx = tid; idx < (BM + BN) * 8; idx += 256) {
            int r = idx >> 3, c4 = idx & 7;
            const float* src = (r < BM)
                ? A  + (size_t)(m0 + r) * K + k0 + c4 * 4
                : Bt + (size_t)(n0 + r - BM) * K + k0 + c4 * 4;
            cp16(dst0 + (uint32_t)(r * 144 + c4 * 16), src);
        }
    };

    // prologue: 3 stages in flight
#pragma unroll
    for (int s = 0; s < 3; s++) { load_stage(s, s * 32); cp_commit(); }

    float acc[MI][NI][4];
#pragma unroll
    for (int mi = 0; mi < MI; mi++)
#pragma unroll
        for (int ni = 0; ni < NI; ni++)
#pragma unroll
            for (int j = 0; j < 4; j++) acc[mi][ni][j] = 0.f;

    for (int kc = 0; kc < nk; kc++) {
        int s = kc % 3;
        cp_wait<2>();
        __syncthreads();
        const float* As = smem + s * STG;
        const float* Bs = As + BM * 36;

#pragma unroll
        for (int kk = 0; kk < 32; kk += 8) {
            uint32_t ah[MI][4], al[MI][4];
#pragma unroll
            for (int mi = 0; mi < MI; mi++) {
                int rb = wm * WM + mi * 16;
                split_tf32(As[(rb + g)     * 36 + kk + t],     ah[mi][0], al[mi][0]);
                split_tf32(As[(rb + g + 8) * 36 + kk + t],     ah[mi][1], al[mi][1]);
                split_tf32(As[(rb + g)     * 36 + kk + t + 4], ah[mi][2], al[mi][2]);
                split_tf32(As[(rb + g + 8) * 36 + kk + t + 4], ah[mi][3], al[mi][3]);
            }
            uint32_t bh[NI][2], bl[NI][2];
#pragma unroll
            for (int ni = 0; ni < NI; ni++) {
                int nb = wn * WN + ni * 8;
                split_tf32(Bs[(nb + g) * 36 + kk + t],     bh[ni][0], bl[ni][0]);
                split_tf32(Bs[(nb + g) * 36 + kk + t + 4], bh[ni][1], bl[ni][1]);
            }
#pragma unroll
            for (int mi = 0; mi < MI; mi++)
#pragma unroll
                for (int ni = 0; ni < NI; ni++) {
                    mma8(acc[mi][ni], ah[mi], bh[ni]);
                    mma8(acc[mi][ni], al[mi], bh[ni]);
                    mma8(acc[mi][ni], ah[mi], bl[ni]);
                }
        }
        __syncthreads();
        if (kc + 3 < nk) load_stage(s, (kc + 3) * 32);
        cp_commit();
    }

    // epilogue: direct float2 stores
#pragma unroll
    for (int mi = 0; mi < MI; mi++) {
        int row0 = m0 + wm * WM + mi * 16 + g;
#pragma unroll
        for (int ni = 0; ni < NI; ni++) {
            int col = n0 + wn * WN + ni * 8 + 2 * t;
            float2 v0, v1;
            v0.x = acc[mi][ni][0]; v0.y = acc[mi][ni][1];
            v1.x = acc[mi][ni][2]; v1.y = acc[mi][ni][3];
            if (RELU) {
                v0.x = fmaxf(v0.x, 0.f); v0.y = fmaxf(v0.y, 0.f);
                v1.x = fmaxf(v1.x, 0.f); v1.y = fmaxf(v1.y, 0.f);
            }
            *(float2*)(C + (size_t)row0 * N + col)       = v0;
            *(float2*)(C + (size_t)(row0 + 8) * N + col) = v1;
        }
    }
}

// ===========================================================================
// x = x_in + t_pos(frame) + s_pos(token)
// ===========================================================================
__global__ void add_pos_kernel(const float* __restrict__ x,
                               const float* __restrict__ tpos,
                               const float* __restrict__ spos) {
    int i = blockIdx.x * blockDim.x + threadIdx.x;
    if (i >= NM * NE) return;
    int e = i % NE;
    int s = (i / NE) % NS;
    g_x[i] = x[i] + tpos[(s / NT) * NE + e] + spos[(s % NT) * NE + e];
}

__global__ void pad_kernel() {
    int i = blockIdx.x * blockDim.x + threadIdx.x;
    if (i < NB * NS) g_pad[i] = (g_x[(size_t)i * NE] == 0.0f) ? 1 : 0;
}

// ===========================================================================
// scores[q,k] = (q.k)*scale, masked (-1e9) for k>q or pad[k].
// ===========================================================================
__global__ void scores_kernel(const float* __restrict__ q,
                              const float* __restrict__ k,
                              float* __restrict__ attn) {
    int kt = blockIdx.x, qt = blockIdx.y, bh = blockIdx.z;
    if (kt > qt) return;
    int b = bh / NH, h = bh % NH;

    __shared__ float Qs[64][65];
    __shared__ float Ks[64][65];
    int tid = threadIdx.x;
    {
        int r = tid >> 2;
        int c = (tid & 3) * 16;
        const float* qp = q + ((size_t)(b * NS + qt * 64 + r)) * NE + h * DK + c;
        const float* kp = k + ((size_t)(b * NS + kt * 64 + r)) * NE + h * DK + c;
#pragma unroll
        for (int j = 0; j < 16; j += 4) {
            float4 v = *(const float4*)(qp + j);
            Qs[r][c + j] = v.x; Qs[r][c + j + 1] = v.y;
            Qs[r][c + j + 2] = v.z; Qs[r][c + j + 3] = v.w;
            float4 w = *(const float4*)(kp + j);
            Ks[r][c + j] = w.x; Ks[r][c + j + 1] = w.y;
            Ks[r][c + j + 2] = w.z; Ks[r][c + j + 3] = w.w;
        }
    }
    __syncthreads();

    int tx = tid & 15, ty = tid >> 4;
    float acc[4][4] = {};
#pragma unroll
    for (int kk = 0; kk < 64; kk++) {
        float a[4], bb[4];
#pragma unroll
        for (int i = 0; i < 4; i++) a[i] = Qs[ty * 4 + i][kk];
#pragma unroll
        for (int j = 0; j < 4; j++) bb[j] = Ks[tx * 4 + j][kk];
#pragma unroll
        for (int i = 0; i < 4; i++)
#pragma unroll
            for (int j = 0; j < 4; j++)
                acc[i][j] += a[i] * bb[j];
    }

    float* out = attn + (size_t)bh * NS * NS;
    const float scale = 0.125f;
#pragma unroll
    for (int i = 0; i < 4; i++) {
        int qi = qt * 64 + ty * 4 + i;
#pragma unroll
        for (int j = 0; j < 4; j++) {
            int ki = kt * 64 + tx * 4 + j;
            float v = acc[i][j] * scale;
            if (ki > qi || g_pad[b * NS + ki]) v = -1e9f;
            out[(size_t)qi * NS + ki] = v;
        }
    }
}

// ===========================================================================
// Row softmax over k in [0, q]; zeros for k > q.
// ===========================================================================
__global__ void softmax_kernel(float* __restrict__ attn) {
    int q  = blockIdx.x;
    int bh = blockIdx.y;
    float* row = attn + (size_t)bh * NS * NS + (size_t)q * NS;
    int n = q + 1;

    __shared__ float buf[NS];
    __shared__ float red[8];
    int tid = threadIdx.x;

    float m = -1e30f;
    for (int i = tid; i < n; i += 256) { float v = row[i]; buf[i] = v; m = fmaxf(m, v); }
#pragma unroll
    for (int o = 16; o; o >>= 1) m = fmaxf(m, __shfl_xor_sync(0xffffffffu, m, o));
    if ((tid & 31) == 0) red[tid >> 5] = m;
    __syncthreads();
    if (tid < 32) {
        float r = (tid < 8) ? red[tid] : -1e30f;
#pragma unroll
        for (int o = 4; o; o >>= 1) r = fmaxf(r, __shfl_xor_sync(0xffffffffu, r, o));
        if (tid == 0) red[0] = r;
    }
    __syncthreads();
    float mx = red[0];
    __syncthreads();

    float s = 0.f;
    for (int i = tid; i < n; i += 256) { float e = expf(buf[i] - mx); buf[i] = e; s += e; }
#pragma unroll
    for (int o = 16; o; o >>= 1) s += __shfl_xor_sync(0xffffffffu, s, o);
    if ((tid & 31) == 0) red[tid >> 5] = s;
    __syncthreads();
    if (tid < 32) {
        float r = (tid < 8) ? red[tid] : 0.f;
#pragma unroll
        for (int o = 4; o; o >>= 1) r += __shfl_xor_sync(0xffffffffu, r, o);
        if (tid == 0) red[0] = r;
    }
    __syncthreads();
    float inv = 1.0f / red[0];

    for (int i = tid; i < n; i += 256) row[i] = buf[i] * inv;
    for (int i = n + tid; i < NS; i += 256) row[i] = 0.0f;
}

// ===========================================================================
// ctx = attn @ v (causal-truncated)
// ===========================================================================
__global__ void ctx_kernel(const float* __restrict__ attn,
                           const float* __restrict__ v) {
    int qt = blockIdx.x, bh = blockIdx.y;
    int b = bh / NH, h = bh % NH;
    const float* arow = attn + (size_t)bh * NS * NS;

    __shared__ float As[64][65];
    __shared__ float Vs[64][65];
    int tid = threadIdx.x;
    int tx = tid & 15, ty = tid >> 4;
    float acc[4][4] = {};

    for (int kt = 0; kt <= qt; kt++) {
        {
            int r = tid >> 2;
            int c = (tid & 3) * 16;
            const float* ap = arow + (size_t)(qt * 64 + r) * NS + kt * 64 + c;
            const float* vp = v + ((size_t)(b * NS + kt * 64 + r)) * NE + h * DK + c;
#pragma unroll
            for (int j = 0; j < 16; j += 4) {
                float4 a4 = *(const float4*)(ap + j);
                As[r][c + j] = a4.x; As[r][c + j + 1] = a4.y;
                As[r][c + j + 2] = a4.z; As[r][c + j + 3] = a4.w;
                float4 v4 = *(const float4*)(vp + j);
                Vs[r][c + j] = v4.x; Vs[r][c + j + 1] = v4.y;
                Vs[r][c + j + 2] = v4.z; Vs[r][c + j + 3] = v4.w;
            }
        }
        __syncthreads();
#pragma unroll
        for (int kk = 0; kk < 64; kk++) {
            float a[4], bb[4];
#pragma unroll
            for (int i = 0; i < 4; i++) a[i] = As[ty * 4 + i][kk];
#pragma unroll
            for (int j = 0; j < 4; j++) bb[j] = Vs[kk][tx * 4 + j];
#pragma unroll
            for (int i = 0; i < 4; i++)
#pragma unroll
                for (int j = 0; j < 4; j++)
                    acc[i][j] += a[i] * bb[j];
        }
        __syncthreads();
    }
#pragma unroll
    for (int i = 0; i < 4; i++) {
        int qi = qt * 64 + ty * 4 + i;
        float4 o;
        o.x = acc[i][0]; o.y = acc[i][1]; o.z = acc[i][2]; o.w = acc[i][3];
        *(float4*)(g_ctx + ((size_t)(b * NS + qi)) * NE + h * DK + tx * 4) = o;
    }
}

// ===========================================================================
// x = LayerNorm(y + x) * g + b   (in place on xio)
// ===========================================================================
__global__ void ln_kernel(const float* __restrict__ y,
                          float* __restrict__ xio,
                          const float* __restrict__ gamma,
                          const float* __restrict__ beta) {
    int row = blockIdx.x;
    __shared__ float buf[NE];
    __shared__ float red[8];
    int tid = threadIdx.x;

    float s = 0.f;
    for (int i = tid; i < NE; i += 256) {
        float v = y[(size_t)row * NE + i] + xio[(size_t)row * NE + i];
        buf[i] = v;
        s += v;
    }
#pragma unroll
    for (int o = 16; o; o >>= 1) s += __shfl_xor_sync(0xffffffffu, s, o);
    if ((tid & 31) == 0) red[tid >> 5] = s;
    __syncthreads();
    if (tid < 32) {
        float r = (tid < 8) ? red[tid] : 0.f;
#pragma unroll
        for (int o = 4; o; o >>= 1) r += __shfl_xor_sync(0xffffffffu, r, o);
        if (tid == 0) red[0] = r;
    }
    __syncthreads();
    float mean = red[0] * (1.0f / NE);
    __syncthreads();

    float vs = 0.f;
    for (int i = tid; i < NE; i += 256) {
        float d = buf[i] - mean;
        vs += d * d;
    }
#pragma unroll
    for (int o = 16; o; o >>= 1) vs += __shfl_xor_sync(0xffffffffu, vs, o);
    if ((tid & 31) == 0) red[tid >> 5] = vs;
    __syncthreads();
    if (tid < 32) {
        float r = (tid < 8) ? red[tid] : 0.f;
#pragma unroll
        for (int o = 4; o; o >>= 1) r += __shfl_xor_sync(0xffffffffu, r, o);
        if (tid == 0) red[0] = r;
    }
    __syncthreads();
    float rstd = rsqrtf(red[0] * (1.0f / NE) + EPS);

    for (int i = tid; i < NE; i += 256) {
        xio[(size_t)row * NE + i] = (buf[i] - mean) * rstd * gamma[i] + beta[i];
    }
}

__global__ void copy_x_kernel(float* __restrict__ out) {
    int i = blockIdx.x * blockDim.x + threadIdx.x;
    if (i < NM * NE) out[i] = g_x[i];
}

// ===========================================================================
extern "C" void kernel_launch(void* const* d_in, const int* in_sizes, int n_in,
                              void* d_out, int out_size) {
    const float* x    = (const float*)d_in[0];
    const float* tpos = (const float*)d_in[1];
    const float* spos = (const float*)d_in[2];
    const float* Wq   = (const float*)d_in[3];
    const float* Wk   = (const float*)d_in[4];
    const float* Wv   = (const float*)d_in[5];
    const float* Wo   = (const float*)d_in[6];
    const float* ln1g = (const float*)d_in[7];
    const float* ln1b = (const float*)d_in[8];
    const float* W1   = (const float*)d_in[9];
    const float* W2   = (const float*)d_in[10];
    const float* ln2g = (const float*)d_in[11];
    const float* ln2b = (const float*)d_in[12];

    float* out      = (float*)d_out;
    float* attn_out = out + (size_t)NM * NE;

    float *px, *pq, *pk, *pv, *pctx, *ptmp, *phid;
    float *pwqt, *pwkt, *pwvt, *pwot, *pw1t, *pw2t;
    cudaGetSymbolAddress((void**)&px,   g_x);
    cudaGetSymbolAddress((void**)&pq,   g_q);
    cudaGetSymbolAddress((void**)&pk,   g_k);
    cudaGetSymbolAddress((void**)&pv,   g_v);
    cudaGetSymbolAddress((void**)&pctx, g_ctx);
    cudaGetSymbolAddress((void**)&ptmp, g_tmp);
    cudaGetSymbolAddress((void**)&phid, g_hid);
    cudaGetSymbolAddress((void**)&pwqt, g_wqt);
    cudaGetSymbolAddress((void**)&pwkt, g_wkt);
    cudaGetSymbolAddress((void**)&pwvt, g_wvt);
    cudaGetSymbolAddress((void**)&pwot, g_wot);
    cudaGetSymbolAddress((void**)&pw1t, g_w1t);
    cudaGetSymbolAddress((void**)&pw2t, g_w2t);

    // smem sizes: big tile = (128+128)*36*4*3 = 110,592 B; small = 82,944 B
    const int SM_BIG   = (128 + 128) * 36 * 4 * 3;
    const int SM_SMALL = (64 + 128) * 36 * 4 * 3;
    cudaFuncSetAttribute(mma_gemm<128,128,32,64,true>,
        cudaFuncAttributeMaxDynamicSharedMemorySize, SM_BIG);
    cudaFuncSetAttribute(mma_gemm<64,128,32,32,false>,
        cudaFuncAttributeMaxDynamicSharedMemorySize, SM_SMALL);

    add_pos_kernel<<<(NM * NE + 255) / 256, 256>>>(x, tpos, spos);
    pad_kernel<<<(NB * NS + 255) / 256, 256>>>();

    // transpose all weights to K-major
    {
        dim3 blk(32, 8);
        dim3 gEE(NE / 32, NE / 32);
        dim3 gE_F(DFF / 32, NE / 32);    // W1 [768,3072] -> [3072,768]
        dim3 gF_E(NE / 32, DFF / 32);    // W2 [3072,768] -> [768,3072]
        for (int l = 0; l < NL; l++) {
            transpose_kernel<<<gEE, blk>>>(Wq + (size_t)l * NE * NE, pwqt + (size_t)l * NE * NE, NE, NE);
            transpose_kernel<<<gEE, blk>>>(Wk + (size_t)l * NE * NE, pwkt + (size_t)l * NE * NE, NE, NE);
            transpose_kernel<<<gEE, blk>>>(Wv + (size_t)l * NE * NE, pwvt + (size_t)l * NE * NE, NE, NE);
            transpose_kernel<<<gEE, blk>>>(Wo + (size_t)l * NE * NE, pwot + (size_t)l * NE * NE, NE, NE);
            transpose_kernel<<<gE_F, blk>>>(W1 + (size_t)l * NE * DFF, pw1t + (size_t)l * NE * DFF, NE, DFF);
            transpose_kernel<<<gF_E, blk>>>(W2 + (size_t)l * NE * DFF, pw2t + (size_t)l * NE * DFF, DFF, NE);
        }
    }

    dim3 gProj(NE / 128, NM / 64);             // (6, 32)  64x128 tiles
    dim3 gFF1(DFF / 128, NM / 128);            // (24, 16) 128x128 tiles
    dim3 gScores(NS / 64, NS / 64, NB * NH);
    dim3 gSoft(NS, NB * NH);
    dim3 gCtx(NS / 64, NB * NH);

    for (int l = 0; l < NL; l++) {
        float* wqt = pwqt + (size_t)l * NE * NE;
        float* wkt = pwkt + (size_t)l * NE * NE;
        float* wvt = pwvt + (size_t)l * NE * NE;
        float* wot = pwot + (size_t)l * NE * NE;
        float* w1t = pw1t + (size_t)l * NE * DFF;
        float* w2t = pw2t + (size_t)l * NE * DFF;
        float* attn_l = attn_out + (size_t)l * NB * NH * NS * NS;

        mma_gemm<64,128,32,32,false><<<gProj, 256, SM_SMALL>>>(px, wqt, pq, NM, NE, NE);
        mma_gemm<64,128,32,32,false><<<gProj, 256, SM_SMALL>>>(px, wkt, pk, NM, NE, NE);
        mma_gemm<64,128,32,32,false><<<gProj, 256, SM_SMALL>>>(px, wvt, pv, NM, NE, NE);

        scores_kernel<<<gScores, 256>>>(pq, pk, attn_l);
        softmax_kernel<<<gSoft, 256>>>(attn_l);
        ctx_kernel<<<gCtx, 256>>>(attn_l, pv);

        mma_gemm<64,128,32,32,false><<<gProj, 256, SM_SMALL>>>(pctx, wot, ptmp, NM, NE, NE);
        ln_kernel<<<NM, 256>>>(ptmp, px, ln1g + (size_t)l * NE, ln1b + (size_t)l * NE);

        mma_gemm<128,128,32,64,true><<<gFF1, 256, SM_BIG>>>(px, w1t, phid, NM, DFF, NE);
        mma_gemm<64,128,32,32,false><<<gProj, 256, SM_SMALL>>>(phid, w2t, ptmp, NM, NE, DFF);
        ln_kernel<<<NM, 256>>>(ptmp, px, ln2g + (size_t)l * NE, ln2b + (size_t)l * NE);
    }

    copy_x_kernel<<<(NM * NE + 255) / 256, 256>>>(out);
}

// round 4
// speedup vs baseline: 1.6008x; 1.4416x over previous
#include <cuda_runtime.h>
#include <cuda_bf16.h>
#include <math.h>
#include <stdint.h>

#define NL 6
#define NB 2
#define NF 16
#define NT 64
#define NS 1024
#define NE 768
#define NH 12
#define DK 64
#define DFF 3072
#define NM (NB*NS)        // 2048 rows
#define EPS 1e-5f

// ---- scratch (allocation-free rule: __device__ globals) ----
__device__ float g_x[NM*NE];
__device__ float g_q[NM*NE];
__device__ float g_k[NM*NE];
__device__ float g_v[NM*NE];
__device__ float g_tmp[NM*NE];
__device__ int   g_pad[NB*NS];
// bf16 split planes for activations
__device__ __nv_bfloat16 g_xh[NM*NE],  g_xl[NM*NE];
__device__ __nv_bfloat16 g_ch[NM*NE],  g_cl[NM*NE];          // ctx
__device__ __nv_bfloat16 g_hh[NM*DFF], g_hl[NM*DFF];         // hidden
// bf16 split planes for K-major transposed weights
__device__ __nv_bfloat16 g_wqh[NL*NE*NE], g_wql[NL*NE*NE];
__device__ __nv_bfloat16 g_wkh[NL*NE*NE], g_wkl[NL*NE*NE];
__device__ __nv_bfloat16 g_wvh[NL*NE*NE], g_wvl[NL*NE*NE];
__device__ __nv_bfloat16 g_woh[NL*NE*NE], g_wol[NL*NE*NE];
__device__ __nv_bfloat16 g_w1h[NL*(size_t)NE*DFF], g_w1l[NL*(size_t)NE*DFF];
__device__ __nv_bfloat16 g_w2h[NL*(size_t)NE*DFF], g_w2l[NL*(size_t)NE*DFF];

// ===========================================================================
// PTX helpers (all base-sm_103 features: cp.async, ldmatrix, mma.sync bf16)
// ===========================================================================
__device__ __forceinline__ uint32_t smem_u32(const void* p) {
    uint32_t a;
    asm("{ .reg .u64 t; cvta.to.shared.u64 t, %1; cvt.u32.u64 %0, t; }"
        : "=r"(a) : "l"(p));
    return a;
}
__device__ __forceinline__ void cp16(uint32_t s, const void* g) {
    asm volatile("cp.async.cg.shared.global [%0], [%1], 16;" :: "r"(s), "l"(g));
}
__device__ __forceinline__ void cp_commit() {
    asm volatile("cp.async.commit_group;" ::: "memory");
}
template <int N>
__device__ __forceinline__ void cp_wait() {
    asm volatile("cp.async.wait_group %0;" :: "n"(N) : "memory");
}
__device__ __forceinline__ void ldsm4(uint32_t* r, uint32_t addr) {
    asm volatile("ldmatrix.sync.aligned.m8n8.x4.shared.b16 {%0,%1,%2,%3}, [%4];"
        : "=r"(r[0]), "=r"(r[1]), "=r"(r[2]), "=r"(r[3]) : "r"(addr));
}
__device__ __forceinline__ void mma16816(float* c, const uint32_t* a, const uint32_t* b) {
    asm volatile(
        "mma.sync.aligned.m16n8k16.row.col.f32.bf16.bf16.f32 "
        "{%0,%1,%2,%3},{%4,%5,%6,%7},{%8,%9},{%0,%1,%2,%3};"
        : "+f"(c[0]), "+f"(c[1]), "+f"(c[2]), "+f"(c[3])
        : "r"(a[0]), "r"(a[1]), "r"(a[2]), "r"(a[3]), "r"(b[0]), "r"(b[1]));
}
__device__ __forceinline__ void split1(float v, __nv_bfloat16& h, __nv_bfloat16& l) {
    h = __float2bfloat16_rn(v);
    l = __float2bfloat16_rn(v - __bfloat162float(h));
}

// ===========================================================================
// weight transpose + bf16 split: oh/ol[c*R + r] = split(in[r*C + c])
// ===========================================================================
__global__ void transpose_split_kernel(const float* __restrict__ in,
                                       __nv_bfloat16* __restrict__ oh,
                                       __nv_bfloat16* __restrict__ ol,
                                       int R, int C) {
    __shared__ float t[32][33];
    int c0 = blockIdx.x * 32, r0 = blockIdx.y * 32;
    int x = threadIdx.x, y = threadIdx.y;   // 32 x 8
#pragma unroll
    for (int i = 0; i < 32; i += 8)
        t[y + i][x] = in[(size_t)(r0 + y + i) * C + c0 + x];
    __syncthreads();
#pragma unroll
    for (int i = 0; i < 32; i += 8) {
        float v = t[x][y + i];
        __nv_bfloat16 h, l;
        split1(v, h, l);
        size_t o = (size_t)(c0 + y + i) * R + r0 + x;
        oh[o] = h; ol[o] = l;
    }
}

// ===========================================================================
// bf16x3 mma GEMM: C[M,N] = (Ah+Al)[M,K] @ (Bh+Bl)[N,K]^T
// CTA tile BM x BN, BK=32, 256 threads. 3-stage cp.async pipeline.
// smem row stride 80 B (16B aligned, conflict-free ldmatrix).
// MODE 0: fp32 out C.  MODE 1: relu + bf16-split out (Ch, Cl).
// ===========================================================================
template <int BM, int BN, int WM, int WN, int MODE>
__global__ void __launch_bounds__(256)
bf16_gemm(const __nv_bfloat16* __restrict__ Ah, const __nv_bfloat16* __restrict__ Al,
          const __nv_bfloat16* __restrict__ Bh, const __nv_bfloat16* __restrict__ Bl,
          float* __restrict__ C,
          __nv_bfloat16* __restrict__ Ch, __nv_bfloat16* __restrict__ Cl,
          int M, int N, int K) {
    constexpr int MI = WM / 16;
    constexpr int NI = WN / 8;
    constexpr int WGN = BN / WN;
    constexpr int ROWS = 2 * (BM + BN);
    constexpr uint32_t SSTR = (uint32_t)ROWS * 80;     // bytes per stage
    constexpr uint32_t OFF_AH = 0;
    constexpr uint32_t OFF_AL = (uint32_t)BM * 80;
    constexpr uint32_t OFF_BH = (uint32_t)(2 * BM) * 80;
    constexpr uint32_t OFF_BL = (uint32_t)(2 * BM + BN) * 80;

    extern __shared__ char smem[];
    uint32_t sbase = smem_u32(smem);
    int tid = threadIdx.x, lane = tid & 31, wid = tid >> 5;
    int wn = wid % WGN, wm = wid / WGN;
    int g = lane >> 2, t = lane & 3;
    int m0 = blockIdx.y * BM, n0 = blockIdx.x * BN;
    const int nk = K >> 5;

    auto load_stage = [&](int stage, int k0) {
        uint32_t dst0 = sbase + (uint32_t)stage * SSTR;
#pragma unroll
        for (int idx = tid; idx < ROWS * 4; idx += 256) {
            int r = idx >> 2, c = idx & 3;
            const __nv_bfloat16* src;
            if (r < BM)               src = Ah + (size_t)(m0 + r) * K;
            else if (r < 2 * BM)      src = Al + (size_t)(m0 + r - BM) * K;
            else if (r < 2 * BM + BN) src = Bh + (size_t)(n0 + r - 2 * BM) * K;
            else                      src = Bl + (size_t)(n0 + r - 2 * BM - BN) * K;
            cp16(dst0 + (uint32_t)(r * 80 + c * 16), src + k0 + c * 8);
        }
    };

    // lane-relative ldmatrix offsets (bytes)
    uint32_t aRel = (uint32_t)((wm * WM + (lane & 15)) * 80 + ((lane >> 4) & 1) * 16);
    uint32_t bRel = (uint32_t)((wn * WN + (lane & 7) + ((lane >> 4) << 3)) * 80
                               + ((lane >> 3) & 1) * 16);

    // prologue
#pragma unroll
    for (int s = 0; s < 3; s++) { load_stage(s, s * 32); cp_commit(); }

    float acc[MI][NI][4];
#pragma unroll
    for (int mi = 0; mi < MI; mi++)
#pragma unroll
        for (int ni = 0; ni < NI; ni++)
#pragma unroll
            for (int j = 0; j < 4; j++) acc[mi][ni][j] = 0.f;

    for (int kc = 0; kc < nk; kc++) {
        int s = kc % 3;
        cp_wait<2>();
        __syncthreads();
        uint32_t stg = sbase + (uint32_t)s * SSTR;

#pragma unroll
        for (int h2 = 0; h2 < 2; h2++) {       // two k16 steps per BK=32
            uint32_t koff = (uint32_t)(h2 * 32);
            uint32_t ah[MI][4], al[MI][4];
#pragma unroll
            for (int mi = 0; mi < MI; mi++) {
                ldsm4(ah[mi], stg + OFF_AH + aRel + mi * (16 * 80) + koff);
                ldsm4(al[mi], stg + OFF_AL + aRel + mi * (16 * 80) + koff);
            }
            uint32_t bh[NI][2], bl[NI][2];
#pragma unroll
            for (int n2 = 0; n2 < NI / 2; n2++) {
                uint32_t r4[4];
                ldsm4(r4, stg + OFF_BH + bRel + n2 * (16 * 80) + koff);
                bh[2*n2][0] = r4[0]; bh[2*n2][1] = r4[1];
                bh[2*n2+1][0] = r4[2]; bh[2*n2+1][1] = r4[3];
                ldsm4(r4, stg + OFF_BL + bRel + n2 * (16 * 80) + koff);
                bl[2*n2][0] = r4[0]; bl[2*n2][1] = r4[1];
                bl[2*n2+1][0] = r4[2]; bl[2*n2+1][1] = r4[3];
            }
#pragma unroll
            for (int mi = 0; mi < MI; mi++)
#pragma unroll
                for (int ni = 0; ni < NI; ni++) {
                    mma16816(acc[mi][ni], ah[mi], bh[ni]);
                    mma16816(acc[mi][ni], al[mi], bh[ni]);
                    mma16816(acc[mi][ni], ah[mi], bl[ni]);
                }
        }
        __syncthreads();
        if (kc + 3 < nk) load_stage(s, (kc + 3) * 32);
        cp_commit();
    }

    // epilogue
#pragma unroll
    for (int mi = 0; mi < MI; mi++) {
        int row0 = m0 + wm * WM + mi * 16 + g;
#pragma unroll
        for (int ni = 0; ni < NI; ni++) {
            int col = n0 + wn * WN + ni * 8 + 2 * t;
            if (MODE == 0) {
                float2 v0, v1;
                v0.x = acc[mi][ni][0]; v0.y = acc[mi][ni][1];
                v1.x = acc[mi][ni][2]; v1.y = acc[mi][ni][3];
                *(float2*)(C + (size_t)row0 * N + col)       = v0;
                *(float2*)(C + (size_t)(row0 + 8) * N + col) = v1;
            } else {
#pragma unroll
                for (int hrow = 0; hrow < 2; hrow++) {
                    int row = row0 + hrow * 8;
                    float x0 = fmaxf(acc[mi][ni][hrow*2+0], 0.f);
                    float x1 = fmaxf(acc[mi][ni][hrow*2+1], 0.f);
                    __nv_bfloat16 h0, l0, h1, l1;
                    split1(x0, h0, l0); split1(x1, h1, l1);
                    uint32_t hw = (uint32_t)*(uint16_t*)&h0 | ((uint32_t)*(uint16_t*)&h1 << 16);
                    uint32_t lw = (uint32_t)*(uint16_t*)&l0 | ((uint32_t)*(uint16_t*)&l1 << 16);
                    size_t e = ((size_t)row * N + col) >> 1;
                    ((uint32_t*)Ch)[e] = hw;
                    ((uint32_t*)Cl)[e] = lw;
                }
            }
        }
    }
}

// ===========================================================================
// x = x_in + t_pos + s_pos  (+ bf16 split planes)
// ===========================================================================
__global__ void add_pos_kernel(const float* __restrict__ x,
                               const float* __restrict__ tpos,
                               const float* __restrict__ spos) {
    int i = blockIdx.x * blockDim.x + threadIdx.x;
    if (i >= NM * NE) return;
    int e = i % NE;
    int s = (i / NE) % NS;
    float v = x[i] + tpos[(s / NT) * NE + e] + spos[(s % NT) * NE + e];
    g_x[i] = v;
    __nv_bfloat16 h, l;
    split1(v, h, l);
    g_xh[i] = h; g_xl[i] = l;
}

__global__ void pad_kernel() {
    int i = blockIdx.x * blockDim.x + threadIdx.x;
    if (i < NB * NS) g_pad[i] = (g_x[(size_t)i * NE] == 0.0f) ? 1 : 0;
}

// ===========================================================================
// scores[q,k] = (q.k)*scale, masked (-1e9) for k>q or pad[k].
// ===========================================================================
__global__ void scores_kernel(const float* __restrict__ q,
                              const float* __restrict__ k,
                              float* __restrict__ attn) {
    int kt = blockIdx.x, qt = blockIdx.y, bh = blockIdx.z;
    if (kt > qt) return;
    int b = bh / NH, h = bh % NH;

    __shared__ float Qs[64][65];
    __shared__ float Ks[64][65];
    int tid = threadIdx.x;
    {
        int r = tid >> 2;
        int c = (tid & 3) * 16;
        const float* qp = q + ((size_t)(b * NS + qt * 64 + r)) * NE + h * DK + c;
        const float* kp = k + ((size_t)(b * NS + kt * 64 + r)) * NE + h * DK + c;
#pragma unroll
        for (int j = 0; j < 16; j += 4) {
            float4 v = *(const float4*)(qp + j);
            Qs[r][c + j] = v.x; Qs[r][c + j + 1] = v.y;
            Qs[r][c + j + 2] = v.z; Qs[r][c + j + 3] = v.w;
            float4 w = *(const float4*)(kp + j);
            Ks[r][c + j] = w.x; Ks[r][c + j + 1] = w.y;
            Ks[r][c + j + 2] = w.z; Ks[r][c + j + 3] = w.w;
        }
    }
    __syncthreads();

    int tx = tid & 15, ty = tid >> 4;
    float acc[4][4] = {};
#pragma unroll
    for (int kk = 0; kk < 64; kk++) {
        float a[4], bb[4];
#pragma unroll
        for (int i = 0; i < 4; i++) a[i] = Qs[ty * 4 + i][kk];
#pragma unroll
        for (int j = 0; j < 4; j++) bb[j] = Ks[tx * 4 + j][kk];
#pragma unroll
        for (int i = 0; i < 4; i++)
#pragma unroll
            for (int j = 0; j < 4; j++)
                acc[i][j] += a[i] * bb[j];
    }

    float* out = attn + (size_t)bh * NS * NS;
    const float scale = 0.125f;
#pragma unroll
    for (int i = 0; i < 4; i++) {
        int qi = qt * 64 + ty * 4 + i;
#pragma unroll
        for (int j = 0; j < 4; j++) {
            int ki = kt * 64 + tx * 4 + j;
            float v = acc[i][j] * scale;
            if (ki > qi || g_pad[b * NS + ki]) v = -1e9f;
            out[(size_t)qi * NS + ki] = v;
        }
    }
}

// ===========================================================================
// Row softmax over k in [0, q]; zeros for k > q.
// ===========================================================================
__global__ void softmax_kernel(float* __restrict__ attn) {
    int q  = blockIdx.x;
    int bh = blockIdx.y;
    float* row = attn + (size_t)bh * NS * NS + (size_t)q * NS;
    int n = q + 1;

    __shared__ float buf[NS];
    __shared__ float red[8];
    int tid = threadIdx.x;

    float m = -1e30f;
    for (int i = tid; i < n; i += 256) { float v = row[i]; buf[i] = v; m = fmaxf(m, v); }
#pragma unroll
    for (int o = 16; o; o >>= 1) m = fmaxf(m, __shfl_xor_sync(0xffffffffu, m, o));
    if ((tid & 31) == 0) red[tid >> 5] = m;
    __syncthreads();
    if (tid < 32) {
        float r = (tid < 8) ? red[tid] : -1e30f;
#pragma unroll
        for (int o = 4; o; o >>= 1) r = fmaxf(r, __shfl_xor_sync(0xffffffffu, r, o));
        if (tid == 0) red[0] = r;
    }
    __syncthreads();
    float mx = red[0];
    __syncthreads();

    float s = 0.f;
    for (int i = tid; i < n; i += 256) { float e = expf(buf[i] - mx); buf[i] = e; s += e; }
#pragma unroll
    for (int o = 16; o; o >>= 1) s += __shfl_xor_sync(0xffffffffu, s, o);
    if ((tid & 31) == 0) red[tid >> 5] = s;
    __syncthreads();
    if (tid < 32) {
        float r = (tid < 8) ? red[tid] : 0.f;
#pragma unroll
        for (int o = 4; o; o >>= 1) r += __shfl_xor_sync(0xffffffffu, r, o);
        if (tid == 0) red[0] = r;
    }
    __syncthreads();
    float inv = 1.0f / red[0];

    for (int i = tid; i < n; i += 256) row[i] = buf[i] * inv;
    for (int i = n + tid; i < NS; i += 256) row[i] = 0.0f;
}

// ===========================================================================
// ctx = attn @ v (causal-truncated), writes bf16 split planes
// ===========================================================================
__global__ void ctx_kernel(const float* __restrict__ attn,
                           const float* __restrict__ v) {
    int qt = blockIdx.x, bh = blockIdx.y;
    int b = bh / NH, h = bh % NH;
    const float* arow = attn + (size_t)bh * NS * NS;

    __shared__ float As[64][65];
    __shared__ float Vs[64][65];
    int tid = threadIdx.x;
    int tx = tid & 15, ty = tid >> 4;
    float acc[4][4] = {};

    for (int kt = 0; kt <= qt; kt++) {
        {
            int r = tid >> 2;
            int c = (tid & 3) * 16;
            const float* ap = arow + (size_t)(qt * 64 + r) * NS + kt * 64 + c;
            const float* vp = v + ((size_t)(b * NS + kt * 64 + r)) * NE + h * DK + c;
#pragma unroll
            for (int j = 0; j < 16; j += 4) {
                float4 a4 = *(const float4*)(ap + j);
                As[r][c + j] = a4.x; As[r][c + j + 1] = a4.y;
                As[r][c + j + 2] = a4.z; As[r][c + j + 3] = a4.w;
                float4 v4 = *(const float4*)(vp + j);
                Vs[r][c + j] = v4.x; Vs[r][c + j + 1] = v4.y;
                Vs[r][c + j + 2] = v4.z; Vs[r][c + j + 3] = v4.w;
            }
        }
        __syncthreads();
#pragma unroll
        for (int kk = 0; kk < 64; kk++) {
            float a[4], bb[4];
#pragma unroll
            for (int i = 0; i < 4; i++) a[i] = As[ty * 4 + i][kk];
#pragma unroll
            for (int j = 0; j < 4; j++) bb[j] = Vs[kk][tx * 4 + j];
#pragma unroll
            for (int i = 0; i < 4; i++)
#pragma unroll
                for (int j = 0; j < 4; j++)
                    acc[i][j] += a[i] * bb[j];
        }
        __syncthreads();
    }
#pragma unroll
    for (int i = 0; i < 4; i++) {
        int qi = qt * 64 + ty * 4 + i;
        size_t base = ((size_t)(b * NS + qi)) * NE + h * DK + tx * 4;
#pragma unroll
        for (int p = 0; p < 2; p++) {
            float x0 = acc[i][2*p], x1 = acc[i][2*p+1];
            __nv_bfloat16 h0, l0, h1, l1;
            split1(x0, h0, l0); split1(x1, h1, l1);
            uint32_t hw = (uint32_t)*(uint16_t*)&h0 | ((uint32_t)*(uint16_t*)&h1 << 16);
            uint32_t lw = (uint32_t)*(uint16_t*)&l0 | ((uint32_t)*(uint16_t*)&l1 << 16);
            ((uint32_t*)g_ch)[(base >> 1) + p] = hw;
            ((uint32_t*)g_cl)[(base >> 1) + p] = lw;
        }
    }
}

// ===========================================================================
// x = LayerNorm(y + x) * g + b  (in place on xio; also writes split planes)
// ===========================================================================
__global__ void ln_kernel(const float* __restrict__ y,
                          float* __restrict__ xio,
                          const float* __restrict__ gamma,
                          const float* __restrict__ beta) {
    int row = blockIdx.x;
    __shared__ float buf[NE];
    __shared__ float red[8];
    int tid = threadIdx.x;

    float s = 0.f;
    for (int i = tid; i < NE; i += 256) {
        float v = y[(size_t)row * NE + i] + xio[(size_t)row * NE + i];
        buf[i] = v;
        s += v;
    }
#pragma unroll
    for (int o = 16; o; o >>= 1) s += __shfl_xor_sync(0xffffffffu, s, o);
    if ((tid & 31) == 0) red[tid >> 5] = s;
    __syncthreads();
    if (tid < 32) {
        float r = (tid < 8) ? red[tid] : 0.f;
#pragma unroll
        for (int o = 4; o; o >>= 1) r += __shfl_xor_sync(0xffffffffu, r, o);
        if (tid == 0) red[0] = r;
    }
    __syncthreads();
    float mean = red[0] * (1.0f / NE);
    __syncthreads();

    float vs = 0.f;
    for (int i = tid; i < NE; i += 256) {
        float d = buf[i] - mean;
        vs += d * d;
    }
#pragma unroll
    for (int o = 16; o; o >>= 1) vs += __shfl_xor_sync(0xffffffffu, vs, o);
    if ((tid & 31) == 0) red[tid >> 5] = vs;
    __syncthreads();
    if (tid < 32) {
        float r = (tid < 8) ? red[tid] : 0.f;
#pragma unroll
        for (int o = 4; o; o >>= 1) r += __shfl_xor_sync(0xffffffffu, r, o);
        if (tid == 0) red[0] = r;
    }
    __syncthreads();
    float rstd = rsqrtf(red[0] * (1.0f / NE) + EPS);

    for (int i = tid; i < NE; i += 256) {
        float v = (buf[i] - mean) * rstd * gamma[i] + beta[i];
        size_t o = (size_t)row * NE + i;
        xio[o] = v;
        __nv_bfloat16 h, l;
        split1(v, h, l);
        g_xh[o] = h; g_xl[o] = l;
    }
}

__global__ void copy_x_kernel(float* __restrict__ out) {
    int i = blockIdx.x * blockDim.x + threadIdx.x;
    if (i < NM * NE) out[i] = g_x[i];
}

// ===========================================================================
extern "C" void kernel_launch(void* const* d_in, const int* in_sizes, int n_in,
                              void* d_out, int out_size) {
    const float* x    = (const float*)d_in[0];
    const float* tpos = (const float*)d_in[1];
    const float* spos = (const float*)d_in[2];
    const float* Wq   = (const float*)d_in[3];
    const float* Wk   = (const float*)d_in[4];
    const float* Wv   = (const float*)d_in[5];
    const float* Wo   = (const float*)d_in[6];
    const float* ln1g = (const float*)d_in[7];
    const float* ln1b = (const float*)d_in[8];
    const float* W1   = (const float*)d_in[9];
    const float* W2   = (const float*)d_in[10];
    const float* ln2g = (const float*)d_in[11];
    const float* ln2b = (const float*)d_in[12];

    float* out      = (float*)d_out;
    float* attn_out = out + (size_t)NM * NE;

    float *px, *pq, *pk, *pv, *ptmp;
    __nv_bfloat16 *pxh, *pxl, *pch, *pcl, *phh, *phl;
    __nv_bfloat16 *pwqh, *pwql, *pwkh, *pwkl, *pwvh, *pwvl, *pwoh, *pwol;
    __nv_bfloat16 *pw1h, *pw1l, *pw2h, *pw2l;
    cudaGetSymbolAddress((void**)&px,   g_x);
    cudaGetSymbolAddress((void**)&pq,   g_q);
    cudaGetSymbolAddress((void**)&pk,   g_k);
    cudaGetSymbolAddress((void**)&pv,   g_v);
    cudaGetSymbolAddress((void**)&ptmp, g_tmp);
    cudaGetSymbolAddress((void**)&pxh,  g_xh);
    cudaGetSymbolAddress((void**)&pxl,  g_xl);
    cudaGetSymbolAddress((void**)&pch,  g_ch);
    cudaGetSymbolAddress((void**)&pcl,  g_cl);
    cudaGetSymbolAddress((void**)&phh,  g_hh);
    cudaGetSymbolAddress((void**)&phl,  g_hl);
    cudaGetSymbolAddress((void**)&pwqh, g_wqh);
    cudaGetSymbolAddress((void**)&pwql, g_wql);
    cudaGetSymbolAddress((void**)&pwkh, g_wkh);
    cudaGetSymbolAddress((void**)&pwkl, g_wkl);
    cudaGetSymbolAddress((void**)&pwvh, g_wvh);
    cudaGetSymbolAddress((void**)&pwvl, g_wvl);
    cudaGetSymbolAddress((void**)&pwoh, g_woh);
    cudaGetSymbolAddress((void**)&pwol, g_wol);
    cudaGetSymbolAddress((void**)&pw1h, g_w1h);
    cudaGetSymbolAddress((void**)&pw1l, g_w1l);
    cudaGetSymbolAddress((void**)&pw2h, g_w2h);
    cudaGetSymbolAddress((void**)&pw2l, g_w2l);

    // smem: cfgA (128+64)*2*80*3 = 92,160 ; cfgB (128+128)*2*80*3 = 122,880
    const int SM_A = 2 * (128 + 64) * 80 * 3;
    const int SM_B = 2 * (128 + 128) * 80 * 3;
    cudaFuncSetAttribute(bf16_gemm<128,64,32,32,0>,
        cudaFuncAttributeMaxDynamicSharedMemorySize, SM_A);
    cudaFuncSetAttribute(bf16_gemm<128,128,32,64,1>,
        cudaFuncAttributeMaxDynamicSharedMemorySize, SM_B);

    add_pos_kernel<<<(NM * NE + 255) / 256, 256>>>(x, tpos, spos);
    pad_kernel<<<(NB * NS + 255) / 256, 256>>>();

    // transpose + split all weights to K-major bf16 planes
    {
        dim3 blk(32, 8);
        dim3 gEE(NE / 32, NE / 32);
        dim3 gE_F(DFF / 32, NE / 32);    // W1 [768,3072] -> [3072,768]
        dim3 gF_E(NE / 32, DFF / 32);    // W2 [3072,768] -> [768,3072]
        for (int l = 0; l < NL; l++) {
            size_t oE = (size_t)l * NE * NE, oF = (size_t)l * NE * DFF;
            transpose_split_kernel<<<gEE, blk>>>(Wq + oE, pwqh + oE, pwql + oE, NE, NE);
            transpose_split_kernel<<<gEE, blk>>>(Wk + oE, pwkh + oE, pwkl + oE, NE, NE);
            transpose_split_kernel<<<gEE, blk>>>(Wv + oE, pwvh + oE, pwvl + oE, NE, NE);
            transpose_split_kernel<<<gEE, blk>>>(Wo + oE, pwoh + oE, pwol + oE, NE, NE);
            transpose_split_kernel<<<gE_F, blk>>>(W1 + oF, pw1h + oF, pw1l + oF, NE, DFF);
            transpose_split_kernel<<<gF_E, blk>>>(W2 + oF, pw2h + oF, pw2l + oF, DFF, NE);
        }
    }

    dim3 gProj(NE / 64, NM / 128);             // (12, 16)  128x64 tiles
    dim3 gFF1(DFF / 128, NM / 128);            // (24, 16)  128x128 tiles
    dim3 gScores(NS / 64, NS / 64, NB * NH);
    dim3 gSoft(NS, NB * NH);
    dim3 gCtx(NS / 64, NB * NH);

    for (int l = 0; l < NL; l++) {
        size_t oE = (size_t)l * NE * NE, oF = (size_t)l * NE * DFF;
        float* attn_l = attn_out + (size_t)l * NB * NH * NS * NS;

        bf16_gemm<128,64,32,32,0><<<gProj, 256, SM_A>>>(
            pxh, pxl, pwqh + oE, pwql + oE, pq, nullptr, nullptr, NM, NE, NE);
        bf16_gemm<128,64,32,32,0><<<gProj, 256, SM_A>>>(
            pxh, pxl, pwkh + oE, pwkl + oE, pk, nullptr, nullptr, NM, NE, NE);
        bf16_gemm<128,64,32,32,0><<<gProj, 256, SM_A>>>(
            pxh, pxl, pwvh + oE, pwvl + oE, pv, nullptr, nullptr, NM, NE, NE);

        scores_kernel<<<gScores, 256>>>(pq, pk, attn_l);
        softmax_kernel<<<gSoft, 256>>>(attn_l);
        ctx_kernel<<<gCtx, 256>>>(attn_l, pv);

        bf16_gemm<128,64,32,32,0><<<gProj, 256, SM_A>>>(
            pch, pcl, pwoh + oE, pwol + oE, ptmp, nullptr, nullptr, NM, NE, NE);
        ln_kernel<<<NM, 256>>>(ptmp, px, ln1g + (size_t)l * NE, ln1b + (size_t)l * NE);

        bf16_gemm<128,128,32,64,1><<<gFF1, 256, SM_B>>>(
            pxh, pxl, pw1h + oF, pw1l + oF, nullptr, phh, phl, NM, DFF, NE);
        bf16_gemm<128,64,32,32,0><<<gProj, 256, SM_A>>>(
            phh, phl, pw2h + oF, pw2l + oF, ptmp, nullptr, nullptr, NM, NE, DFF);
        ln_kernel<<<NM, 256>>>(ptmp, px, ln2g + (size_t)l * NE, ln2b + (size_t)l * NE);
    }

    copy_x_kernel<<<(NM * NE + 255) / 256, 256>>>(out);
}

// round 5
// speedup vs baseline: 1.9179x; 1.1981x over previous
#include <cuda_runtime.h>
#include <cuda_bf16.h>
#include <math.h>
#include <stdint.h>

#define NL 6
#define NB 2
#define NF 16
#define NT 64
#define NS 1024
#define NE 768
#define NH 12
#define DK 64
#define DFF 3072
#define NM (NB*NS)        // 2048 rows
#define NQKV 2304
#define EPS 1e-5f

// ---- scratch (allocation-free rule: __device__ globals) ----
__device__ float g_x[NM*NE];
__device__ float g_tmp[NM*NE];
__device__ float g_tmp2[NM*NE];
__device__ int   g_pad[NB*NS];
// bf16 split planes
__device__ __nv_bfloat16 g_xh[NM*NE],  g_xl[NM*NE];
__device__ __nv_bfloat16 g_qkvh[NM*NQKV], g_qkvl[NM*NQKV];
__device__ __nv_bfloat16 g_ch[NM*NE],  g_cl[NM*NE];            // ctx
__device__ __nv_bfloat16 g_hh[NM*DFF], g_hl[NM*DFF];           // hidden
__device__ __nv_bfloat16 g_ah[(size_t)NB*NH*NS*NS];            // attn hi
__device__ __nv_bfloat16 g_al[(size_t)NB*NH*NS*NS];            // attn lo
// K-major weight planes; QKV concatenated [2304 x 768]
__device__ __nv_bfloat16 g_wqkvh[NL*(size_t)NQKV*NE], g_wqkvl[NL*(size_t)NQKV*NE];
__device__ __nv_bfloat16 g_woh[NL*NE*NE],             g_wol[NL*NE*NE];
__device__ __nv_bfloat16 g_w1h[NL*(size_t)NE*DFF],    g_w1l[NL*(size_t)NE*DFF];
__device__ __nv_bfloat16 g_w2h[NL*(size_t)NE*DFF],    g_w2l[NL*(size_t)NE*DFF];

// ===========================================================================
// PTX helpers (base-sm_103 features only)
// ===========================================================================
__device__ __forceinline__ uint32_t smem_u32(const void* p) {
    uint32_t a;
    asm("{ .reg .u64 t; cvta.to.shared.u64 t, %1; cvt.u32.u64 %0, t; }"
        : "=r"(a) : "l"(p));
    return a;
}
__device__ __forceinline__ void cp16(uint32_t s, const void* g) {
    asm volatile("cp.async.cg.shared.global [%0], [%1], 16;" :: "r"(s), "l"(g));
}
__device__ __forceinline__ void cp_commit() {
    asm volatile("cp.async.commit_group;" ::: "memory");
}
template <int N>
__device__ __forceinline__ void cp_wait() {
    asm volatile("cp.async.wait_group %0;" :: "n"(N) : "memory");
}
__device__ __forceinline__ void ldsm4(uint32_t* r, uint32_t addr) {
    asm volatile("ldmatrix.sync.aligned.m8n8.x4.shared.b16 {%0,%1,%2,%3}, [%4];"
        : "=r"(r[0]), "=r"(r[1]), "=r"(r[2]), "=r"(r[3]) : "r"(addr));
}
__device__ __forceinline__ void ldsm2t(uint32_t* r, uint32_t addr) {
    asm volatile("ldmatrix.sync.aligned.m8n8.x2.trans.shared.b16 {%0,%1}, [%2];"
        : "=r"(r[0]), "=r"(r[1]) : "r"(addr));
}
__device__ __forceinline__ void mma16816(float* c, const uint32_t* a, const uint32_t* b) {
    asm volatile(
        "mma.sync.aligned.m16n8k16.row.col.f32.bf16.bf16.f32 "
        "{%0,%1,%2,%3},{%4,%5,%6,%7},{%8,%9},{%0,%1,%2,%3};"
        : "+f"(c[0]), "+f"(c[1]), "+f"(c[2]), "+f"(c[3])
        : "r"(a[0]), "r"(a[1]), "r"(a[2]), "r"(a[3]), "r"(b[0]), "r"(b[1]));
}
__device__ __forceinline__ void split1(float v, __nv_bfloat16& h, __nv_bfloat16& l) {
    h = __float2bfloat16_rn(v);
    l = __float2bfloat16_rn(v - __bfloat162float(h));
}
__device__ __forceinline__ uint32_t pack_split2(float x0, float x1,
                                                uint32_t& lw) {
    __nv_bfloat16 h0, l0, h1, l1;
    split1(x0, h0, l0); split1(x1, h1, l1);
    lw = (uint32_t)*(uint16_t*)&l0 | ((uint32_t)*(uint16_t*)&l1 << 16);
    return (uint32_t)*(uint16_t*)&h0 | ((uint32_t)*(uint16_t*)&h1 << 16);
}

// ===========================================================================
// weight transpose + bf16 split: oh/ol[c*R + r] = split(in[r*C + c])
// ===========================================================================
__global__ void transpose_split_kernel(const float* __restrict__ in,
                                       __nv_bfloat16* __restrict__ oh,
                                       __nv_bfloat16* __restrict__ ol,
                                       int R, int C) {
    __shared__ float t[32][33];
    int c0 = blockIdx.x * 32, r0 = blockIdx.y * 32;
    int x = threadIdx.x, y = threadIdx.y;   // 32 x 8
#pragma unroll
    for (int i = 0; i < 32; i += 8)
        t[y + i][x] = in[(size_t)(r0 + y + i) * C + c0 + x];
    __syncthreads();
#pragma unroll
    for (int i = 0; i < 32; i += 8) {
        float v = t[x][y + i];
        __nv_bfloat16 h, l;
        split1(v, h, l);
        size_t o = (size_t)(c0 + y + i) * R + r0 + x;
        oh[o] = h; ol[o] = l;
    }
}

// ===========================================================================
// bf16x3 mma GEMM: C[M,N] = (Ah+Al)[M,K] @ (Bh+Bl)[N,K]^T
// MODE 0: fp32 out C.  MODE 1: (opt relu) + bf16-split out (Ch, Cl).
// ldk = row stride of A/B in elements, lenK = reduction length.
// ===========================================================================
template <int BM, int BN, int WM, int WN, int NTHR, int MODE, bool RELU>
__global__ void __launch_bounds__(NTHR)
bf16_gemm(const __nv_bfloat16* __restrict__ Ah, const __nv_bfloat16* __restrict__ Al,
          const __nv_bfloat16* __restrict__ Bh, const __nv_bfloat16* __restrict__ Bl,
          float* __restrict__ C,
          __nv_bfloat16* __restrict__ Ch, __nv_bfloat16* __restrict__ Cl,
          int M, int N, int ldk, int lenK) {
    constexpr int MI = WM / 16;
    constexpr int NI = WN / 8;
    constexpr int WGN = BN / WN;
    constexpr int ROWS = 2 * (BM + BN);
    constexpr uint32_t SSTR = (uint32_t)ROWS * 80;
    constexpr uint32_t OFF_AH = 0;
    constexpr uint32_t OFF_AL = (uint32_t)BM * 80;
    constexpr uint32_t OFF_BH = (uint32_t)(2 * BM) * 80;
    constexpr uint32_t OFF_BL = (uint32_t)(2 * BM + BN) * 80;

    extern __shared__ char smem[];
    uint32_t sbase = smem_u32(smem);
    int tid = threadIdx.x, lane = tid & 31, wid = tid >> 5;
    int wn = wid % WGN, wm = wid / WGN;
    int g = lane >> 2, t = lane & 3;
    int m0 = blockIdx.y * BM, n0 = blockIdx.x * BN;
    const int nk = lenK >> 5;

    auto load_stage = [&](int stage, int k0) {
        uint32_t dst0 = sbase + (uint32_t)stage * SSTR;
#pragma unroll
        for (int idx = tid; idx < ROWS * 4; idx += NTHR) {
            int r = idx >> 2, c = idx & 3;
            const __nv_bfloat16* src;
            if (r < BM)               src = Ah + (size_t)(m0 + r) * ldk;
            else if (r < 2 * BM)      src = Al + (size_t)(m0 + r - BM) * ldk;
            else if (r < 2 * BM + BN) src = Bh + (size_t)(n0 + r - 2 * BM) * ldk;
            else                      src = Bl + (size_t)(n0 + r - 2 * BM - BN) * ldk;
            cp16(dst0 + (uint32_t)(r * 80 + c * 16), src + k0 + c * 8);
        }
    };

    uint32_t aRel = (uint32_t)((wm * WM + (lane & 15)) * 80 + ((lane >> 4) & 1) * 16);
    uint32_t bRel = (uint32_t)((wn * WN + (lane & 7) + ((lane >> 4) << 3)) * 80
                               + ((lane >> 3) & 1) * 16);

#pragma unroll
    for (int s = 0; s < 3; s++) { load_stage(s, s * 32); cp_commit(); }

    float acc[MI][NI][4];
#pragma unroll
    for (int mi = 0; mi < MI; mi++)
#pragma unroll
        for (int ni = 0; ni < NI; ni++)
#pragma unroll
            for (int j = 0; j < 4; j++) acc[mi][ni][j] = 0.f;

    for (int kc = 0; kc < nk; kc++) {
        int s = kc % 3;
        cp_wait<2>();
        __syncthreads();
        uint32_t stg = sbase + (uint32_t)s * SSTR;

#pragma unroll
        for (int h2 = 0; h2 < 2; h2++) {
            uint32_t koff = (uint32_t)(h2 * 32);
            uint32_t ah[MI][4], al[MI][4];
#pragma unroll
            for (int mi = 0; mi < MI; mi++) {
                ldsm4(ah[mi], stg + OFF_AH + aRel + mi * (16 * 80) + koff);
                ldsm4(al[mi], stg + OFF_AL + aRel + mi * (16 * 80) + koff);
            }
            uint32_t bh[NI][2], bl[NI][2];
#pragma unroll
            for (int n2 = 0; n2 < NI / 2; n2++) {
                uint32_t r4[4];
                ldsm4(r4, stg + OFF_BH + bRel + n2 * (16 * 80) + koff);
                bh[2*n2][0] = r4[0]; bh[2*n2][1] = r4[1];
                bh[2*n2+1][0] = r4[2]; bh[2*n2+1][1] = r4[3];
                ldsm4(r4, stg + OFF_BL + bRel + n2 * (16 * 80) + koff);
                bl[2*n2][0] = r4[0]; bl[2*n2][1] = r4[1];
                bl[2*n2+1][0] = r4[2]; bl[2*n2+1][1] = r4[3];
            }
#pragma unroll
            for (int mi = 0; mi < MI; mi++)
#pragma unroll
                for (int ni = 0; ni < NI; ni++) {
                    mma16816(acc[mi][ni], ah[mi], bh[ni]);
                    mma16816(acc[mi][ni], al[mi], bh[ni]);
                    mma16816(acc[mi][ni], ah[mi], bl[ni]);
                }
        }
        __syncthreads();
        if (kc + 3 < nk) load_stage(s, (kc + 3) * 32);
        cp_commit();
    }

#pragma unroll
    for (int mi = 0; mi < MI; mi++) {
        int row0 = m0 + wm * WM + mi * 16 + g;
#pragma unroll
        for (int ni = 0; ni < NI; ni++) {
            int col = n0 + wn * WN + ni * 8 + 2 * t;
            if (MODE == 0) {
                float2 v0, v1;
                v0.x = acc[mi][ni][0]; v0.y = acc[mi][ni][1];
                v1.x = acc[mi][ni][2]; v1.y = acc[mi][ni][3];
                *(float2*)(C + (size_t)row0 * N + col)       = v0;
                *(float2*)(C + (size_t)(row0 + 8) * N + col) = v1;
            } else {
#pragma unroll
                for (int hrow = 0; hrow < 2; hrow++) {
                    int row = row0 + hrow * 8;
                    float x0 = acc[mi][ni][hrow*2+0];
                    float x1 = acc[mi][ni][hrow*2+1];
                    if (RELU) { x0 = fmaxf(x0, 0.f); x1 = fmaxf(x1, 0.f); }
                    uint32_t lw;
                    uint32_t hw = pack_split2(x0, x1, lw);
                    size_t e = ((size_t)row * N + col) >> 1;
                    ((uint32_t*)Ch)[e] = hw;
                    ((uint32_t*)Cl)[e] = lw;
                }
            }
        }
    }
}

// ===========================================================================
// x = x_in + t_pos + s_pos  (+ bf16 split planes)
// ===========================================================================
__global__ void add_pos_kernel(const float* __restrict__ x,
                               const float* __restrict__ tpos,
                               const float* __restrict__ spos) {
    int i = blockIdx.x * blockDim.x + threadIdx.x;
    if (i >= NM * NE) return;
    int e = i % NE;
    int s = (i / NE) % NS;
    float v = x[i] + tpos[(s / NT) * NE + e] + spos[(s % NT) * NE + e];
    g_x[i] = v;
    __nv_bfloat16 h, l;
    split1(v, h, l);
    g_xh[i] = h; g_xl[i] = l;
}

__global__ void pad_kernel() {
    int i = blockIdx.x * blockDim.x + threadIdx.x;
    if (i < NB * NS) g_pad[i] = (g_x[(size_t)i * NE] == 0.0f) ? 1 : 0;
}

// ===========================================================================
// scores_mma: 128x128 tile of q.k^T * scale, causal+pad masked -> fp32 attn.
// A = q planes, B = k planes (from fused qkv planes). 8 warps, WM32 WN64.
// ===========================================================================
__global__ void __launch_bounds__(256)
scores_mma(const __nv_bfloat16* __restrict__ qkvh,
           const __nv_bfloat16* __restrict__ qkvl,
           float* __restrict__ attn) {
    int kt = blockIdx.x, qt = blockIdx.y, bh = blockIdx.z;
    if (kt > qt) return;
    int b = bh / NH, h = bh % NH;

    extern __shared__ char smem[];
    uint32_t sb = smem_u32(smem);
    const uint32_t QH = 0, QL = 128*144, KH = 2*128*144, KL = 3*128*144;

    int tid = threadIdx.x, lane = tid & 31, wid = tid >> 5;
    int wm = wid >> 1, wn = wid & 1;
    int g = lane >> 2, t = lane & 3;

    for (int idx = tid; idx < 128 * 8; idx += 256) {
        int r = idx >> 3, c = idx & 7;
        size_t qrow = (size_t)(b * NS + qt * 128 + r) * NQKV + h * DK + c * 8;
        size_t krow = (size_t)(b * NS + kt * 128 + r) * NQKV + NE + h * DK + c * 8;
        uint32_t d = (uint32_t)(r * 144 + c * 16);
        cp16(sb + QH + d, qkvh + qrow);
        cp16(sb + QL + d, qkvl + qrow);
        cp16(sb + KH + d, qkvh + krow);
        cp16(sb + KL + d, qkvl + krow);
    }
    cp_commit();
    cp_wait<0>();
    __syncthreads();

    uint32_t aRel = (uint32_t)((wm * 32 + (lane & 15)) * 144 + ((lane >> 4) & 1) * 16);
    uint32_t bRel = (uint32_t)((wn * 64 + (lane & 7) + ((lane >> 4) << 3)) * 144
                               + ((lane >> 3) & 1) * 16);

    float acc[2][8][4];
#pragma unroll
    for (int mi = 0; mi < 2; mi++)
#pragma unroll
        for (int ni = 0; ni < 8; ni++)
#pragma unroll
            for (int j = 0; j < 4; j++) acc[mi][ni][j] = 0.f;

#pragma unroll
    for (int kk = 0; kk < 4; kk++) {
        uint32_t koff = (uint32_t)(kk * 32);
        uint32_t ah[2][4], al[2][4];
#pragma unroll
        for (int mi = 0; mi < 2; mi++) {
            ldsm4(ah[mi], sb + QH + aRel + mi * (16 * 144) + koff);
            ldsm4(al[mi], sb + QL + aRel + mi * (16 * 144) + koff);
        }
        uint32_t bh_[8][2], bl_[8][2];
#pragma unroll
        for (int n2 = 0; n2 < 4; n2++) {
            uint32_t r4[4];
            ldsm4(r4, sb + KH + bRel + n2 * (16 * 144) + koff);
            bh_[2*n2][0] = r4[0]; bh_[2*n2][1] = r4[1];
            bh_[2*n2+1][0] = r4[2]; bh_[2*n2+1][1] = r4[3];
            ldsm4(r4, sb + KL + bRel + n2 * (16 * 144) + koff);
            bl_[2*n2][0] = r4[0]; bl_[2*n2][1] = r4[1];
            bl_[2*n2+1][0] = r4[2]; bl_[2*n2+1][1] = r4[3];
        }
#pragma unroll
        for (int mi = 0; mi < 2; mi++)
#pragma unroll
            for (int ni = 0; ni < 8; ni++) {
                mma16816(acc[mi][ni], ah[mi], bh_[ni]);
                mma16816(acc[mi][ni], al[mi], bh_[ni]);
                mma16816(acc[mi][ni], ah[mi], bl_[ni]);
            }
    }

    float* out = attn + (size_t)bh * NS * NS;
    const float scale = 0.125f;
#pragma unroll
    for (int mi = 0; mi < 2; mi++) {
#pragma unroll
        for (int hrow = 0; hrow < 2; hrow++) {
            int qi = qt * 128 + wm * 32 + mi * 16 + g + hrow * 8;
#pragma unroll
            for (int ni = 0; ni < 8; ni++) {
                int ki = kt * 128 + wn * 64 + ni * 8 + 2 * t;
                float v0 = acc[mi][ni][hrow*2+0] * scale;
                float v1 = acc[mi][ni][hrow*2+1] * scale;
                if (ki     > qi || g_pad[b * NS + ki])     v0 = -1e9f;
                if (ki + 1 > qi || g_pad[b * NS + ki + 1]) v1 = -1e9f;
                float2 v; v.x = v0; v.y = v1;
                *(float2*)(out + (size_t)qi * NS + ki) = v;
            }
        }
    }
}

// ===========================================================================
// Row softmax over k in [0, q]; zeros for k > q. Also writes bf16 split
// planes (zero-padded to 128-boundary) for the ctx mma.
// ===========================================================================
__global__ void softmax_kernel(float* __restrict__ attn,
                               __nv_bfloat16* __restrict__ ph,
                               __nv_bfloat16* __restrict__ pl) {
    int q  = blockIdx.x;
    int bh = blockIdx.y;
    size_t pbase = (size_t)bh * NS * NS + (size_t)q * NS;
    float* row = attn + pbase;
    int n = q + 1;

    __shared__ float buf[NS];
    __shared__ float red[8];
    int tid = threadIdx.x;

    float m = -1e30f;
    for (int i = tid; i < n; i += 256) { float v = row[i]; buf[i] = v; m = fmaxf(m, v); }
#pragma unroll
    for (int o = 16; o; o >>= 1) m = fmaxf(m, __shfl_xor_sync(0xffffffffu, m, o));
    if ((tid & 31) == 0) red[tid >> 5] = m;
    __syncthreads();
    if (tid < 32) {
        float r = (tid < 8) ? red[tid] : -1e30f;
#pragma unroll
        for (int o = 4; o; o >>= 1) r = fmaxf(r, __shfl_xor_sync(0xffffffffu, r, o));
        if (tid == 0) red[0] = r;
    }
    __syncthreads();
    float mx = red[0];
    __syncthreads();

    float s = 0.f;
    for (int i = tid; i < n; i += 256) { float e = expf(buf[i] - mx); buf[i] = e; s += e; }
#pragma unroll
    for (int o = 16; o; o >>= 1) s += __shfl_xor_sync(0xffffffffu, s, o);
    if ((tid & 31) == 0) red[tid >> 5] = s;
    __syncthreads();
    if (tid < 32) {
        float r = (tid < 8) ? red[tid] : 0.f;
#pragma unroll
        for (int o = 4; o; o >>= 1) r += __shfl_xor_sync(0xffffffffu, r, o);
        if (tid == 0) red[0] = r;
    }
    __syncthreads();
    float inv = 1.0f / red[0];

    for (int i = tid; i < n; i += 256) {
        float p = buf[i] * inv;
        row[i] = p;
        __nv_bfloat16 h, l;
        split1(p, h, l);
        ph[pbase + i] = h; pl[pbase + i] = l;
    }
    int npad = (n + 127) & ~127;
    __nv_bfloat16 z = __float2bfloat16(0.f);
    for (int i = n + tid; i < NS; i += 256) row[i] = 0.0f;
    for (int i = n + tid; i < npad; i += 256) { ph[pbase + i] = z; pl[pbase + i] = z; }
}

// ===========================================================================
// ctx_mma: ctx[128q x 64d] = attn_planes @ v_planes (causal kt loop).
// A via ldsm4 (row-major), B = v via ldsm2 trans. Split bf16 output planes.
// ===========================================================================
__global__ void __launch_bounds__(256)
ctx_mma(const __nv_bfloat16* __restrict__ ph, const __nv_bfloat16* __restrict__ pl,
        const __nv_bfloat16* __restrict__ qkvh, const __nv_bfloat16* __restrict__ qkvl,
        __nv_bfloat16* __restrict__ ch, __nv_bfloat16* __restrict__ cl) {
    int qt = (int)gridDim.x - 1 - (int)blockIdx.x;   // heavy tiles first
    int bh = blockIdx.y;
    int b = bh / NH, h = bh % NH;

    extern __shared__ char smem[];
    uint32_t sb = smem_u32(smem);
    const uint32_t AH = 0, AL = 128*272, VH = 2*128*272, VL = 2*128*272 + 128*144;

    int tid = threadIdx.x, lane = tid & 31, wid = tid >> 5;
    int wm = wid >> 1, wn = wid & 1;
    int g = lane >> 2, t = lane & 3;

    uint32_t aRel = (uint32_t)((wm * 32 + (lane & 15)) * 272 + ((lane >> 4) & 1) * 16);

    float acc[2][4][4];
#pragma unroll
    for (int mi = 0; mi < 2; mi++)
#pragma unroll
        for (int ni = 0; ni < 4; ni++)
#pragma unroll
            for (int j = 0; j < 4; j++) acc[mi][ni][j] = 0.f;

    for (int kt = 0; kt <= qt; kt++) {
        for (int idx = tid; idx < 128 * 16; idx += 256) {
            int r = idx >> 4, c = idx & 15;
            size_t arow = (size_t)bh * NS * NS + (size_t)(qt * 128 + r) * NS
                        + kt * 128 + c * 8;
            uint32_t d = (uint32_t)(r * 272 + c * 16);
            cp16(sb + AH + d, ph + arow);
            cp16(sb + AL + d, pl + arow);
        }
        for (int idx = tid; idx < 128 * 8; idx += 256) {
            int r = idx >> 3, c = idx & 7;
            size_t vrow = (size_t)(b * NS + kt * 128 + r) * NQKV + 1536 + h * DK + c * 8;
            uint32_t d = (uint32_t)(r * 144 + c * 16);
            cp16(sb + VH + d, qkvh + vrow);
            cp16(sb + VL + d, qkvl + vrow);
        }
        cp_commit();
        cp_wait<0>();
        __syncthreads();

#pragma unroll
        for (int kk = 0; kk < 8; kk++) {
            uint32_t koff = (uint32_t)(kk * 32);
            uint32_t ah[2][4], al[2][4];
#pragma unroll
            for (int mi = 0; mi < 2; mi++) {
                ldsm4(ah[mi], sb + AH + aRel + mi * (16 * 272) + koff);
                ldsm4(al[mi], sb + AL + aRel + mi * (16 * 272) + koff);
            }
            uint32_t vrowRel = (uint32_t)((kk * 16 + (lane & 15)) * 144);
            uint32_t bh_[4][2], bl_[4][2];
#pragma unroll
            for (int ni = 0; ni < 4; ni++) {
                uint32_t coff = (uint32_t)((wn * 32 + ni * 8) * 2);
                ldsm2t(bh_[ni], sb + VH + vrowRel + coff);
                ldsm2t(bl_[ni], sb + VL + vrowRel + coff);
            }
#pragma unroll
            for (int mi = 0; mi < 2; mi++)
#pragma unroll
                for (int ni = 0; ni < 4; ni++) {
                    mma16816(acc[mi][ni], ah[mi], bh_[ni]);
                    mma16816(acc[mi][ni], al[mi], bh_[ni]);
                    mma16816(acc[mi][ni], ah[mi], bl_[ni]);
                }
        }
        __syncthreads();
    }

#pragma unroll
    for (int mi = 0; mi < 2; mi++) {
#pragma unroll
        for (int ni = 0; ni < 4; ni++) {
            int dcol = h * DK + wn * 32 + ni * 8 + 2 * t;
#pragma unroll
            for (int hrow = 0; hrow < 2; hrow++) {
                int q = qt * 128 + wm * 32 + mi * 16 + g + hrow * 8;
                uint32_t lw;
                uint32_t hw = pack_split2(acc[mi][ni][hrow*2], acc[mi][ni][hrow*2+1], lw);
                size_t e = ((size_t)(b * NS + q) * NE + dcol) >> 1;
                ((uint32_t*)ch)[e] = hw;
                ((uint32_t*)cl)[e] = lw;
            }
        }
    }
}

// ===========================================================================
// x = LayerNorm(y1 [+ y2] + x) * g + b  (in place; writes split planes)
// ===========================================================================
__global__ void ln_kernel(const float* __restrict__ y1,
                          const float* __restrict__ y2,
                          float* __restrict__ xio,
                          const float* __restrict__ gamma,
                          const float* __restrict__ beta) {
    int row = blockIdx.x;
    __shared__ float buf[NE];
    __shared__ float red[8];
    int tid = threadIdx.x;

    float s = 0.f;
    for (int i = tid; i < NE; i += 256) {
        size_t o = (size_t)row * NE + i;
        float v = y1[o] + xio[o];
        if (y2) v += y2[o];
        buf[i] = v;
        s += v;
    }
#pragma unroll
    for (int o = 16; o; o >>= 1) s += __shfl_xor_sync(0xffffffffu, s, o);
    if ((tid & 31) == 0) red[tid >> 5] = s;
    __syncthreads();
    if (tid < 32) {
        float r = (tid < 8) ? red[tid] : 0.f;
#pragma unroll
        for (int o = 4; o; o >>= 1) r += __shfl_xor_sync(0xffffffffu, r, o);
        if (tid == 0) red[0] = r;
    }
    __syncthreads();
    float mean = red[0] * (1.0f / NE);
    __syncthreads();

    float vs = 0.f;
    for (int i = tid; i < NE; i += 256) {
        float d = buf[i] - mean;
        vs += d * d;
    }
#pragma unroll
    for (int o = 16; o; o >>= 1) vs += __shfl_xor_sync(0xffffffffu, vs, o);
    if ((tid & 31) == 0) red[tid >> 5] = vs;
    __syncthreads();
    if (tid < 32) {
        float r = (tid < 8) ? red[tid] : 0.f;
#pragma unroll
        for (int o = 4; o; o >>= 1) r += __shfl_xor_sync(0xffffffffu, r, o);
        if (tid == 0) red[0] = r;
    }
    __syncthreads();
    float rstd = rsqrtf(red[0] * (1.0f / NE) + EPS);

    for (int i = tid; i < NE; i += 256) {
        float v = (buf[i] - mean) * rstd * gamma[i] + beta[i];
        size_t o = (size_t)row * NE + i;
        xio[o] = v;
        __nv_bfloat16 h, l;
        split1(v, h, l);
        g_xh[o] = h; g_xl[o] = l;
    }
}

__global__ void copy_x_kernel(float* __restrict__ out) {
    int i = blockIdx.x * blockDim.x + threadIdx.x;
    if (i < NM * NE) out[i] = g_x[i];
}

// ===========================================================================
extern "C" void kernel_launch(void* const* d_in, const int* in_sizes, int n_in,
                              void* d_out, int out_size) {
    const float* x    = (const float*)d_in[0];
    const float* tpos = (const float*)d_in[1];
    const float* spos = (const float*)d_in[2];
    const float* Wq   = (const float*)d_in[3];
    const float* Wk   = (const float*)d_in[4];
    const float* Wv   = (const float*)d_in[5];
    const float* Wo   = (const float*)d_in[6];
    const float* ln1g = (const float*)d_in[7];
    const float* ln1b = (const float*)d_in[8];
    const float* W1   = (const float*)d_in[9];
    const float* W2   = (const float*)d_in[10];
    const float* ln2g = (const float*)d_in[11];
    const float* ln2b = (const float*)d_in[12];

    float* out      = (float*)d_out;
    float* attn_out = out + (size_t)NM * NE;

    float *px, *ptmp, *ptmp2;
    __nv_bfloat16 *pxh, *pxl, *pqkvh, *pqkvl, *pch, *pcl, *phh, *phl, *pah, *pal;
    __nv_bfloat16 *pwqkvh, *pwqkvl, *pwoh, *pwol, *pw1h, *pw1l, *pw2h, *pw2l;
    cudaGetSymbolAddress((void**)&px,    g_x);
    cudaGetSymbolAddress((void**)&ptmp,  g_tmp);
    cudaGetSymbolAddress((void**)&ptmp2, g_tmp2);
    cudaGetSymbolAddress((void**)&pxh,   g_xh);
    cudaGetSymbolAddress((void**)&pxl,   g_xl);
    cudaGetSymbolAddress((void**)&pqkvh, g_qkvh);
    cudaGetSymbolAddress((void**)&pqkvl, g_qkvl);
    cudaGetSymbolAddress((void**)&pch,   g_ch);
    cudaGetSymbolAddress((void**)&pcl,   g_cl);
    cudaGetSymbolAddress((void**)&phh,   g_hh);
    cudaGetSymbolAddress((void**)&phl,   g_hl);
    cudaGetSymbolAddress((void**)&pah,   g_ah);
    cudaGetSymbolAddress((void**)&pal,   g_al);
    cudaGetSymbolAddress((void**)&pwqkvh, g_wqkvh);
    cudaGetSymbolAddress((void**)&pwqkvl, g_wqkvl);
    cudaGetSymbolAddress((void**)&pwoh,  g_woh);
    cudaGetSymbolAddress((void**)&pwol,  g_wol);
    cudaGetSymbolAddress((void**)&pw1h,  g_w1h);
    cudaGetSymbolAddress((void**)&pw1l,  g_w1l);
    cudaGetSymbolAddress((void**)&pw2h,  g_w2h);
    cudaGetSymbolAddress((void**)&pw2l,  g_w2l);

    // projection config: 128x64 tile, 4 warps of 64x32, 128 threads
    const int SM_P  = 2 * (128 + 64) * 80 * 3;     //  92,160
    const int SM_F1 = 2 * (128 + 128) * 80 * 3;    // 122,880
    const int SM_SC = 4 * 128 * 144;               //  73,728
    const int SM_CX = 2 * 128 * 272 + 2 * 128 * 144; // 106,496

    cudaFuncSetAttribute((const void*)bf16_gemm<128,64,64,32,128,0,false>,
        cudaFuncAttributeMaxDynamicSharedMemorySize, SM_P);
    cudaFuncSetAttribute((const void*)bf16_gemm<128,64,64,32,128,1,false>,
        cudaFuncAttributeMaxDynamicSharedMemorySize, SM_P);
    cudaFuncSetAttribute((const void*)bf16_gemm<128,128,32,64,256,1,true>,
        cudaFuncAttributeMaxDynamicSharedMemorySize, SM_F1);
    cudaFuncSetAttribute((const void*)scores_mma,
        cudaFuncAttributeMaxDynamicSharedMemorySize, SM_SC);
    cudaFuncSetAttribute((const void*)ctx_mma,
        cudaFuncAttributeMaxDynamicSharedMemorySize, SM_CX);

    add_pos_kernel<<<(NM * NE + 255) / 256, 256>>>(x, tpos, spos);
    pad_kernel<<<(NB * NS + 255) / 256, 256>>>();

    // transpose + split all weights to K-major bf16 planes (QKV concatenated)
    {
        dim3 blk(32, 8);
        dim3 gEE(NE / 32, NE / 32);
        dim3 gE_F(DFF / 32, NE / 32);    // W1 [768,3072] -> [3072,768]
        dim3 gF_E(NE / 32, DFF / 32);    // W2 [3072,768] -> [768,3072]
        for (int l = 0; l < NL; l++) {
            size_t oE = (size_t)l * NE * NE, oF = (size_t)l * NE * DFF;
            size_t oQ = (size_t)l * NQKV * NE;
            transpose_split_kernel<<<gEE, blk>>>(Wq + oE, pwqkvh + oQ,
                                                 pwqkvl + oQ, NE, NE);
            transpose_split_kernel<<<gEE, blk>>>(Wk + oE, pwqkvh + oQ + (size_t)NE*NE,
                                                 pwqkvl + oQ + (size_t)NE*NE, NE, NE);
            transpose_split_kernel<<<gEE, blk>>>(Wv + oE, pwqkvh + oQ + (size_t)2*NE*NE,
                                                 pwqkvl + oQ + (size_t)2*NE*NE, NE, NE);
            transpose_split_kernel<<<gEE, blk>>>(Wo + oE, pwoh + oE, pwol + oE, NE, NE);
            transpose_split_kernel<<<gE_F, blk>>>(W1 + oF, pw1h + oF, pw1l + oF, NE, DFF);
            transpose_split_kernel<<<gF_E, blk>>>(W2 + oF, pw2h + oF, pw2l + oF, DFF, NE);
        }
    }

    dim3 gQKV(NQKV / 64, NM / 128);            // (36, 16)
    dim3 gWo(NE / 64, NM / 128);               // (12, 16)
    dim3 gFF1(DFF / 128, NM / 128);            // (24, 16)
    dim3 gScores(NS / 128, NS / 128, NB * NH); // (8, 8, 24)
    dim3 gSoft(NS, NB * NH);
    dim3 gCtx(NS / 128, NB * NH);              // (8, 24)

    for (int l = 0; l < NL; l++) {
        size_t oE = (size_t)l * NE * NE, oF = (size_t)l * NE * DFF;
        size_t oQ = (size_t)l * NQKV * NE;
        float* attn_l = attn_out + (size_t)l * NB * NH * NS * NS;

        bf16_gemm<128,64,64,32,128,1,false><<<gQKV, 128, SM_P>>>(
            pxh, pxl, pwqkvh + oQ, pwqkvl + oQ,
            nullptr, pqkvh, pqkvl, NM, NQKV, NE, NE);

        scores_mma<<<gScores, 256, SM_SC>>>(pqkvh, pqkvl, attn_l);
        softmax_kernel<<<gSoft, 256>>>(attn_l, pah, pal);
        ctx_mma<<<gCtx, 256, SM_CX>>>(pah, pal, pqkvh, pqkvl, pch, pcl);

        bf16_gemm<128,64,64,32,128,0,false><<<gWo, 128, SM_P>>>(
            pch, pcl, pwoh + oE, pwol + oE, ptmp, nullptr, nullptr,
            NM, NE, NE, NE);
        ln_kernel<<<NM, 256>>>(ptmp, nullptr, px,
                               ln1g + (size_t)l * NE, ln1b + (size_t)l * NE);

        bf16_gemm<128,128,32,64,256,1,true><<<gFF1, 256, SM_F1>>>(
            pxh, pxl, pw1h + oF, pw1l + oF, nullptr, phh, phl,
            NM, DFF, NE, NE);

        // FFN2 split-K: halves summed inside ln_kernel
        bf16_gemm<128,64,64,32,128,0,false><<<gWo, 128, SM_P>>>(
            phh, phl, pw2h + oF, pw2l + oF, ptmp, nullptr, nullptr,
            NM, NE, DFF, 1536);
        bf16_gemm<128,64,64,32,128,0,false><<<gWo, 128, SM_P>>>(
            phh + 1536, phl + 1536, pw2h + oF + 1536, pw2l + oF + 1536,
            ptmp2, nullptr, nullptr, NM, NE, DFF, 1536);
        ln_kernel<<<NM, 256>>>(ptmp, ptmp2, px,
                               ln2g + (size_t)l * NE, ln2b + (size_t)l * NE);
    }

    copy_x_kernel<<<(NM * NE + 255) / 256, 256>>>(out);
}

// round 6
// speedup vs baseline: 1.9871x; 1.0361x over previous
#include <cuda_runtime.h>
#include <cuda_bf16.h>
#include <math.h>
#include <stdint.h>

#define NL 6
#define NB 2
#define NF 16
#define NT 64
#define NS 1024
#define NE 768
#define NH 12
#define DK 64
#define DFF 3072
#define NM (NB*NS)        // 2048 rows
#define NQKV 2304
#define EPS 1e-5f

// ---- scratch (allocation-free rule: __device__ globals) ----
__device__ float g_x[NM*NE];
__device__ float g_tmp[NM*NE];
__device__ float g_tmp2[NM*NE];
__device__ int   g_pad[NB*NS];
// bf16 split planes
__device__ __nv_bfloat16 g_xh[NM*NE],  g_xl[NM*NE];
__device__ __nv_bfloat16 g_qkvh[NM*NQKV], g_qkvl[NM*NQKV];
__device__ __nv_bfloat16 g_ch[NM*NE],  g_cl[NM*NE];            // ctx
__device__ __nv_bfloat16 g_hh[NM*DFF], g_hl[NM*DFF];           // hidden
__device__ __nv_bfloat16 g_ah[(size_t)NB*NH*NS*NS];            // attn hi
__device__ __nv_bfloat16 g_al[(size_t)NB*NH*NS*NS];            // attn lo
// K-major weight planes; QKV concatenated [2304 x 768]
__device__ __nv_bfloat16 g_wqkvh[NL*(size_t)NQKV*NE], g_wqkvl[NL*(size_t)NQKV*NE];
__device__ __nv_bfloat16 g_woh[NL*NE*NE],             g_wol[NL*NE*NE];
__device__ __nv_bfloat16 g_w1h[NL*(size_t)NE*DFF],    g_w1l[NL*(size_t)NE*DFF];
__device__ __nv_bfloat16 g_w2h[NL*(size_t)NE*DFF],    g_w2l[NL*(size_t)NE*DFF];

// ===========================================================================
// PTX helpers (base-sm_103 features only)
// ===========================================================================
__device__ __forceinline__ uint32_t smem_u32(const void* p) {
    uint32_t a;
    asm("{ .reg .u64 t; cvta.to.shared.u64 t, %1; cvt.u32.u64 %0, t; }"
        : "=r"(a) : "l"(p));
    return a;
}
__device__ __forceinline__ void cp16(uint32_t s, const void* g) {
    asm volatile("cp.async.cg.shared.global [%0], [%1], 16;" :: "r"(s), "l"(g));
}
__device__ __forceinline__ void cp_commit() {
    asm volatile("cp.async.commit_group;" ::: "memory");
}
template <int N>
__device__ __forceinline__ void cp_wait() {
    asm volatile("cp.async.wait_group %0;" :: "n"(N) : "memory");
}
__device__ __forceinline__ void ldsm4(uint32_t* r, uint32_t addr) {
    asm volatile("ldmatrix.sync.aligned.m8n8.x4.shared.b16 {%0,%1,%2,%3}, [%4];"
        : "=r"(r[0]), "=r"(r[1]), "=r"(r[2]), "=r"(r[3]) : "r"(addr));
}
__device__ __forceinline__ void ldsm2t(uint32_t* r, uint32_t addr) {
    asm volatile("ldmatrix.sync.aligned.m8n8.x2.trans.shared.b16 {%0,%1}, [%2];"
        : "=r"(r[0]), "=r"(r[1]) : "r"(addr));
}
__device__ __forceinline__ void mma16816(float* c, const uint32_t* a, const uint32_t* b) {
    asm volatile(
        "mma.sync.aligned.m16n8k16.row.col.f32.bf16.bf16.f32 "
        "{%0,%1,%2,%3},{%4,%5,%6,%7},{%8,%9},{%0,%1,%2,%3};"
        : "+f"(c[0]), "+f"(c[1]), "+f"(c[2]), "+f"(c[3])
        : "r"(a[0]), "r"(a[1]), "r"(a[2]), "r"(a[3]), "r"(b[0]), "r"(b[1]));
}
__device__ __forceinline__ void split1(float v, __nv_bfloat16& h, __nv_bfloat16& l) {
    h = __float2bfloat16_rn(v);
    l = __float2bfloat16_rn(v - __bfloat162float(h));
}
__device__ __forceinline__ uint32_t pack_split2(float x0, float x1,
                                                uint32_t& lw) {
    __nv_bfloat16 h0, l0, h1, l1;
    split1(x0, h0, l0); split1(x1, h1, l1);
    lw = (uint32_t)*(uint16_t*)&l0 | ((uint32_t)*(uint16_t*)&l1 << 16);
    return (uint32_t)*(uint16_t*)&h0 | ((uint32_t)*(uint16_t*)&h1 << 16);
}

// ===========================================================================
// weight transpose + bf16 split: oh/ol[c*R + r] = split(in[r*C + c])
// ===========================================================================
__global__ void transpose_split_kernel(const float* __restrict__ in,
                                       __nv_bfloat16* __restrict__ oh,
                                       __nv_bfloat16* __restrict__ ol,
                                       int R, int C) {
    __shared__ float t[32][33];
    int c0 = blockIdx.x * 32, r0 = blockIdx.y * 32;
    int x = threadIdx.x, y = threadIdx.y;   // 32 x 8
#pragma unroll
    for (int i = 0; i < 32; i += 8)
        t[y + i][x] = in[(size_t)(r0 + y + i) * C + c0 + x];
    __syncthreads();
#pragma unroll
    for (int i = 0; i < 32; i += 8) {
        float v = t[x][y + i];
        __nv_bfloat16 h, l;
        split1(v, h, l);
        size_t o = (size_t)(c0 + y + i) * R + r0 + x;
        oh[o] = h; ol[o] = l;
    }
}

// ===========================================================================
// bf16x3 mma GEMM: C[M,N] = (Ah+Al)[M,K] @ (Bh+Bl)[N,K]^T
// Unified config: CTA 128x64, 4 warps of 64x32, 128 threads, 3-stage
// cp.async pipeline, 2 CTAs/SM. All 24 ldsm for a k32 chunk are issued
// before the first mma (fragment prefetch; LDS latency exposed once).
// MODE 0: fp32 out C.  MODE 1: (opt relu) + bf16-split out (Ch, Cl).
// ===========================================================================
template <int MODE, bool RELU>
__global__ void __launch_bounds__(128, 2)
bf16_gemm(const __nv_bfloat16* __restrict__ Ah, const __nv_bfloat16* __restrict__ Al,
          const __nv_bfloat16* __restrict__ Bh, const __nv_bfloat16* __restrict__ Bl,
          float* __restrict__ C,
          __nv_bfloat16* __restrict__ Ch, __nv_bfloat16* __restrict__ Cl,
          int M, int N, int ldk, int lenK) {
    constexpr int BM = 128, BN = 64, WM = 64, WN = 32;
    constexpr int MI = WM / 16;   // 4
    constexpr int NI = WN / 8;    // 4
    constexpr int WGN = BN / WN;  // 2
    constexpr int ROWS = 2 * (BM + BN);      // 384
    constexpr uint32_t SSTR = (uint32_t)ROWS * 80;
    constexpr uint32_t OFF_AH = 0;
    constexpr uint32_t OFF_AL = (uint32_t)BM * 80;
    constexpr uint32_t OFF_BH = (uint32_t)(2 * BM) * 80;
    constexpr uint32_t OFF_BL = (uint32_t)(2 * BM + BN) * 80;

    extern __shared__ char smem[];
    uint32_t sbase = smem_u32(smem);
    int tid = threadIdx.x, lane = tid & 31, wid = tid >> 5;
    int wn = wid % WGN, wm = wid / WGN;
    int g = lane >> 2, t = lane & 3;
    int m0 = blockIdx.y * BM, n0 = blockIdx.x * BN;
    const int nk = lenK >> 5;

    auto load_stage = [&](int stage, int k0) {
        uint32_t dst0 = sbase + (uint32_t)stage * SSTR;
#pragma unroll
        for (int idx = tid; idx < ROWS * 4; idx += 128) {
            int r = idx >> 2, c = idx & 3;
            const __nv_bfloat16* src;
            if (r < BM)               src = Ah + (size_t)(m0 + r) * ldk;
            else if (r < 2 * BM)      src = Al + (size_t)(m0 + r - BM) * ldk;
            else if (r < 2 * BM + BN) src = Bh + (size_t)(n0 + r - 2 * BM) * ldk;
            else                      src = Bl + (size_t)(n0 + r - 2 * BM - BN) * ldk;
            cp16(dst0 + (uint32_t)(r * 80 + c * 16), src + k0 + c * 8);
        }
    };

    uint32_t aRel = (uint32_t)((wm * WM + (lane & 15)) * 80 + ((lane >> 4) & 1) * 16);
    uint32_t bRel = (uint32_t)((wn * WN + (lane & 7) + ((lane >> 4) << 3)) * 80
                               + ((lane >> 3) & 1) * 16);

#pragma unroll
    for (int s = 0; s < 3; s++) { load_stage(s, s * 32); cp_commit(); }

    float acc[MI][NI][4];
#pragma unroll
    for (int mi = 0; mi < MI; mi++)
#pragma unroll
        for (int ni = 0; ni < NI; ni++)
#pragma unroll
            for (int j = 0; j < 4; j++) acc[mi][ni][j] = 0.f;

    for (int kc = 0; kc < nk; kc++) {
        int s = kc % 3;
        cp_wait<2>();
        __syncthreads();
        uint32_t stg = sbase + (uint32_t)s * SSTR;

        // ---- fragment prefetch: issue ALL ldsm for both k16 halves ----
        uint32_t ah[2][MI][4], al[2][MI][4];
        uint32_t bh[2][NI][2], bl[2][NI][2];
#pragma unroll
        for (int u = 0; u < 2; u++) {
            uint32_t koff = (uint32_t)(u * 32);
#pragma unroll
            for (int mi = 0; mi < MI; mi++) {
                ldsm4(ah[u][mi], stg + OFF_AH + aRel + mi * (16 * 80) + koff);
                ldsm4(al[u][mi], stg + OFF_AL + aRel + mi * (16 * 80) + koff);
            }
#pragma unroll
            for (int n2 = 0; n2 < NI / 2; n2++) {
                uint32_t r4[4];
                ldsm4(r4, stg + OFF_BH + bRel + n2 * (16 * 80) + koff);
                bh[u][2*n2][0] = r4[0]; bh[u][2*n2][1] = r4[1];
                bh[u][2*n2+1][0] = r4[2]; bh[u][2*n2+1][1] = r4[3];
                ldsm4(r4, stg + OFF_BL + bRel + n2 * (16 * 80) + koff);
                bl[u][2*n2][0] = r4[0]; bl[u][2*n2][1] = r4[1];
                bl[u][2*n2+1][0] = r4[2]; bl[u][2*n2+1][1] = r4[3];
            }
        }
        // ---- all mmas ----
#pragma unroll
        for (int u = 0; u < 2; u++)
#pragma unroll
            for (int mi = 0; mi < MI; mi++)
#pragma unroll
                for (int ni = 0; ni < NI; ni++) {
                    mma16816(acc[mi][ni], ah[u][mi], bh[u][ni]);
                    mma16816(acc[mi][ni], al[u][mi], bh[u][ni]);
                    mma16816(acc[mi][ni], ah[u][mi], bl[u][ni]);
                }
        __syncthreads();
        if (kc + 3 < nk) load_stage(s, (kc + 3) * 32);
        cp_commit();
    }

#pragma unroll
    for (int mi = 0; mi < MI; mi++) {
        int row0 = m0 + wm * WM + mi * 16 + g;
#pragma unroll
        for (int ni = 0; ni < NI; ni++) {
            int col = n0 + wn * WN + ni * 8 + 2 * t;
            if (MODE == 0) {
                float2 v0, v1;
                v0.x = acc[mi][ni][0]; v0.y = acc[mi][ni][1];
                v1.x = acc[mi][ni][2]; v1.y = acc[mi][ni][3];
                *(float2*)(C + (size_t)row0 * N + col)       = v0;
                *(float2*)(C + (size_t)(row0 + 8) * N + col) = v1;
            } else {
#pragma unroll
                for (int hrow = 0; hrow < 2; hrow++) {
                    int row = row0 + hrow * 8;
                    float x0 = acc[mi][ni][hrow*2+0];
                    float x1 = acc[mi][ni][hrow*2+1];
                    if (RELU) { x0 = fmaxf(x0, 0.f); x1 = fmaxf(x1, 0.f); }
                    uint32_t lw;
                    uint32_t hw = pack_split2(x0, x1, lw);
                    size_t e = ((size_t)row * N + col) >> 1;
                    ((uint32_t*)Ch)[e] = hw;
                    ((uint32_t*)Cl)[e] = lw;
                }
            }
        }
    }
}

// ===========================================================================
// x = x_in + t_pos + s_pos  (+ bf16 split planes)
// ===========================================================================
__global__ void add_pos_kernel(const float* __restrict__ x,
                               const float* __restrict__ tpos,
                               const float* __restrict__ spos) {
    int i = blockIdx.x * blockDim.x + threadIdx.x;
    if (i >= NM * NE) return;
    int e = i % NE;
    int s = (i / NE) % NS;
    float v = x[i] + tpos[(s / NT) * NE + e] + spos[(s % NT) * NE + e];
    g_x[i] = v;
    __nv_bfloat16 h, l;
    split1(v, h, l);
    g_xh[i] = h; g_xl[i] = l;
}

__global__ void pad_kernel() {
    int i = blockIdx.x * blockDim.x + threadIdx.x;
    if (i < NB * NS) g_pad[i] = (g_x[(size_t)i * NE] == 0.0f) ? 1 : 0;
}

// ===========================================================================
// scores_mma: 128x128 tile of q.k^T * scale, causal+pad masked -> fp32 attn.
// ===========================================================================
__global__ void __launch_bounds__(256)
scores_mma(const __nv_bfloat16* __restrict__ qkvh,
           const __nv_bfloat16* __restrict__ qkvl,
           float* __restrict__ attn) {
    int kt = blockIdx.x, qt = blockIdx.y, bh = blockIdx.z;
    if (kt > qt) return;
    int b = bh / NH, h = bh % NH;

    extern __shared__ char smem[];
    uint32_t sb = smem_u32(smem);
    const uint32_t QH = 0, QL = 128*144, KH = 2*128*144, KL = 3*128*144;

    int tid = threadIdx.x, lane = tid & 31, wid = tid >> 5;
    int wm = wid >> 1, wn = wid & 1;
    int g = lane >> 2, t = lane & 3;

    for (int idx = tid; idx < 128 * 8; idx += 256) {
        int r = idx >> 3, c = idx & 7;
        size_t qrow = (size_t)(b * NS + qt * 128 + r) * NQKV + h * DK + c * 8;
        size_t krow = (size_t)(b * NS + kt * 128 + r) * NQKV + NE + h * DK + c * 8;
        uint32_t d = (uint32_t)(r * 144 + c * 16);
        cp16(sb + QH + d, qkvh + qrow);
        cp16(sb + QL + d, qkvl + qrow);
        cp16(sb + KH + d, qkvh + krow);
        cp16(sb + KL + d, qkvl + krow);
    }
    cp_commit();
    cp_wait<0>();
    __syncthreads();

    uint32_t aRel = (uint32_t)((wm * 32 + (lane & 15)) * 144 + ((lane >> 4) & 1) * 16);
    uint32_t bRel = (uint32_t)((wn * 64 + (lane & 7) + ((lane >> 4) << 3)) * 144
                               + ((lane >> 3) & 1) * 16);

    float acc[2][8][4];
#pragma unroll
    for (int mi = 0; mi < 2; mi++)
#pragma unroll
        for (int ni = 0; ni < 8; ni++)
#pragma unroll
            for (int j = 0; j < 4; j++) acc[mi][ni][j] = 0.f;

#pragma unroll
    for (int kk = 0; kk < 4; kk++) {
        uint32_t koff = (uint32_t)(kk * 32);
        uint32_t ah[2][4], al[2][4];
#pragma unroll
        for (int mi = 0; mi < 2; mi++) {
            ldsm4(ah[mi], sb + QH + aRel + mi * (16 * 144) + koff);
            ldsm4(al[mi], sb + QL + aRel + mi * (16 * 144) + koff);
        }
        uint32_t bh_[8][2], bl_[8][2];
#pragma unroll
        for (int n2 = 0; n2 < 4; n2++) {
            uint32_t r4[4];
            ldsm4(r4, sb + KH + bRel + n2 * (16 * 144) + koff);
            bh_[2*n2][0] = r4[0]; bh_[2*n2][1] = r4[1];
            bh_[2*n2+1][0] = r4[2]; bh_[2*n2+1][1] = r4[3];
            ldsm4(r4, sb + KL + bRel + n2 * (16 * 144) + koff);
            bl_[2*n2][0] = r4[0]; bl_[2*n2][1] = r4[1];
            bl_[2*n2+1][0] = r4[2]; bl_[2*n2+1][1] = r4[3];
        }
#pragma unroll
        for (int mi = 0; mi < 2; mi++)
#pragma unroll
            for (int ni = 0; ni < 8; ni++) {
                mma16816(acc[mi][ni], ah[mi], bh_[ni]);
                mma16816(acc[mi][ni], al[mi], bh_[ni]);
                mma16816(acc[mi][ni], ah[mi], bl_[ni]);
            }
    }

    float* out = attn + (size_t)bh * NS * NS;
    const float scale = 0.125f;
#pragma unroll
    for (int mi = 0; mi < 2; mi++) {
#pragma unroll
        for (int hrow = 0; hrow < 2; hrow++) {
            int qi = qt * 128 + wm * 32 + mi * 16 + g + hrow * 8;
#pragma unroll
            for (int ni = 0; ni < 8; ni++) {
                int ki = kt * 128 + wn * 64 + ni * 8 + 2 * t;
                float v0 = acc[mi][ni][hrow*2+0] * scale;
                float v1 = acc[mi][ni][hrow*2+1] * scale;
                if (ki     > qi || g_pad[b * NS + ki])     v0 = -1e9f;
                if (ki + 1 > qi || g_pad[b * NS + ki + 1]) v1 = -1e9f;
                float2 v; v.x = v0; v.y = v1;
                *(float2*)(out + (size_t)qi * NS + ki) = v;
            }
        }
    }
}

// ===========================================================================
// Row softmax over k in [0, q]; zeros for k > q. Also writes bf16 split
// planes (zero-padded to 128-boundary) for the ctx mma.
// ===========================================================================
__global__ void softmax_kernel(float* __restrict__ attn,
                               __nv_bfloat16* __restrict__ ph,
                               __nv_bfloat16* __restrict__ pl) {
    int q  = blockIdx.x;
    int bh = blockIdx.y;
    size_t pbase = (size_t)bh * NS * NS + (size_t)q * NS;
    float* row = attn + pbase;
    int n = q + 1;

    __shared__ float buf[NS];
    __shared__ float red[8];
    int tid = threadIdx.x;

    float m = -1e30f;
    for (int i = tid; i < n; i += 256) { float v = row[i]; buf[i] = v; m = fmaxf(m, v); }
#pragma unroll
    for (int o = 16; o; o >>= 1) m = fmaxf(m, __shfl_xor_sync(0xffffffffu, m, o));
    if ((tid & 31) == 0) red[tid >> 5] = m;
    __syncthreads();
    if (tid < 32) {
        float r = (tid < 8) ? red[tid] : -1e30f;
#pragma unroll
        for (int o = 4; o; o >>= 1) r = fmaxf(r, __shfl_xor_sync(0xffffffffu, r, o));
        if (tid == 0) red[0] = r;
    }
    __syncthreads();
    float mx = red[0];
    __syncthreads();

    float s = 0.f;
    for (int i = tid; i < n; i += 256) { float e = expf(buf[i] - mx); buf[i] = e; s += e; }
#pragma unroll
    for (int o = 16; o; o >>= 1) s += __shfl_xor_sync(0xffffffffu, s, o);
    if ((tid & 31) == 0) red[tid >> 5] = s;
    __syncthreads();
    if (tid < 32) {
        float r = (tid < 8) ? red[tid] : 0.f;
#pragma unroll
        for (int o = 4; o; o >>= 1) r += __shfl_xor_sync(0xffffffffu, r, o);
        if (tid == 0) red[0] = r;
    }
    __syncthreads();
    float inv = 1.0f / red[0];

    for (int i = tid; i < n; i += 256) {
        float p = buf[i] * inv;
        row[i] = p;
        __nv_bfloat16 h, l;
        split1(p, h, l);
        ph[pbase + i] = h; pl[pbase + i] = l;
    }
    int npad = (n + 127) & ~127;
    __nv_bfloat16 z = __float2bfloat16(0.f);
    for (int i = n + tid; i < NS; i += 256) row[i] = 0.0f;
    for (int i = n + tid; i < npad; i += 256) { ph[pbase + i] = z; pl[pbase + i] = z; }
}

// ===========================================================================
// ctx_mma: ctx[128q x 64d] = attn_planes @ v_planes (causal kt loop).
// ===========================================================================
__global__ void __launch_bounds__(256)
ctx_mma(const __nv_bfloat16* __restrict__ ph, const __nv_bfloat16* __restrict__ pl,
        const __nv_bfloat16* __restrict__ qkvh, const __nv_bfloat16* __restrict__ qkvl,
        __nv_bfloat16* __restrict__ ch, __nv_bfloat16* __restrict__ cl) {
    int qt = (int)gridDim.x - 1 - (int)blockIdx.x;   // heavy tiles first
    int bh = blockIdx.y;
    int b = bh / NH, h = bh % NH;

    extern __shared__ char smem[];
    uint32_t sb = smem_u32(smem);
    const uint32_t AH = 0, AL = 128*272, VH = 2*128*272, VL = 2*128*272 + 128*144;

    int tid = threadIdx.x, lane = tid & 31, wid = tid >> 5;
    int wm = wid >> 1, wn = wid & 1;
    int g = lane >> 2, t = lane & 3;

    uint32_t aRel = (uint32_t)((wm * 32 + (lane & 15)) * 272 + ((lane >> 4) & 1) * 16);

    float acc[2][4][4];
#pragma unroll
    for (int mi = 0; mi < 2; mi++)
#pragma unroll
        for (int ni = 0; ni < 4; ni++)
#pragma unroll
            for (int j = 0; j < 4; j++) acc[mi][ni][j] = 0.f;

    for (int kt = 0; kt <= qt; kt++) {
        for (int idx = tid; idx < 128 * 16; idx += 256) {
            int r = idx >> 4, c = idx & 15;
            size_t arow = (size_t)bh * NS * NS + (size_t)(qt * 128 + r) * NS
                        + kt * 128 + c * 8;
            uint32_t d = (uint32_t)(r * 272 + c * 16);
            cp16(sb + AH + d, ph + arow);
            cp16(sb + AL + d, pl + arow);
        }
        for (int idx = tid; idx < 128 * 8; idx += 256) {
            int r = idx >> 3, c = idx & 7;
            size_t vrow = (size_t)(b * NS + kt * 128 + r) * NQKV + 1536 + h * DK + c * 8;
            uint32_t d = (uint32_t)(r * 144 + c * 16);
            cp16(sb + VH + d, qkvh + vrow);
            cp16(sb + VL + d, qkvl + vrow);
        }
        cp_commit();
        cp_wait<0>();
        __syncthreads();

#pragma unroll
        for (int kk = 0; kk < 8; kk++) {
            uint32_t koff = (uint32_t)(kk * 32);
            uint32_t ah[2][4], al[2][4];
#pragma unroll
            for (int mi = 0; mi < 2; mi++) {
                ldsm4(ah[mi], sb + AH + aRel + mi * (16 * 272) + koff);
                ldsm4(al[mi], sb + AL + aRel + mi * (16 * 272) + koff);
            }
            uint32_t vrowRel = (uint32_t)((kk * 16 + (lane & 15)) * 144);
            uint32_t bh_[4][2], bl_[4][2];
#pragma unroll
            for (int ni = 0; ni < 4; ni++) {
                uint32_t coff = (uint32_t)((wn * 32 + ni * 8) * 2);
                ldsm2t(bh_[ni], sb + VH + vrowRel + coff);
                ldsm2t(bl_[ni], sb + VL + vrowRel + coff);
            }
#pragma unroll
            for (int mi = 0; mi < 2; mi++)
#pragma unroll
                for (int ni = 0; ni < 4; ni++) {
                    mma16816(acc[mi][ni], ah[mi], bh_[ni]);
                    mma16816(acc[mi][ni], al[mi], bh_[ni]);
                    mma16816(acc[mi][ni], ah[mi], bl_[ni]);
                }
        }
        __syncthreads();
    }

#pragma unroll
    for (int mi = 0; mi < 2; mi++) {
#pragma unroll
        for (int ni = 0; ni < 4; ni++) {
            int dcol = h * DK + wn * 32 + ni * 8 + 2 * t;
#pragma unroll
            for (int hrow = 0; hrow < 2; hrow++) {
                int q = qt * 128 + wm * 32 + mi * 16 + g + hrow * 8;
                uint32_t lw;
                uint32_t hw = pack_split2(acc[mi][ni][hrow*2], acc[mi][ni][hrow*2+1], lw);
                size_t e = ((size_t)(b * NS + q) * NE + dcol) >> 1;
                ((uint32_t*)ch)[e] = hw;
                ((uint32_t*)cl)[e] = lw;
            }
        }
    }
}

// ===========================================================================
// x = LayerNorm(y1 [+ y2] + x) * g + b  (in place; writes split planes)
// ===========================================================================
__global__ void ln_kernel(const float* __restrict__ y1,
                          const float* __restrict__ y2,
                          float* __restrict__ xio,
                          const float* __restrict__ gamma,
                          const float* __restrict__ beta) {
    int row = blockIdx.x;
    __shared__ float buf[NE];
    __shared__ float red[8];
    int tid = threadIdx.x;

    float s = 0.f;
    for (int i = tid; i < NE; i += 256) {
        size_t o = (size_t)row * NE + i;
        float v = y1[o] + xio[o];
        if (y2) v += y2[o];
        buf[i] = v;
        s += v;
    }
#pragma unroll
    for (int o = 16; o; o >>= 1) s += __shfl_xor_sync(0xffffffffu, s, o);
    if ((tid & 31) == 0) red[tid >> 5] = s;
    __syncthreads();
    if (tid < 32) {
        float r = (tid < 8) ? red[tid] : 0.f;
#pragma unroll
        for (int o = 4; o; o >>= 1) r += __shfl_xor_sync(0xffffffffu, r, o);
        if (tid == 0) red[0] = r;
    }
    __syncthreads();
    float mean = red[0] * (1.0f / NE);
    __syncthreads();

    float vs = 0.f;
    for (int i = tid; i < NE; i += 256) {
        float d = buf[i] - mean;
        vs += d * d;
    }
#pragma unroll
    for (int o = 16; o; o >>= 1) vs += __shfl_xor_sync(0xffffffffu, vs, o);
    if ((tid & 31) == 0) red[tid >> 5] = vs;
    __syncthreads();
    if (tid < 32) {
        float r = (tid < 8) ? red[tid] : 0.f;
#pragma unroll
        for (int o = 4; o; o >>= 1) r += __shfl_xor_sync(0xffffffffu, r, o);
        if (tid == 0) red[0] = r;
    }
    __syncthreads();
    float rstd = rsqrtf(red[0] * (1.0f / NE) + EPS);

    for (int i = tid; i < NE; i += 256) {
        float v = (buf[i] - mean) * rstd * gamma[i] + beta[i];
        size_t o = (size_t)row * NE + i;
        xio[o] = v;
        __nv_bfloat16 h, l;
        split1(v, h, l);
        g_xh[o] = h; g_xl[o] = l;
    }
}

__global__ void copy_x_kernel(float* __restrict__ out) {
    int i = blockIdx.x * blockDim.x + threadIdx.x;
    if (i < NM * NE) out[i] = g_x[i];
}

// ===========================================================================
extern "C" void kernel_launch(void* const* d_in, const int* in_sizes, int n_in,
                              void* d_out, int out_size) {
    const float* x    = (const float*)d_in[0];
    const float* tpos = (const float*)d_in[1];
    const float* spos = (const float*)d_in[2];
    const float* Wq   = (const float*)d_in[3];
    const float* Wk   = (const float*)d_in[4];
    const float* Wv   = (const float*)d_in[5];
    const float* Wo   = (const float*)d_in[6];
    const float* ln1g = (const float*)d_in[7];
    const float* ln1b = (const float*)d_in[8];
    const float* W1   = (const float*)d_in[9];
    const float* W2   = (const float*)d_in[10];
    const float* ln2g = (const float*)d_in[11];
    const float* ln2b = (const float*)d_in[12];

    float* out      = (float*)d_out;
    float* attn_out = out + (size_t)NM * NE;

    float *px, *ptmp, *ptmp2;
    __nv_bfloat16 *pxh, *pxl, *pqkvh, *pqkvl, *pch, *pcl, *phh, *phl, *pah, *pal;
    __nv_bfloat16 *pwqkvh, *pwqkvl, *pwoh, *pwol, *pw1h, *pw1l, *pw2h, *pw2l;
    cudaGetSymbolAddress((void**)&px,    g_x);
    cudaGetSymbolAddress((void**)&ptmp,  g_tmp);
    cudaGetSymbolAddress((void**)&ptmp2, g_tmp2);
    cudaGetSymbolAddress((void**)&pxh,   g_xh);
    cudaGetSymbolAddress((void**)&pxl,   g_xl);
    cudaGetSymbolAddress((void**)&pqkvh, g_qkvh);
    cudaGetSymbolAddress((void**)&pqkvl, g_qkvl);
    cudaGetSymbolAddress((void**)&pch,   g_ch);
    cudaGetSymbolAddress((void**)&pcl,   g_cl);
    cudaGetSymbolAddress((void**)&phh,   g_hh);
    cudaGetSymbolAddress((void**)&phl,   g_hl);
    cudaGetSymbolAddress((void**)&pah,   g_ah);
    cudaGetSymbolAddress((void**)&pal,   g_al);
    cudaGetSymbolAddress((void**)&pwqkvh, g_wqkvh);
    cudaGetSymbolAddress((void**)&pwqkvl, g_wqkvl);
    cudaGetSymbolAddress((void**)&pwoh,  g_woh);
    cudaGetSymbolAddress((void**)&pwol,  g_wol);
    cudaGetSymbolAddress((void**)&pw1h,  g_w1h);
    cudaGetSymbolAddress((void**)&pw1l,  g_w1l);
    cudaGetSymbolAddress((void**)&pw2h,  g_w2h);
    cudaGetSymbolAddress((void**)&pw2l,  g_w2l);

    const int SM_P  = 2 * (128 + 64) * 80 * 3;       //  92,160
    const int SM_SC = 4 * 128 * 144;                 //  73,728
    const int SM_CX = 2 * 128 * 272 + 2 * 128 * 144; // 106,496

    cudaFuncSetAttribute((const void*)bf16_gemm<0,false>,
        cudaFuncAttributeMaxDynamicSharedMemorySize, SM_P);
    cudaFuncSetAttribute((const void*)bf16_gemm<1,false>,
        cudaFuncAttributeMaxDynamicSharedMemorySize, SM_P);
    cudaFuncSetAttribute((const void*)bf16_gemm<1,true>,
        cudaFuncAttributeMaxDynamicSharedMemorySize, SM_P);
    cudaFuncSetAttribute((const void*)scores_mma,
        cudaFuncAttributeMaxDynamicSharedMemorySize, SM_SC);
    cudaFuncSetAttribute((const void*)ctx_mma,
        cudaFuncAttributeMaxDynamicSharedMemorySize, SM_CX);

    add_pos_kernel<<<(NM * NE + 255) / 256, 256>>>(x, tpos, spos);
    pad_kernel<<<(NB * NS + 255) / 256, 256>>>();

    // transpose + split all weights to K-major bf16 planes (QKV concatenated)
    {
        dim3 blk(32, 8);
        dim3 gEE(NE / 32, NE / 32);
        dim3 gE_F(DFF / 32, NE / 32);    // W1 [768,3072] -> [3072,768]
        dim3 gF_E(NE / 32, DFF / 32);    // W2 [3072,768] -> [768,3072]
        for (int l = 0; l < NL; l++) {
            size_t oE = (size_t)l * NE * NE, oF = (size_t)l * NE * DFF;
            size_t oQ = (size_t)l * NQKV * NE;
            transpose_split_kernel<<<gEE, blk>>>(Wq + oE, pwqkvh + oQ,
                                                 pwqkvl + oQ, NE, NE);
            transpose_split_kernel<<<gEE, blk>>>(Wk + oE, pwqkvh + oQ + (size_t)NE*NE,
                                                 pwqkvl + oQ + (size_t)NE*NE, NE, NE);
            transpose_split_kernel<<<gEE, blk>>>(Wv + oE, pwqkvh + oQ + (size_t)2*NE*NE,
                                                 pwqkvl + oQ + (size_t)2*NE*NE, NE, NE);
            transpose_split_kernel<<<gEE, blk>>>(Wo + oE, pwoh + oE, pwol + oE, NE, NE);
            transpose_split_kernel<<<gE_F, blk>>>(W1 + oF, pw1h + oF, pw1l + oF, NE, DFF);
            transpose_split_kernel<<<gF_E, blk>>>(W2 + oF, pw2h + oF, pw2l + oF, DFF, NE);
        }
    }

    dim3 gQKV(NQKV / 64, NM / 128);            // (36, 16)
    dim3 gWo(NE / 64, NM / 128);               // (12, 16)
    dim3 gFF1(DFF / 64, NM / 128);             // (48, 16)
    dim3 gScores(NS / 128, NS / 128, NB * NH); // (8, 8, 24)
    dim3 gSoft(NS, NB * NH);
    dim3 gCtx(NS / 128, NB * NH);              // (8, 24)

    for (int l = 0; l < NL; l++) {
        size_t oE = (size_t)l * NE * NE, oF = (size_t)l * NE * DFF;
        size_t oQ = (size_t)l * NQKV * NE;
        float* attn_l = attn_out + (size_t)l * NB * NH * NS * NS;

        bf16_gemm<1,false><<<gQKV, 128, SM_P>>>(
            pxh, pxl, pwqkvh + oQ, pwqkvl + oQ,
            nullptr, pqkvh, pqkvl, NM, NQKV, NE, NE);

        scores_mma<<<gScores, 256, SM_SC>>>(pqkvh, pqkvl, attn_l);
        softmax_kernel<<<gSoft, 256>>>(attn_l, pah, pal);
        ctx_mma<<<gCtx, 256, SM_CX>>>(pah, pal, pqkvh, pqkvl, pch, pcl);

        // Wo split-K x2: halves summed inside ln_kernel
        bf16_gemm<0,false><<<gWo, 128, SM_P>>>(
            pch, pcl, pwoh + oE, pwol + oE, ptmp, nullptr, nullptr,
            NM, NE, NE, 384);
        bf16_gemm<0,false><<<gWo, 128, SM_P>>>(
            pch + 384, pcl + 384, pwoh + oE + 384, pwol + oE + 384,
            ptmp2, nullptr, nullptr, NM, NE, NE, 384);
        ln_kernel<<<NM, 256>>>(ptmp, ptmp2, px,
                               ln1g + (size_t)l * NE, ln1b + (size_t)l * NE);

        bf16_gemm<1,true><<<gFF1, 128, SM_P>>>(
            pxh, pxl, pw1h + oF, pw1l + oF, nullptr, phh, phl,
            NM, DFF, NE, NE);

        // FFN2 split-K x2
        bf16_gemm<0,false><<<gWo, 128, SM_P>>>(
            phh, phl, pw2h + oF, pw2l + oF, ptmp, nullptr, nullptr,
            NM, NE, DFF, 1536);
        bf16_gemm<0,false><<<gWo, 128, SM_P>>>(
            phh + 1536, phl + 1536, pw2h + oF + 1536, pw2l + oF + 1536,
            ptmp2, nullptr, nullptr, NM, NE, DFF, 1536);
        ln_kernel<<<NM, 256>>>(ptmp, ptmp2, px,
                               ln2g + (size_t)l * NE, ln2b + (size_t)l * NE);
    }

    copy_x_kernel<<<(NM * NE + 255) / 256, 256>>>(out);
}

// round 7
// speedup vs baseline: 2.1536x; 1.0838x over previous
#include <cuda_runtime.h>
#include <cuda_bf16.h>
#include <math.h>
#include <stdint.h>

#define NL 6
#define NB 2
#define NF 16
#define NT 64
#define NS 1024
#define NE 768
#define NH 12
#define DK 64
#define DFF 3072
#define NM (NB*NS)        // 2048 rows
#define NQKV 2304
#define EPS 1e-5f

// ---- scratch (allocation-free rule: __device__ globals) ----
__device__ float g_x[NM*NE];
__device__ float g_tmp[NM*NE];
__device__ float g_tmp2[NM*NE];
__device__ int   g_pad[NB*NS];
// bf16 split planes
__device__ __nv_bfloat16 g_xh[NM*NE],  g_xl[NM*NE];
__device__ __nv_bfloat16 g_qkvh[NM*NQKV], g_qkvl[NM*NQKV];
__device__ __nv_bfloat16 g_ch[NM*NE],  g_cl[NM*NE];            // ctx
__device__ __nv_bfloat16 g_hh[NM*DFF], g_hl[NM*DFF];           // hidden
__device__ __nv_bfloat16 g_ah[(size_t)NB*NH*NS*NS];            // attn hi
__device__ __nv_bfloat16 g_al[(size_t)NB*NH*NS*NS];            // attn lo
// K-major weight planes; QKV concatenated [2304 x 768]
__device__ __nv_bfloat16 g_wqkvh[NL*(size_t)NQKV*NE], g_wqkvl[NL*(size_t)NQKV*NE];
__device__ __nv_bfloat16 g_woh[NL*NE*NE],             g_wol[NL*NE*NE];
__device__ __nv_bfloat16 g_w1h[NL*(size_t)NE*DFF],    g_w1l[NL*(size_t)NE*DFF];
__device__ __nv_bfloat16 g_w2h[NL*(size_t)NE*DFF],    g_w2l[NL*(size_t)NE*DFF];

// ===========================================================================
// PTX helpers (base-sm_103 features only)
// ===========================================================================
__device__ __forceinline__ uint32_t smem_u32(const void* p) {
    uint32_t a;
    asm("{ .reg .u64 t; cvta.to.shared.u64 t, %1; cvt.u32.u64 %0, t; }"
        : "=r"(a) : "l"(p));
    return a;
}
__device__ __forceinline__ void cp16(uint32_t s, const void* g) {
    asm volatile("cp.async.cg.shared.global [%0], [%1], 16;" :: "r"(s), "l"(g));
}
__device__ __forceinline__ void cp_commit() {
    asm volatile("cp.async.commit_group;" ::: "memory");
}
template <int N>
__device__ __forceinline__ void cp_wait() {
    asm volatile("cp.async.wait_group %0;" :: "n"(N) : "memory");
}
__device__ __forceinline__ void ldsm4(uint32_t* r, uint32_t addr) {
    asm volatile("ldmatrix.sync.aligned.m8n8.x4.shared.b16 {%0,%1,%2,%3}, [%4];"
        : "=r"(r[0]), "=r"(r[1]), "=r"(r[2]), "=r"(r[3]) : "r"(addr));
}
__device__ __forceinline__ void ldsm2t(uint32_t* r, uint32_t addr) {
    asm volatile("ldmatrix.sync.aligned.m8n8.x2.trans.shared.b16 {%0,%1}, [%2];"
        : "=r"(r[0]), "=r"(r[1]) : "r"(addr));
}
__device__ __forceinline__ void mma16816(float* c, const uint32_t* a, const uint32_t* b) {
    asm volatile(
        "mma.sync.aligned.m16n8k16.row.col.f32.bf16.bf16.f32 "
        "{%0,%1,%2,%3},{%4,%5,%6,%7},{%8,%9},{%0,%1,%2,%3};"
        : "+f"(c[0]), "+f"(c[1]), "+f"(c[2]), "+f"(c[3])
        : "r"(a[0]), "r"(a[1]), "r"(a[2]), "r"(a[3]), "r"(b[0]), "r"(b[1]));
}
__device__ __forceinline__ void split1(float v, __nv_bfloat16& h, __nv_bfloat16& l) {
    h = __float2bfloat16_rn(v);
    l = __float2bfloat16_rn(v - __bfloat162float(h));
}
__device__ __forceinline__ uint32_t pack_split2(float x0, float x1,
                                                uint32_t& lw) {
    __nv_bfloat16 h0, l0, h1, l1;
    split1(x0, h0, l0); split1(x1, h1, l1);
    lw = (uint32_t)*(uint16_t*)&l0 | ((uint32_t)*(uint16_t*)&l1 << 16);
    return (uint32_t)*(uint16_t*)&h0 | ((uint32_t)*(uint16_t*)&h1 << 16);
}

// ===========================================================================
// Batched weight transpose + split.
// EE kernel: z enumerates (layer, kind) over Wq/Wk/Wv/Wo.
// W kernel:  z enumerates layers for one [R,C] weight.
// ===========================================================================
__device__ __forceinline__ void tr_body(const float* __restrict__ in,
                                        __nv_bfloat16* __restrict__ oh,
                                        __nv_bfloat16* __restrict__ ol,
                                        int R, int C) {
    __shared__ float tb[32][33];
    int c0 = blockIdx.x * 32, r0 = blockIdx.y * 32;
    int x = threadIdx.x, y = threadIdx.y;   // 32 x 8
#pragma unroll
    for (int i = 0; i < 32; i += 8)
        tb[y + i][x] = in[(size_t)(r0 + y + i) * C + c0 + x];
    __syncthreads();
#pragma unroll
    for (int i = 0; i < 32; i += 8) {
        float v = tb[x][y + i];
        __nv_bfloat16 h, l;
        split1(v, h, l);
        size_t o = (size_t)(c0 + y + i) * R + r0 + x;
        oh[o] = h; ol[o] = l;
    }
}

__global__ void transpose_split_ee(const float* __restrict__ Wq,
                                   const float* __restrict__ Wk,
                                   const float* __restrict__ Wv,
                                   const float* __restrict__ Wo,
                                   __nv_bfloat16* __restrict__ wqkvh,
                                   __nv_bfloat16* __restrict__ wqkvl,
                                   __nv_bfloat16* __restrict__ woh,
                                   __nv_bfloat16* __restrict__ wol) {
    int zc = blockIdx.z, l = zc >> 2, kind = zc & 3;
    size_t oE = (size_t)l * NE * NE;
    size_t oQ = (size_t)l * NQKV * NE;
    const float* in;
    __nv_bfloat16 *oh, *ol;
    if (kind == 0)      { in = Wq + oE; oh = wqkvh + oQ;                    ol = wqkvl + oQ; }
    else if (kind == 1) { in = Wk + oE; oh = wqkvh + oQ + (size_t)NE*NE;    ol = wqkvl + oQ + (size_t)NE*NE; }
    else if (kind == 2) { in = Wv + oE; oh = wqkvh + oQ + (size_t)2*NE*NE;  ol = wqkvl + oQ + (size_t)2*NE*NE; }
    else                { in = Wo + oE; oh = woh + oE;                      ol = wol + oE; }
    tr_body(in, oh, ol, NE, NE);
}

__global__ void transpose_split_w(const float* __restrict__ in0,
                                  __nv_bfloat16* __restrict__ oh0,
                                  __nv_bfloat16* __restrict__ ol0,
                                  int R, int C) {
    size_t off = (size_t)blockIdx.z * NE * DFF;
    tr_body(in0 + off, oh0 + off, ol0 + off, R, C);
}

// ===========================================================================
// bf16x3 mma GEMM: C[M,N] = (Ah+Al)[M,K] @ (Bh+Bl)[N,K]^T
// CTA 128x64, 4 warps of 64x32, 128 threads, 3-stage cp.async, 2 CTAs/SM.
// Fragment prefetch (all 24 ldsm per k32 before mmas).
// blockIdx.z == 1 selects the second split-K half: A/B advanced by ksh
// elements within the row, output redirected to C2.
// MODE 0: fp32 out.  MODE 1: (opt relu) + bf16-split out (Ch, Cl).
// ===========================================================================
template <int MODE, bool RELU>
__global__ void __launch_bounds__(128, 2)
bf16_gemm(const __nv_bfloat16* __restrict__ Ah, const __nv_bfloat16* __restrict__ Al,
          const __nv_bfloat16* __restrict__ Bh, const __nv_bfloat16* __restrict__ Bl,
          float* __restrict__ C, float* __restrict__ C2,
          __nv_bfloat16* __restrict__ Ch, __nv_bfloat16* __restrict__ Cl,
          int M, int N, int ldk, int lenK, int ksh) {
    constexpr int BM = 128, BN = 64, WM = 64, WN = 32;
    constexpr int MI = WM / 16;   // 4
    constexpr int NI = WN / 8;    // 4
    constexpr int WGN = BN / WN;  // 2
    constexpr int ROWS = 2 * (BM + BN);      // 384
    constexpr uint32_t SSTR = (uint32_t)ROWS * 80;
    constexpr uint32_t OFF_AH = 0;
    constexpr uint32_t OFF_AL = (uint32_t)BM * 80;
    constexpr uint32_t OFF_BH = (uint32_t)(2 * BM) * 80;
    constexpr uint32_t OFF_BL = (uint32_t)(2 * BM + BN) * 80;

    if (blockIdx.z) { Ah += ksh; Al += ksh; Bh += ksh; Bl += ksh; C = C2; }

    extern __shared__ char smem[];
    uint32_t sbase = smem_u32(smem);
    int tid = threadIdx.x, lane = tid & 31, wid = tid >> 5;
    int wn = wid % WGN, wm = wid / WGN;
    int g = lane >> 2, t = lane & 3;
    int m0 = blockIdx.y * BM, n0 = blockIdx.x * BN;
    const int nk = lenK >> 5;

    auto load_stage = [&](int stage, int k0) {
        uint32_t dst0 = sbase + (uint32_t)stage * SSTR;
#pragma unroll
        for (int idx = tid; idx < ROWS * 4; idx += 128) {
            int r = idx >> 2, c = idx & 3;
            const __nv_bfloat16* src;
            if (r < BM)               src = Ah + (size_t)(m0 + r) * ldk;
            else if (r < 2 * BM)      src = Al + (size_t)(m0 + r - BM) * ldk;
            else if (r < 2 * BM + BN) src = Bh + (size_t)(n0 + r - 2 * BM) * ldk;
            else                      src = Bl + (size_t)(n0 + r - 2 * BM - BN) * ldk;
            cp16(dst0 + (uint32_t)(r * 80 + c * 16), src + k0 + c * 8);
        }
    };

    uint32_t aRel = (uint32_t)((wm * WM + (lane & 15)) * 80 + ((lane >> 4) & 1) * 16);
    uint32_t bRel = (uint32_t)((wn * WN + (lane & 7) + ((lane >> 4) << 3)) * 80
                               + ((lane >> 3) & 1) * 16);

#pragma unroll
    for (int s = 0; s < 3; s++) { load_stage(s, s * 32); cp_commit(); }

    float acc[MI][NI][4];
#pragma unroll
    for (int mi = 0; mi < MI; mi++)
#pragma unroll
        for (int ni = 0; ni < NI; ni++)
#pragma unroll
            for (int j = 0; j < 4; j++) acc[mi][ni][j] = 0.f;

    for (int kc = 0; kc < nk; kc++) {
        int s = kc % 3;
        cp_wait<2>();
        __syncthreads();
        uint32_t stg = sbase + (uint32_t)s * SSTR;

        uint32_t ah[2][MI][4], al[2][MI][4];
        uint32_t bh[2][NI][2], bl[2][NI][2];
#pragma unroll
        for (int u = 0; u < 2; u++) {
            uint32_t koff = (uint32_t)(u * 32);
#pragma unroll
            for (int mi = 0; mi < MI; mi++) {
                ldsm4(ah[u][mi], stg + OFF_AH + aRel + mi * (16 * 80) + koff);
                ldsm4(al[u][mi], stg + OFF_AL + aRel + mi * (16 * 80) + koff);
            }
#pragma unroll
            for (int n2 = 0; n2 < NI / 2; n2++) {
                uint32_t r4[4];
                ldsm4(r4, stg + OFF_BH + bRel + n2 * (16 * 80) + koff);
                bh[u][2*n2][0] = r4[0]; bh[u][2*n2][1] = r4[1];
                bh[u][2*n2+1][0] = r4[2]; bh[u][2*n2+1][1] = r4[3];
                ldsm4(r4, stg + OFF_BL + bRel + n2 * (16 * 80) + koff);
                bl[u][2*n2][0] = r4[0]; bl[u][2*n2][1] = r4[1];
                bl[u][2*n2+1][0] = r4[2]; bl[u][2*n2+1][1] = r4[3];
            }
        }
#pragma unroll
        for (int u = 0; u < 2; u++)
#pragma unroll
            for (int mi = 0; mi < MI; mi++)
#pragma unroll
                for (int ni = 0; ni < NI; ni++) {
                    mma16816(acc[mi][ni], ah[u][mi], bh[u][ni]);
                    mma16816(acc[mi][ni], al[u][mi], bh[u][ni]);
                    mma16816(acc[mi][ni], ah[u][mi], bl[u][ni]);
                }
        __syncthreads();
        if (kc + 3 < nk) load_stage(s, (kc + 3) * 32);
        cp_commit();
    }

#pragma unroll
    for (int mi = 0; mi < MI; mi++) {
        int row0 = m0 + wm * WM + mi * 16 + g;
#pragma unroll
        for (int ni = 0; ni < NI; ni++) {
            int col = n0 + wn * WN + ni * 8 + 2 * t;
            if (MODE == 0) {
                float2 v0, v1;
                v0.x = acc[mi][ni][0]; v0.y = acc[mi][ni][1];
                v1.x = acc[mi][ni][2]; v1.y = acc[mi][ni][3];
                *(float2*)(C + (size_t)row0 * N + col)       = v0;
                *(float2*)(C + (size_t)(row0 + 8) * N + col) = v1;
            } else {
#pragma unroll
                for (int hrow = 0; hrow < 2; hrow++) {
                    int row = row0 + hrow * 8;
                    float x0 = acc[mi][ni][hrow*2+0];
                    float x1 = acc[mi][ni][hrow*2+1];
                    if (RELU) { x0 = fmaxf(x0, 0.f); x1 = fmaxf(x1, 0.f); }
                    uint32_t lw;
                    uint32_t hw = pack_split2(x0, x1, lw);
                    size_t e = ((size_t)row * N + col) >> 1;
                    ((uint32_t*)Ch)[e] = hw;
                    ((uint32_t*)Cl)[e] = lw;
                }
            }
        }
    }
}

// ===========================================================================
// x = x_in + t_pos + s_pos  (+ bf16 split planes)
// ===========================================================================
__global__ void add_pos_kernel(const float* __restrict__ x,
                               const float* __restrict__ tpos,
                               const float* __restrict__ spos) {
    int i = blockIdx.x * blockDim.x + threadIdx.x;
    if (i >= NM * NE) return;
    int e = i % NE;
    int s = (i / NE) % NS;
    float v = x[i] + tpos[(s / NT) * NE + e] + spos[(s % NT) * NE + e];
    g_x[i] = v;
    __nv_bfloat16 h, l;
    split1(v, h, l);
    g_xh[i] = h; g_xl[i] = l;
}

__global__ void pad_kernel() {
    int i = blockIdx.x * blockDim.x + threadIdx.x;
    if (i < NB * NS) g_pad[i] = (g_x[(size_t)i * NE] == 0.0f) ? 1 : 0;
}

// ===========================================================================
// scores_mma: 128x128 tile of q.k^T * scale, causal+pad masked -> fp32 attn.
// ===========================================================================
__global__ void __launch_bounds__(256)
scores_mma(const __nv_bfloat16* __restrict__ qkvh,
           const __nv_bfloat16* __restrict__ qkvl,
           float* __restrict__ attn) {
    int kt = blockIdx.x, qt = blockIdx.y, bh = blockIdx.z;
    if (kt > qt) return;
    int b = bh / NH, h = bh % NH;

    extern __shared__ char smem[];
    uint32_t sb = smem_u32(smem);
    const uint32_t QH = 0, QL = 128*144, KH = 2*128*144, KL = 3*128*144;

    int tid = threadIdx.x, lane = tid & 31, wid = tid >> 5;
    int wm = wid >> 1, wn = wid & 1;
    int g = lane >> 2, t = lane & 3;

    for (int idx = tid; idx < 128 * 8; idx += 256) {
        int r = idx >> 3, c = idx & 7;
        size_t qrow = (size_t)(b * NS + qt * 128 + r) * NQKV + h * DK + c * 8;
        size_t krow = (size_t)(b * NS + kt * 128 + r) * NQKV + NE + h * DK + c * 8;
        uint32_t d = (uint32_t)(r * 144 + c * 16);
        cp16(sb + QH + d, qkvh + qrow);
        cp16(sb + QL + d, qkvl + qrow);
        cp16(sb + KH + d, qkvh + krow);
        cp16(sb + KL + d, qkvl + krow);
    }
    cp_commit();
    cp_wait<0>();
    __syncthreads();

    uint32_t aRel = (uint32_t)((wm * 32 + (lane & 15)) * 144 + ((lane >> 4) & 1) * 16);
    uint32_t bRel = (uint32_t)((wn * 64 + (lane & 7) + ((lane >> 4) << 3)) * 144
                               + ((lane >> 3) & 1) * 16);

    float acc[2][8][4];
#pragma unroll
    for (int mi = 0; mi < 2; mi++)
#pragma unroll
        for (int ni = 0; ni < 8; ni++)
#pragma unroll
            for (int j = 0; j < 4; j++) acc[mi][ni][j] = 0.f;

#pragma unroll
    for (int kk = 0; kk < 4; kk++) {
        uint32_t koff = (uint32_t)(kk * 32);
        uint32_t ah[2][4], al[2][4];
#pragma unroll
        for (int mi = 0; mi < 2; mi++) {
            ldsm4(ah[mi], sb + QH + aRel + mi * (16 * 144) + koff);
            ldsm4(al[mi], sb + QL + aRel + mi * (16 * 144) + koff);
        }
        uint32_t bh_[8][2], bl_[8][2];
#pragma unroll
        for (int n2 = 0; n2 < 4; n2++) {
            uint32_t r4[4];
            ldsm4(r4, sb + KH + bRel + n2 * (16 * 144) + koff);
            bh_[2*n2][0] = r4[0]; bh_[2*n2][1] = r4[1];
            bh_[2*n2+1][0] = r4[2]; bh_[2*n2+1][1] = r4[3];
            ldsm4(r4, sb + KL + bRel + n2 * (16 * 144) + koff);
            bl_[2*n2][0] = r4[0]; bl_[2*n2][1] = r4[1];
            bl_[2*n2+1][0] = r4[2]; bl_[2*n2+1][1] = r4[3];
        }
#pragma unroll
        for (int mi = 0; mi < 2; mi++)
#pragma unroll
            for (int ni = 0; ni < 8; ni++) {
                mma16816(acc[mi][ni], ah[mi], bh_[ni]);
                mma16816(acc[mi][ni], al[mi], bh_[ni]);
                mma16816(acc[mi][ni], ah[mi], bl_[ni]);
            }
    }

    float* out = attn + (size_t)bh * NS * NS;
    const float scale = 0.125f;
#pragma unroll
    for (int mi = 0; mi < 2; mi++) {
#pragma unroll
        for (int hrow = 0; hrow < 2; hrow++) {
            int qi = qt * 128 + wm * 32 + mi * 16 + g + hrow * 8;
#pragma unroll
            for (int ni = 0; ni < 8; ni++) {
                int ki = kt * 128 + wn * 64 + ni * 8 + 2 * t;
                float v0 = acc[mi][ni][hrow*2+0] * scale;
                float v1 = acc[mi][ni][hrow*2+1] * scale;
                if (ki     > qi || g_pad[b * NS + ki])     v0 = -1e9f;
                if (ki + 1 > qi || g_pad[b * NS + ki + 1]) v1 = -1e9f;
                float2 v; v.x = v0; v.y = v1;
                *(float2*)(out + (size_t)qi * NS + ki) = v;
            }
        }
    }
}

// ===========================================================================
// Row softmax over k in [0, q]; zeros for k > q. Also writes bf16 split
// planes (zero-padded to 128-boundary) for the ctx mma.
// ===========================================================================
__global__ void softmax_kernel(float* __restrict__ attn,
                               __nv_bfloat16* __restrict__ ph,
                               __nv_bfloat16* __restrict__ pl) {
    int q  = blockIdx.x;
    int bh = blockIdx.y;
    size_t pbase = (size_t)bh * NS * NS + (size_t)q * NS;
    float* row = attn + pbase;
    int n = q + 1;

    __shared__ float buf[NS];
    __shared__ float red[8];
    int tid = threadIdx.x;

    float m = -1e30f;
    for (int i = tid; i < n; i += 256) { float v = row[i]; buf[i] = v; m = fmaxf(m, v); }
#pragma unroll
    for (int o = 16; o; o >>= 1) m = fmaxf(m, __shfl_xor_sync(0xffffffffu, m, o));
    if ((tid & 31) == 0) red[tid >> 5] = m;
    __syncthreads();
    if (tid < 32) {
        float r = (tid < 8) ? red[tid] : -1e30f;
#pragma unroll
        for (int o = 4; o; o >>= 1) r = fmaxf(r, __shfl_xor_sync(0xffffffffu, r, o));
        if (tid == 0) red[0] = r;
    }
    __syncthreads();
    float mx = red[0];
    __syncthreads();

    float s = 0.f;
    for (int i = tid; i < n; i += 256) { float e = expf(buf[i] - mx); buf[i] = e; s += e; }
#pragma unroll
    for (int o = 16; o; o >>= 1) s += __shfl_xor_sync(0xffffffffu, s, o);
    if ((tid & 31) == 0) red[tid >> 5] = s;
    __syncthreads();
    if (tid < 32) {
        float r = (tid < 8) ? red[tid] : 0.f;
#pragma unroll
        for (int o = 4; o; o >>= 1) r += __shfl_xor_sync(0xffffffffu, r, o);
        if (tid == 0) red[0] = r;
    }
    __syncthreads();
    float inv = 1.0f / red[0];

    for (int i = tid; i < n; i += 256) {
        float p = buf[i] * inv;
        row[i] = p;
        __nv_bfloat16 h, l;
        split1(p, h, l);
        ph[pbase + i] = h; pl[pbase + i] = l;
    }
    int npad = (n + 127) & ~127;
    __nv_bfloat16 z = __float2bfloat16(0.f);
    for (int i = n + tid; i < NS; i += 256) row[i] = 0.0f;
    for (int i = n + tid; i < npad; i += 256) { ph[pbase + i] = z; pl[pbase + i] = z; }
}

// ===========================================================================
// ctx_mma: ctx[128q x 64d] = attn_planes @ v_planes (causal kt loop).
// ===========================================================================
__global__ void __launch_bounds__(256)
ctx_mma(const __nv_bfloat16* __restrict__ ph, const __nv_bfloat16* __restrict__ pl,
        const __nv_bfloat16* __restrict__ qkvh, const __nv_bfloat16* __restrict__ qkvl,
        __nv_bfloat16* __restrict__ ch, __nv_bfloat16* __restrict__ cl) {
    int qt = (int)gridDim.x - 1 - (int)blockIdx.x;   // heavy tiles first
    int bh = blockIdx.y;
    int b = bh / NH, h = bh % NH;

    extern __shared__ char smem[];
    uint32_t sb = smem_u32(smem);
    const uint32_t AH = 0, AL = 128*272, VH = 2*128*272, VL = 2*128*272 + 128*144;

    int tid = threadIdx.x, lane = tid & 31, wid = tid >> 5;
    int wm = wid >> 1, wn = wid & 1;
    int g = lane >> 2, t = lane & 3;

    uint32_t aRel = (uint32_t)((wm * 32 + (lane & 15)) * 272 + ((lane >> 4) & 1) * 16);

    float acc[2][4][4];
#pragma unroll
    for (int mi = 0; mi < 2; mi++)
#pragma unroll
        for (int ni = 0; ni < 4; ni++)
#pragma unroll
            for (int j = 0; j < 4; j++) acc[mi][ni][j] = 0.f;

    for (int kt = 0; kt <= qt; kt++) {
        for (int idx = tid; idx < 128 * 16; idx += 256) {
            int r = idx >> 4, c = idx & 15;
            size_t arow = (size_t)bh * NS * NS + (size_t)(qt * 128 + r) * NS
                        + kt * 128 + c * 8;
            uint32_t d = (uint32_t)(r * 272 + c * 16);
            cp16(sb + AH + d, ph + arow);
            cp16(sb + AL + d, pl + arow);
        }
        for (int idx = tid; idx < 128 * 8; idx += 256) {
            int r = idx >> 3, c = idx & 7;
            size_t vrow = (size_t)(b * NS + kt * 128 + r) * NQKV + 1536 + h * DK + c * 8;
            uint32_t d = (uint32_t)(r * 144 + c * 16);
            cp16(sb + VH + d, qkvh + vrow);
            cp16(sb + VL + d, qkvl + vrow);
        }
        cp_commit();
        cp_wait<0>();
        __syncthreads();

#pragma unroll
        for (int kk = 0; kk < 8; kk++) {
            uint32_t koff = (uint32_t)(kk * 32);
            uint32_t ah[2][4], al[2][4];
#pragma unroll
            for (int mi = 0; mi < 2; mi++) {
                ldsm4(ah[mi], sb + AH + aRel + mi * (16 * 272) + koff);
                ldsm4(al[mi], sb + AL + aRel + mi * (16 * 272) + koff);
            }
            uint32_t vrowRel = (uint32_t)((kk * 16 + (lane & 15)) * 144);
            uint32_t bh_[4][2], bl_[4][2];
#pragma unroll
            for (int ni = 0; ni < 4; ni++) {
                uint32_t coff = (uint32_t)((wn * 32 + ni * 8) * 2);
                ldsm2t(bh_[ni], sb + VH + vrowRel + coff);
                ldsm2t(bl_[ni], sb + VL + vrowRel + coff);
            }
#pragma unroll
            for (int mi = 0; mi < 2; mi++)
#pragma unroll
                for (int ni = 0; ni < 4; ni++) {
                    mma16816(acc[mi][ni], ah[mi], bh_[ni]);
                    mma16816(acc[mi][ni], al[mi], bh_[ni]);
                    mma16816(acc[mi][ni], ah[mi], bl_[ni]);
                }
        }
        __syncthreads();
    }

#pragma unroll
    for (int mi = 0; mi < 2; mi++) {
#pragma unroll
        for (int ni = 0; ni < 4; ni++) {
            int dcol = h * DK + wn * 32 + ni * 8 + 2 * t;
#pragma unroll
            for (int hrow = 0; hrow < 2; hrow++) {
                int q = qt * 128 + wm * 32 + mi * 16 + g + hrow * 8;
                uint32_t lw;
                uint32_t hw = pack_split2(acc[mi][ni][hrow*2], acc[mi][ni][hrow*2+1], lw);
                size_t e = ((size_t)(b * NS + q) * NE + dcol) >> 1;
                ((uint32_t*)ch)[e] = hw;
                ((uint32_t*)cl)[e] = lw;
            }
        }
    }
}

// ===========================================================================
// x = LayerNorm(y1 [+ y2] + x) * g + b  (in place; writes split planes;
// optional extra fp32 destination xout e.g. final output buffer)
// ===========================================================================
__global__ void ln_kernel(const float* __restrict__ y1,
                          const float* __restrict__ y2,
                          float* __restrict__ xio,
                          float* __restrict__ xout,
                          const float* __restrict__ gamma,
                          const float* __restrict__ beta) {
    int row = blockIdx.x;
    __shared__ float buf[NE];
    __shared__ float red[8];
    int tid = threadIdx.x;

    float s = 0.f;
    for (int i = tid; i < NE; i += 256) {
        size_t o = (size_t)row * NE + i;
        float v = y1[o] + xio[o];
        if (y2) v += y2[o];
        buf[i] = v;
        s += v;
    }
#pragma unroll
    for (int o = 16; o; o >>= 1) s += __shfl_xor_sync(0xffffffffu, s, o);
    if ((tid & 31) == 0) red[tid >> 5] = s;
    __syncthreads();
    if (tid < 32) {
        float r = (tid < 8) ? red[tid] : 0.f;
#pragma unroll
        for (int o = 4; o; o >>= 1) r += __shfl_xor_sync(0xffffffffu, r, o);
        if (tid == 0) red[0] = r;
    }
    __syncthreads();
    float mean = red[0] * (1.0f / NE);
    __syncthreads();

    float vs = 0.f;
    for (int i = tid; i < NE; i += 256) {
        float d = buf[i] - mean;
        vs += d * d;
    }
#pragma unroll
    for (int o = 16; o; o >>= 1) vs += __shfl_xor_sync(0xffffffffu, vs, o);
    if ((tid & 31) == 0) red[tid >> 5] = vs;
    __syncthreads();
    if (tid < 32) {
        float r = (tid < 8) ? red[tid] : 0.f;
#pragma unroll
        for (int o = 4; o; o >>= 1) r += __shfl_xor_sync(0xffffffffu, r, o);
        if (tid == 0) red[0] = r;
    }
    __syncthreads();
    float rstd = rsqrtf(red[0] * (1.0f / NE) + EPS);

    for (int i = tid; i < NE; i += 256) {
        float v = (buf[i] - mean) * rstd * gamma[i] + beta[i];
        size_t o = (size_t)row * NE + i;
        xio[o] = v;
        if (xout) xout[o] = v;
        __nv_bfloat16 h, l;
        split1(v, h, l);
        g_xh[o] = h; g_xl[o] = l;
    }
}

// ===========================================================================
extern "C" void kernel_launch(void* const* d_in, const int* in_sizes, int n_in,
                              void* d_out, int out_size) {
    const float* x    = (const float*)d_in[0];
    const float* tpos = (const float*)d_in[1];
    const float* spos = (const float*)d_in[2];
    const float* Wq   = (const float*)d_in[3];
    const float* Wk   = (const float*)d_in[4];
    const float* Wv   = (const float*)d_in[5];
    const float* Wo   = (const float*)d_in[6];
    const float* ln1g = (const float*)d_in[7];
    const float* ln1b = (const float*)d_in[8];
    const float* W1   = (const float*)d_in[9];
    const float* W2   = (const float*)d_in[10];
    const float* ln2g = (const float*)d_in[11];
    const float* ln2b = (const float*)d_in[12];

    float* out      = (float*)d_out;
    float* attn_out = out + (size_t)NM * NE;

    float *px, *ptmp, *ptmp2;
    __nv_bfloat16 *pxh, *pxl, *pqkvh, *pqkvl, *pch, *pcl, *phh, *phl, *pah, *pal;
    __nv_bfloat16 *pwqkvh, *pwqkvl, *pwoh, *pwol, *pw1h, *pw1l, *pw2h, *pw2l;
    cudaGetSymbolAddress((void**)&px,    g_x);
    cudaGetSymbolAddress((void**)&ptmp,  g_tmp);
    cudaGetSymbolAddress((void**)&ptmp2, g_tmp2);
    cudaGetSymbolAddress((void**)&pxh,   g_xh);
    cudaGetSymbolAddress((void**)&pxl,   g_xl);
    cudaGetSymbolAddress((void**)&pqkvh, g_qkvh);
    cudaGetSymbolAddress((void**)&pqkvl, g_qkvl);
    cudaGetSymbolAddress((void**)&pch,   g_ch);
    cudaGetSymbolAddress((void**)&pcl,   g_cl);
    cudaGetSymbolAddress((void**)&phh,   g_hh);
    cudaGetSymbolAddress((void**)&phl,   g_hl);
    cudaGetSymbolAddress((void**)&pah,   g_ah);
    cudaGetSymbolAddress((void**)&pal,   g_al);
    cudaGetSymbolAddress((void**)&pwqkvh, g_wqkvh);
    cudaGetSymbolAddress((void**)&pwqkvl, g_wqkvl);
    cudaGetSymbolAddress((void**)&pwoh,  g_woh);
    cudaGetSymbolAddress((void**)&pwol,  g_wol);
    cudaGetSymbolAddress((void**)&pw1h,  g_w1h);
    cudaGetSymbolAddress((void**)&pw1l,  g_w1l);
    cudaGetSymbolAddress((void**)&pw2h,  g_w2h);
    cudaGetSymbolAddress((void**)&pw2l,  g_w2l);

    const int SM_P  = 2 * (128 + 64) * 80 * 3;       //  92,160
    const int SM_SC = 4 * 128 * 144;                 //  73,728
    const int SM_CX = 2 * 128 * 272 + 2 * 128 * 144; // 106,496

    cudaFuncSetAttribute((const void*)bf16_gemm<0,false>,
        cudaFuncAttributeMaxDynamicSharedMemorySize, SM_P);
    cudaFuncSetAttribute((const void*)bf16_gemm<1,false>,
        cudaFuncAttributeMaxDynamicSharedMemorySize, SM_P);
    cudaFuncSetAttribute((const void*)bf16_gemm<1,true>,
        cudaFuncAttributeMaxDynamicSharedMemorySize, SM_P);
    cudaFuncSetAttribute((const void*)scores_mma,
        cudaFuncAttributeMaxDynamicSharedMemorySize, SM_SC);
    cudaFuncSetAttribute((const void*)ctx_mma,
        cudaFuncAttributeMaxDynamicSharedMemorySize, SM_CX);

    add_pos_kernel<<<(NM * NE + 255) / 256, 256>>>(x, tpos, spos);
    pad_kernel<<<(NB * NS + 255) / 256, 256>>>();

    // batched weight transpose+split: 3 launches total
    {
        dim3 blk(32, 8);
        transpose_split_ee<<<dim3(NE/32, NE/32, NL*4), blk>>>(
            Wq, Wk, Wv, Wo, pwqkvh, pwqkvl, pwoh, pwol);
        transpose_split_w<<<dim3(DFF/32, NE/32, NL), blk>>>(W1, pw1h, pw1l, NE, DFF);
        transpose_split_w<<<dim3(NE/32, DFF/32, NL), blk>>>(W2, pw2h, pw2l, DFF, NE);
    }

    dim3 gQKV(NQKV / 64, NM / 128, 1);         // (36, 16)
    dim3 gWo(NE / 64, NM / 128, 2);            // (12, 16, 2) split-K merged
    dim3 gFF1(DFF / 64, NM / 128, 1);          // (48, 16)
    dim3 gFF2(NE / 64, NM / 128, 2);           // (12, 16, 2) split-K merged
    dim3 gScores(NS / 128, NS / 128, NB * NH); // (8, 8, 24)
    dim3 gSoft(NS, NB * NH);
    dim3 gCtx(NS / 128, NB * NH);              // (8, 24)

    for (int l = 0; l < NL; l++) {
        size_t oE = (size_t)l * NE * NE, oF = (size_t)l * NE * DFF;
        size_t oQ = (size_t)l * NQKV * NE;
        float* attn_l = attn_out + (size_t)l * NB * NH * NS * NS;
        float* xout2 = (l == NL - 1) ? out : nullptr;

        bf16_gemm<1,false><<<gQKV, 128, SM_P>>>(
            pxh, pxl, pwqkvh + oQ, pwqkvl + oQ,
            nullptr, nullptr, pqkvh, pqkvl, NM, NQKV, NE, NE, 0);

        scores_mma<<<gScores, 256, SM_SC>>>(pqkvh, pqkvl, attn_l);
        softmax_kernel<<<gSoft, 256>>>(attn_l, pah, pal);
        ctx_mma<<<gCtx, 256, SM_CX>>>(pah, pal, pqkvh, pqkvl, pch, pcl);

        // Wo split-K x2 in ONE launch (z selects half); halves summed in ln
        bf16_gemm<0,false><<<gWo, 128, SM_P>>>(
            pch, pcl, pwoh + oE, pwol + oE, ptmp, ptmp2, nullptr, nullptr,
            NM, NE, NE, 384, 384);
        ln_kernel<<<NM, 256>>>(ptmp, ptmp2, px, nullptr,
                               ln1g + (size_t)l * NE, ln1b + (size_t)l * NE);

        bf16_gemm<1,true><<<gFF1, 128, SM_P>>>(
            pxh, pxl, pw1h + oF, pw1l + oF, nullptr, nullptr, phh, phl,
            NM, DFF, NE, NE, 0);

        // FFN2 split-K x2 in ONE launch
        bf16_gemm<0,false><<<gFF2, 128, SM_P>>>(
            phh, phl, pw2h + oF, pw2l + oF, ptmp, ptmp2, nullptr, nullptr,
            NM, NE, DFF, 1536, 1536);
        ln_kernel<<<NM, 256>>>(ptmp, ptmp2, px, xout2,
                               ln2g + (size_t)l * NE, ln2b + (size_t)l * NE);
    }
}

// round 8
// speedup vs baseline: 2.4010x; 1.1149x over previous
#include <cuda_runtime.h>
#include <cuda_bf16.h>
#include <math.h>
#include <stdint.h>

#define NL 6
#define NB 2
#define NF 16
#define NT 64
#define NS 1024
#define NE 768
#define NH 12
#define DK 64
#define DFF 3072
#define NM (NB*NS)        // 2048 rows
#define NQKV 2304
#define EPS 1e-5f

// ---- scratch (allocation-free rule: __device__ globals) ----
__device__ float g_x[NM*NE];
__device__ float g_tmp[NM*NE];
__device__ float g_tmp2[NM*NE];
__device__ int   g_pad[NB*NS];
// bf16 split planes
__device__ __nv_bfloat16 g_xh[NM*NE],  g_xl[NM*NE];
__device__ __nv_bfloat16 g_qkvh[NM*NQKV], g_qkvl[NM*NQKV];
__device__ __nv_bfloat16 g_ch[NM*NE],  g_cl[NM*NE];            // ctx
__device__ __nv_bfloat16 g_hh[NM*DFF], g_hl[NM*DFF];           // hidden
__device__ __nv_bfloat16 g_ah[(size_t)NB*NH*NS*NS];            // attn hi
__device__ __nv_bfloat16 g_al[(size_t)NB*NH*NS*NS];            // attn lo
// K-major weight planes; QKV concatenated [2304 x 768]
__device__ __nv_bfloat16 g_wqkvh[NL*(size_t)NQKV*NE], g_wqkvl[NL*(size_t)NQKV*NE];
__device__ __nv_bfloat16 g_woh[NL*NE*NE],             g_wol[NL*NE*NE];
__device__ __nv_bfloat16 g_w1h[NL*(size_t)NE*DFF],    g_w1l[NL*(size_t)NE*DFF];
__device__ __nv_bfloat16 g_w2h[NL*(size_t)NE*DFF],    g_w2l[NL*(size_t)NE*DFF];

// ===========================================================================
// PTX helpers (base-sm_103 features only)
// ===========================================================================
__device__ __forceinline__ uint32_t smem_u32(const void* p) {
    uint32_t a;
    asm("{ .reg .u64 t; cvta.to.shared.u64 t, %1; cvt.u32.u64 %0, t; }"
        : "=r"(a) : "l"(p));
    return a;
}
__device__ __forceinline__ void cp16(uint32_t s, const void* g) {
    asm volatile("cp.async.cg.shared.global [%0], [%1], 16;" :: "r"(s), "l"(g));
}
__device__ __forceinline__ void cp_commit() {
    asm volatile("cp.async.commit_group;" ::: "memory");
}
template <int N>
__device__ __forceinline__ void cp_wait() {
    asm volatile("cp.async.wait_group %0;" :: "n"(N) : "memory");
}
__device__ __forceinline__ void ldsm4(uint32_t* r, uint32_t addr) {
    asm volatile("ldmatrix.sync.aligned.m8n8.x4.shared.b16 {%0,%1,%2,%3}, [%4];"
        : "=r"(r[0]), "=r"(r[1]), "=r"(r[2]), "=r"(r[3]) : "r"(addr));
}
__device__ __forceinline__ void ldsm2t(uint32_t* r, uint32_t addr) {
    asm volatile("ldmatrix.sync.aligned.m8n8.x2.trans.shared.b16 {%0,%1}, [%2];"
        : "=r"(r[0]), "=r"(r[1]) : "r"(addr));
}
__device__ __forceinline__ void mma16816(float* c, const uint32_t* a, const uint32_t* b) {
    asm volatile(
        "mma.sync.aligned.m16n8k16.row.col.f32.bf16.bf16.f32 "
        "{%0,%1,%2,%3},{%4,%5,%6,%7},{%8,%9},{%0,%1,%2,%3};"
        : "+f"(c[0]), "+f"(c[1]), "+f"(c[2]), "+f"(c[3])
        : "r"(a[0]), "r"(a[1]), "r"(a[2]), "r"(a[3]), "r"(b[0]), "r"(b[1]));
}
__device__ __forceinline__ void split1(float v, __nv_bfloat16& h, __nv_bfloat16& l) {
    h = __float2bfloat16_rn(v);
    l = __float2bfloat16_rn(v - __bfloat162float(h));
}
__device__ __forceinline__ uint32_t pack_split2(float x0, float x1,
                                                uint32_t& lw) {
    __nv_bfloat16 h0, l0, h1, l1;
    split1(x0, h0, l0); split1(x1, h1, l1);
    lw = (uint32_t)*(uint16_t*)&l0 | ((uint32_t)*(uint16_t*)&l1 << 16);
    return (uint32_t)*(uint16_t*)&h0 | ((uint32_t)*(uint16_t*)&h1 << 16);
}

// ===========================================================================
// Batched weight transpose + split.
// ===========================================================================
__device__ __forceinline__ void tr_body(const float* __restrict__ in,
                                        __nv_bfloat16* __restrict__ oh,
                                        __nv_bfloat16* __restrict__ ol,
                                        int R, int C) {
    __shared__ float tb[32][33];
    int c0 = blockIdx.x * 32, r0 = blockIdx.y * 32;
    int x = threadIdx.x, y = threadIdx.y;   // 32 x 8
#pragma unroll
    for (int i = 0; i < 32; i += 8)
        tb[y + i][x] = in[(size_t)(r0 + y + i) * C + c0 + x];
    __syncthreads();
#pragma unroll
    for (int i = 0; i < 32; i += 8) {
        float v = tb[x][y + i];
        __nv_bfloat16 h, l;
        split1(v, h, l);
        size_t o = (size_t)(c0 + y + i) * R + r0 + x;
        oh[o] = h; ol[o] = l;
    }
}

__global__ void transpose_split_ee(const float* __restrict__ Wq,
                                   const float* __restrict__ Wk,
                                   const float* __restrict__ Wv,
                                   const float* __restrict__ Wo,
                                   __nv_bfloat16* __restrict__ wqkvh,
                                   __nv_bfloat16* __restrict__ wqkvl,
                                   __nv_bfloat16* __restrict__ woh,
                                   __nv_bfloat16* __restrict__ wol) {
    int zc = blockIdx.z, l = zc >> 2, kind = zc & 3;
    size_t oE = (size_t)l * NE * NE;
    size_t oQ = (size_t)l * NQKV * NE;
    const float* in;
    __nv_bfloat16 *oh, *ol;
    if (kind == 0)      { in = Wq + oE; oh = wqkvh + oQ;                    ol = wqkvl + oQ; }
    else if (kind == 1) { in = Wk + oE; oh = wqkvh + oQ + (size_t)NE*NE;    ol = wqkvl + oQ + (size_t)NE*NE; }
    else if (kind == 2) { in = Wv + oE; oh = wqkvh + oQ + (size_t)2*NE*NE;  ol = wqkvl + oQ + (size_t)2*NE*NE; }
    else                { in = Wo + oE; oh = woh + oE;                      ol = wol + oE; }
    tr_body(in, oh, ol, NE, NE);
}

__global__ void transpose_split_w(const float* __restrict__ in0,
                                  __nv_bfloat16* __restrict__ oh0,
                                  __nv_bfloat16* __restrict__ ol0,
                                  int R, int C) {
    size_t off = (size_t)blockIdx.z * NE * DFF;
    tr_body(in0 + off, oh0 + off, ol0 + off, R, C);
}

// ===========================================================================
// bf16x3 mma GEMM (unchanged from round 7)
// ===========================================================================
template <int MODE, bool RELU>
__global__ void __launch_bounds__(128, 2)
bf16_gemm(const __nv_bfloat16* __restrict__ Ah, const __nv_bfloat16* __restrict__ Al,
          const __nv_bfloat16* __restrict__ Bh, const __nv_bfloat16* __restrict__ Bl,
          float* __restrict__ C, float* __restrict__ C2,
          __nv_bfloat16* __restrict__ Ch, __nv_bfloat16* __restrict__ Cl,
          int M, int N, int ldk, int lenK, int ksh) {
    constexpr int BM = 128, BN = 64, WM = 64, WN = 32;
    constexpr int MI = WM / 16;   // 4
    constexpr int NI = WN / 8;    // 4
    constexpr int WGN = BN / WN;  // 2
    constexpr int ROWS = 2 * (BM + BN);      // 384
    constexpr uint32_t SSTR = (uint32_t)ROWS * 80;
    constexpr uint32_t OFF_AH = 0;
    constexpr uint32_t OFF_AL = (uint32_t)BM * 80;
    constexpr uint32_t OFF_BH = (uint32_t)(2 * BM) * 80;
    constexpr uint32_t OFF_BL = (uint32_t)(2 * BM + BN) * 80;

    if (blockIdx.z) { Ah += ksh; Al += ksh; Bh += ksh; Bl += ksh; C = C2; }

    extern __shared__ char smem[];
    uint32_t sbase = smem_u32(smem);
    int tid = threadIdx.x, lane = tid & 31, wid = tid >> 5;
    int wn = wid % WGN, wm = wid / WGN;
    int g = lane >> 2, t = lane & 3;
    int m0 = blockIdx.y * BM, n0 = blockIdx.x * BN;
    const int nk = lenK >> 5;

    auto load_stage = [&](int stage, int k0) {
        uint32_t dst0 = sbase + (uint32_t)stage * SSTR;
#pragma unroll
        for (int idx = tid; idx < ROWS * 4; idx += 128) {
            int r = idx >> 2, c = idx & 3;
            const __nv_bfloat16* src;
            if (r < BM)               src = Ah + (size_t)(m0 + r) * ldk;
            else if (r < 2 * BM)      src = Al + (size_t)(m0 + r - BM) * ldk;
            else if (r < 2 * BM + BN) src = Bh + (size_t)(n0 + r - 2 * BM) * ldk;
            else                      src = Bl + (size_t)(n0 + r - 2 * BM - BN) * ldk;
            cp16(dst0 + (uint32_t)(r * 80 + c * 16), src + k0 + c * 8);
        }
    };

    uint32_t aRel = (uint32_t)((wm * WM + (lane & 15)) * 80 + ((lane >> 4) & 1) * 16);
    uint32_t bRel = (uint32_t)((wn * WN + (lane & 7) + ((lane >> 4) << 3)) * 80
                               + ((lane >> 3) & 1) * 16);

#pragma unroll
    for (int s = 0; s < 3; s++) { load_stage(s, s * 32); cp_commit(); }

    float acc[MI][NI][4];
#pragma unroll
    for (int mi = 0; mi < MI; mi++)
#pragma unroll
        for (int ni = 0; ni < NI; ni++)
#pragma unroll
            for (int j = 0; j < 4; j++) acc[mi][ni][j] = 0.f;

    for (int kc = 0; kc < nk; kc++) {
        int s = kc % 3;
        cp_wait<2>();
        __syncthreads();
        uint32_t stg = sbase + (uint32_t)s * SSTR;

        uint32_t ah[2][MI][4], al[2][MI][4];
        uint32_t bh[2][NI][2], bl[2][NI][2];
#pragma unroll
        for (int u = 0; u < 2; u++) {
            uint32_t koff = (uint32_t)(u * 32);
#pragma unroll
            for (int mi = 0; mi < MI; mi++) {
                ldsm4(ah[u][mi], stg + OFF_AH + aRel + mi * (16 * 80) + koff);
                ldsm4(al[u][mi], stg + OFF_AL + aRel + mi * (16 * 80) + koff);
            }
#pragma unroll
            for (int n2 = 0; n2 < NI / 2; n2++) {
                uint32_t r4[4];
                ldsm4(r4, stg + OFF_BH + bRel + n2 * (16 * 80) + koff);
                bh[u][2*n2][0] = r4[0]; bh[u][2*n2][1] = r4[1];
                bh[u][2*n2+1][0] = r4[2]; bh[u][2*n2+1][1] = r4[3];
                ldsm4(r4, stg + OFF_BL + bRel + n2 * (16 * 80) + koff);
                bl[u][2*n2][0] = r4[0]; bl[u][2*n2][1] = r4[1];
                bl[u][2*n2+1][0] = r4[2]; bl[u][2*n2+1][1] = r4[3];
            }
        }
#pragma unroll
        for (int u = 0; u < 2; u++)
#pragma unroll
            for (int mi = 0; mi < MI; mi++)
#pragma unroll
                for (int ni = 0; ni < NI; ni++) {
                    mma16816(acc[mi][ni], ah[u][mi], bh[u][ni]);
                    mma16816(acc[mi][ni], al[u][mi], bh[u][ni]);
                    mma16816(acc[mi][ni], ah[u][mi], bl[u][ni]);
                }
        __syncthreads();
        if (kc + 3 < nk) load_stage(s, (kc + 3) * 32);
        cp_commit();
    }

#pragma unroll
    for (int mi = 0; mi < MI; mi++) {
        int row0 = m0 + wm * WM + mi * 16 + g;
#pragma unroll
        for (int ni = 0; ni < NI; ni++) {
            int col = n0 + wn * WN + ni * 8 + 2 * t;
            if (MODE == 0) {
                float2 v0, v1;
                v0.x = acc[mi][ni][0]; v0.y = acc[mi][ni][1];
                v1.x = acc[mi][ni][2]; v1.y = acc[mi][ni][3];
                *(float2*)(C + (size_t)row0 * N + col)       = v0;
                *(float2*)(C + (size_t)(row0 + 8) * N + col) = v1;
            } else {
#pragma unroll
                for (int hrow = 0; hrow < 2; hrow++) {
                    int row = row0 + hrow * 8;
                    float x0 = acc[mi][ni][hrow*2+0];
                    float x1 = acc[mi][ni][hrow*2+1];
                    if (RELU) { x0 = fmaxf(x0, 0.f); x1 = fmaxf(x1, 0.f); }
                    uint32_t lw;
                    uint32_t hw = pack_split2(x0, x1, lw);
                    size_t e = ((size_t)row * N + col) >> 1;
                    ((uint32_t*)Ch)[e] = hw;
                    ((uint32_t*)Cl)[e] = lw;
                }
            }
        }
    }
}

// ===========================================================================
// x = x_in + t_pos + s_pos  (+ bf16 split planes), float4 vectorized
// ===========================================================================
__global__ void add_pos_kernel(const float* __restrict__ x,
                               const float* __restrict__ tpos,
                               const float* __restrict__ spos) {
    int i4 = blockIdx.x * blockDim.x + threadIdx.x;
    if (i4 >= NM * NE / 4) return;
    int i = i4 * 4;
    int e = i % NE;
    int s = (i / NE) % NS;
    float4 xv = *(const float4*)(x + i);
    float4 tv = *(const float4*)(tpos + (s / NT) * NE + e);
    float4 sv = *(const float4*)(spos + (s % NT) * NE + e);
    float4 v;
    v.x = xv.x + tv.x + sv.x; v.y = xv.y + tv.y + sv.y;
    v.z = xv.z + tv.z + sv.z; v.w = xv.w + tv.w + sv.w;
    *(float4*)(g_x + i) = v;
    uint32_t lw0, lw1;
    uint32_t hw0 = pack_split2(v.x, v.y, lw0);
    uint32_t hw1 = pack_split2(v.z, v.w, lw1);
    uint2 hv, lv;
    hv.x = hw0; hv.y = hw1; lv.x = lw0; lv.y = lw1;
    *(uint2*)((uint32_t*)g_xh + i4 * 2) = hv;
    *(uint2*)((uint32_t*)g_xl + i4 * 2) = lv;
}

__global__ void pad_kernel() {
    int i = blockIdx.x * blockDim.x + threadIdx.x;
    if (i < NB * NS) g_pad[i] = (g_x[(size_t)i * NE] == 0.0f) ? 1 : 0;
}

// ===========================================================================
// scores_mma: 128x128 tile of q.k^T * scale, causal+pad masked -> fp32 attn.
// ===========================================================================
__global__ void __launch_bounds__(256)
scores_mma(const __nv_bfloat16* __restrict__ qkvh,
           const __nv_bfloat16* __restrict__ qkvl,
           float* __restrict__ attn) {
    int kt = blockIdx.x, qt = blockIdx.y, bh = blockIdx.z;
    if (kt > qt) return;
    int b = bh / NH, h = bh % NH;

    extern __shared__ char smem[];
    uint32_t sb = smem_u32(smem);
    const uint32_t QH = 0, QL = 128*144, KH = 2*128*144, KL = 3*128*144;

    int tid = threadIdx.x, lane = tid & 31, wid = tid >> 5;
    int wm = wid >> 1, wn = wid & 1;
    int g = lane >> 2, t = lane & 3;

    for (int idx = tid; idx < 128 * 8; idx += 256) {
        int r = idx >> 3, c = idx & 7;
        size_t qrow = (size_t)(b * NS + qt * 128 + r) * NQKV + h * DK + c * 8;
        size_t krow = (size_t)(b * NS + kt * 128 + r) * NQKV + NE + h * DK + c * 8;
        uint32_t d = (uint32_t)(r * 144 + c * 16);
        cp16(sb + QH + d, qkvh + qrow);
        cp16(sb + QL + d, qkvl + qrow);
        cp16(sb + KH + d, qkvh + krow);
        cp16(sb + KL + d, qkvl + krow);
    }
    cp_commit();
    cp_wait<0>();
    __syncthreads();

    uint32_t aRel = (uint32_t)((wm * 32 + (lane & 15)) * 144 + ((lane >> 4) & 1) * 16);
    uint32_t bRel = (uint32_t)((wn * 64 + (lane & 7) + ((lane >> 4) << 3)) * 144
                               + ((lane >> 3) & 1) * 16);

    float acc[2][8][4];
#pragma unroll
    for (int mi = 0; mi < 2; mi++)
#pragma unroll
        for (int ni = 0; ni < 8; ni++)
#pragma unroll
            for (int j = 0; j < 4; j++) acc[mi][ni][j] = 0.f;

#pragma unroll
    for (int kk = 0; kk < 4; kk++) {
        uint32_t koff = (uint32_t)(kk * 32);
        uint32_t ah[2][4], al[2][4];
#pragma unroll
        for (int mi = 0; mi < 2; mi++) {
            ldsm4(ah[mi], sb + QH + aRel + mi * (16 * 144) + koff);
            ldsm4(al[mi], sb + QL + aRel + mi * (16 * 144) + koff);
        }
        uint32_t bh_[8][2], bl_[8][2];
#pragma unroll
        for (int n2 = 0; n2 < 4; n2++) {
            uint32_t r4[4];
            ldsm4(r4, sb + KH + bRel + n2 * (16 * 144) + koff);
            bh_[2*n2][0] = r4[0]; bh_[2*n2][1] = r4[1];
            bh_[2*n2+1][0] = r4[2]; bh_[2*n2+1][1] = r4[3];
            ldsm4(r4, sb + KL + bRel + n2 * (16 * 144) + koff);
            bl_[2*n2][0] = r4[0]; bl_[2*n2][1] = r4[1];
            bl_[2*n2+1][0] = r4[2]; bl_[2*n2+1][1] = r4[3];
        }
#pragma unroll
        for (int mi = 0; mi < 2; mi++)
#pragma unroll
            for (int ni = 0; ni < 8; ni++) {
                mma16816(acc[mi][ni], ah[mi], bh_[ni]);
                mma16816(acc[mi][ni], al[mi], bh_[ni]);
                mma16816(acc[mi][ni], ah[mi], bl_[ni]);
            }
    }

    float* out = attn + (size_t)bh * NS * NS;
    const float scale = 0.125f;
#pragma unroll
    for (int mi = 0; mi < 2; mi++) {
#pragma unroll
        for (int hrow = 0; hrow < 2; hrow++) {
            int qi = qt * 128 + wm * 32 + mi * 16 + g + hrow * 8;
#pragma unroll
            for (int ni = 0; ni < 8; ni++) {
                int ki = kt * 128 + wn * 64 + ni * 8 + 2 * t;
                float v0 = acc[mi][ni][hrow*2+0] * scale;
                float v1 = acc[mi][ni][hrow*2+1] * scale;
                if (ki     > qi || g_pad[b * NS + ki])     v0 = -1e9f;
                if (ki + 1 > qi || g_pad[b * NS + ki + 1]) v1 = -1e9f;
                float2 v; v.x = v0; v.y = v1;
                *(float2*)(out + (size_t)qi * NS + ki) = v;
            }
        }
    }
}

// ===========================================================================
// Warp-per-row softmax. Each warp owns one row; lane j4 slots cover NS=1024
// (8 float4 per lane). Writes fp32 probs (incl causal zeros) + bf16 planes
// (zero-padded to the 128-tile boundary). No smem, shuffle reductions only.
// grid (NS/8, NB*NH), 256 threads.
// ===========================================================================
__global__ void __launch_bounds__(256)
softmax_kernel(float* __restrict__ attn,
               __nv_bfloat16* __restrict__ ph,
               __nv_bfloat16* __restrict__ pl) {
    int wid = threadIdx.x >> 5, lane = threadIdx.x & 31;
    int q  = blockIdx.x * 8 + wid;
    int bh = blockIdx.y;
    size_t pbase = (size_t)bh * NS * NS + (size_t)q * NS;
    float* row = attn + pbase;
    int n = q + 1;
    int npad = (n + 127) & ~127;

    float4 v[8];
    float m = -1e30f;
#pragma unroll
    for (int j = 0; j < 8; j++) {
        int e0 = (lane + 32 * j) * 4;
        if (e0 < n) {
            float4 tv = *(const float4*)(row + e0);
            v[j].x = tv.x;
            v[j].y = (e0 + 1 < n) ? tv.y : -1e30f;
            v[j].z = (e0 + 2 < n) ? tv.z : -1e30f;
            v[j].w = (e0 + 3 < n) ? tv.w : -1e30f;
        } else {
            v[j].x = -1e30f; v[j].y = -1e30f; v[j].z = -1e30f; v[j].w = -1e30f;
        }
        m = fmaxf(m, fmaxf(fmaxf(v[j].x, v[j].y), fmaxf(v[j].z, v[j].w)));
    }
#pragma unroll
    for (int o = 16; o; o >>= 1) m = fmaxf(m, __shfl_xor_sync(0xffffffffu, m, o));

    float s = 0.f;
#pragma unroll
    for (int j = 0; j < 8; j++) {
        v[j].x = __expf(v[j].x - m);
        v[j].y = __expf(v[j].y - m);
        v[j].z = __expf(v[j].z - m);
        v[j].w = __expf(v[j].w - m);
        s += (v[j].x + v[j].y) + (v[j].z + v[j].w);
    }
#pragma unroll
    for (int o = 16; o; o >>= 1) s += __shfl_xor_sync(0xffffffffu, s, o);
    float inv = 1.0f / s;

#pragma unroll
    for (int j = 0; j < 8; j++) {
        int e0 = (lane + 32 * j) * 4;
        float4 p;
        p.x = v[j].x * inv; p.y = v[j].y * inv;
        p.z = v[j].z * inv; p.w = v[j].w * inv;
        *(float4*)(row + e0) = p;             // probs for i<n, exact 0 beyond
        if (e0 < npad) {
            uint32_t lw0, lw1;
            uint32_t hw0 = pack_split2(p.x, p.y, lw0);
            uint32_t hw1 = pack_split2(p.z, p.w, lw1);
            uint2 hv, lv;
            hv.x = hw0; hv.y = hw1; lv.x = lw0; lv.y = lw1;
            *(uint2*)((uint32_t*)ph + ((pbase + e0) >> 1)) = hv;
            *(uint2*)((uint32_t*)pl + ((pbase + e0) >> 1)) = lv;
        }
    }
}

// ===========================================================================
// ctx_mma: ctx[128q x 64d] = attn_planes @ v_planes (causal kt loop).
// Double-buffered across kt tiles (load kt+1 under compute kt).
// ===========================================================================
#define CTX_SSTR (2*128*272 + 2*128*144)   // 106,496 bytes per stage

__global__ void __launch_bounds__(256)
ctx_mma(const __nv_bfloat16* __restrict__ ph, const __nv_bfloat16* __restrict__ pl,
        const __nv_bfloat16* __restrict__ qkvh, const __nv_bfloat16* __restrict__ qkvl,
        __nv_bfloat16* __restrict__ ch, __nv_bfloat16* __restrict__ cl) {
    int qt = (int)gridDim.x - 1 - (int)blockIdx.x;   // heavy tiles first
    int bh = blockIdx.y;
    int b = bh / NH, h = bh % NH;

    extern __shared__ char smem[];
    uint32_t sb = smem_u32(smem);
    const uint32_t AH = 0, AL = 128*272, VH = 2*128*272, VL = 2*128*272 + 128*144;

    int tid = threadIdx.x, lane = tid & 31, wid = tid >> 5;
    int wm = wid >> 1, wn = wid & 1;
    int g = lane >> 2, t = lane & 3;

    uint32_t aRel = (uint32_t)((wm * 32 + (lane & 15)) * 272 + ((lane >> 4) & 1) * 16);

    auto load_tile = [&](int kt, int st) {
        uint32_t base = sb + (uint32_t)st * CTX_SSTR;
        for (int idx = tid; idx < 128 * 16; idx += 256) {
            int r = idx >> 4, c = idx & 15;
            size_t arow = (size_t)bh * NS * NS + (size_t)(qt * 128 + r) * NS
                        + kt * 128 + c * 8;
            uint32_t d = (uint32_t)(r * 272 + c * 16);
            cp16(base + AH + d, ph + arow);
            cp16(base + AL + d, pl + arow);
        }
        for (int idx = tid; idx < 128 * 8; idx += 256) {
            int r = idx >> 3, c = idx & 7;
            size_t vrow = (size_t)(b * NS + kt * 128 + r) * NQKV + 1536 + h * DK + c * 8;
            uint32_t d = (uint32_t)(r * 144 + c * 16);
            cp16(base + VH + d, qkvh + vrow);
            cp16(base + VL + d, qkvl + vrow);
        }
    };

    float acc[2][4][4];
#pragma unroll
    for (int mi = 0; mi < 2; mi++)
#pragma unroll
        for (int ni = 0; ni < 4; ni++)
#pragma unroll
            for (int j = 0; j < 4; j++) acc[mi][ni][j] = 0.f;

    load_tile(0, 0);
    cp_commit();

    for (int kt = 0; kt <= qt; kt++) {
        int s = kt & 1;
        if (kt < qt) load_tile(kt + 1, s ^ 1);
        cp_commit();
        cp_wait<1>();
        __syncthreads();
        uint32_t base = sb + (uint32_t)s * CTX_SSTR;

#pragma unroll
        for (int kk = 0; kk < 8; kk++) {
            uint32_t koff = (uint32_t)(kk * 32);
            uint32_t ah[2][4], al[2][4];
#pragma unroll
            for (int mi = 0; mi < 2; mi++) {
                ldsm4(ah[mi], base + AH + aRel + mi * (16 * 272) + koff);
                ldsm4(al[mi], base + AL + aRel + mi * (16 * 272) + koff);
            }
            uint32_t vrowRel = (uint32_t)((kk * 16 + (lane & 15)) * 144);
            uint32_t bh_[4][2], bl_[4][2];
#pragma unroll
            for (int ni = 0; ni < 4; ni++) {
                uint32_t coff = (uint32_t)((wn * 32 + ni * 8) * 2);
                ldsm2t(bh_[ni], base + VH + vrowRel + coff);
                ldsm2t(bl_[ni], base + VL + vrowRel + coff);
            }
#pragma unroll
            for (int mi = 0; mi < 2; mi++)
#pragma unroll
                for (int ni = 0; ni < 4; ni++) {
                    mma16816(acc[mi][ni], ah[mi], bh_[ni]);
                    mma16816(acc[mi][ni], al[mi], bh_[ni]);
                    mma16816(acc[mi][ni], ah[mi], bl_[ni]);
                }
        }
        __syncthreads();
    }

#pragma unroll
    for (int mi = 0; mi < 2; mi++) {
#pragma unroll
        for (int ni = 0; ni < 4; ni++) {
            int dcol = h * DK + wn * 32 + ni * 8 + 2 * t;
#pragma unroll
            for (int hrow = 0; hrow < 2; hrow++) {
                int q = qt * 128 + wm * 32 + mi * 16 + g + hrow * 8;
                uint32_t lw;
                uint32_t hw = pack_split2(acc[mi][ni][hrow*2], acc[mi][ni][hrow*2+1], lw);
                size_t e = ((size_t)(b * NS + q) * NE + dcol) >> 1;
                ((uint32_t*)ch)[e] = hw;
                ((uint32_t*)cl)[e] = lw;
            }
        }
    }
}

// ===========================================================================
// x = LayerNorm(y1 [+ y2] + x) * g + b  (float4 vectorized; writes planes;
// optional extra fp32 destination xout)
// ===========================================================================
__global__ void ln_kernel(const float* __restrict__ y1,
                          const float* __restrict__ y2,
                          float* __restrict__ xio,
                          float* __restrict__ xout,
                          const float* __restrict__ gamma,
                          const float* __restrict__ beta) {
    int row = blockIdx.x;
    __shared__ float buf[NE];
    __shared__ float red[8];
    int tid = threadIdx.x;
    size_t rbase = (size_t)row * NE;

    float s = 0.f;
    if (tid < 192) {
        int i = tid * 4;
        float4 a = *(const float4*)(y1 + rbase + i);
        float4 c = *(const float4*)(xio + rbase + i);
        float4 v;
        v.x = a.x + c.x; v.y = a.y + c.y; v.z = a.z + c.z; v.w = a.w + c.w;
        if (y2) {
            float4 d = *(const float4*)(y2 + rbase + i);
            v.x += d.x; v.y += d.y; v.z += d.z; v.w += d.w;
        }
        *(float4*)(buf + i) = v;
        s = (v.x + v.y) + (v.z + v.w);
    }
#pragma unroll
    for (int o = 16; o; o >>= 1) s += __shfl_xor_sync(0xffffffffu, s, o);
    if ((tid & 31) == 0) red[tid >> 5] = s;
    __syncthreads();
    if (tid < 32) {
        float r = (tid < 8) ? red[tid] : 0.f;
#pragma unroll
        for (int o = 4; o; o >>= 1) r += __shfl_xor_sync(0xffffffffu, r, o);
        if (tid == 0) red[0] = r;
    }
    __syncthreads();
    float mean = red[0] * (1.0f / NE);
    __syncthreads();

    float vs = 0.f;
    if (tid < 192) {
        float4 v = *(const float4*)(buf + tid * 4);
        float dx = v.x - mean, dy = v.y - mean, dz = v.z - mean, dw = v.w - mean;
        vs = (dx * dx + dy * dy) + (dz * dz + dw * dw);
    }
#pragma unroll
    for (int o = 16; o; o >>= 1) vs += __shfl_xor_sync(0xffffffffu, vs, o);
    if ((tid & 31) == 0) red[tid >> 5] = vs;
    __syncthreads();
    if (tid < 32) {
        float r = (tid < 8) ? red[tid] : 0.f;
#pragma unroll
        for (int o = 4; o; o >>= 1) r += __shfl_xor_sync(0xffffffffu, r, o);
        if (tid == 0) red[0] = r;
    }
    __syncthreads();
    float rstd = rsqrtf(red[0] * (1.0f / NE) + EPS);

    if (tid < 192) {
        int i = tid * 4;
        float4 v = *(const float4*)(buf + i);
        float4 gm = *(const float4*)(gamma + i);
        float4 bt = *(const float4*)(beta + i);
        float4 o;
        o.x = (v.x - mean) * rstd * gm.x + bt.x;
        o.y = (v.y - mean) * rstd * gm.y + bt.y;
        o.z = (v.z - mean) * rstd * gm.z + bt.z;
        o.w = (v.w - mean) * rstd * gm.w + bt.w;
        *(float4*)(xio + rbase + i) = o;
        if (xout) *(float4*)(xout + rbase + i) = o;
        uint32_t lw0, lw1;
        uint32_t hw0 = pack_split2(o.x, o.y, lw0);
        uint32_t hw1 = pack_split2(o.z, o.w, lw1);
        uint2 hv, lv;
        hv.x = hw0; hv.y = hw1; lv.x = lw0; lv.y = lw1;
        *(uint2*)((uint32_t*)g_xh + ((rbase + i) >> 1)) = hv;
        *(uint2*)((uint32_t*)g_xl + ((rbase + i) >> 1)) = lv;
    }
}

// ===========================================================================
extern "C" void kernel_launch(void* const* d_in, const int* in_sizes, int n_in,
                              void* d_out, int out_size) {
    const float* x    = (const float*)d_in[0];
    const float* tpos = (const float*)d_in[1];
    const float* spos = (const float*)d_in[2];
    const float* Wq   = (const float*)d_in[3];
    const float* Wk   = (const float*)d_in[4];
    const float* Wv   = (const float*)d_in[5];
    const float* Wo   = (const float*)d_in[6];
    const float* ln1g = (const float*)d_in[7];
    const float* ln1b = (const float*)d_in[8];
    const float* W1   = (const float*)d_in[9];
    const float* W2   = (const float*)d_in[10];
    const float* ln2g = (const float*)d_in[11];
    const float* ln2b = (const float*)d_in[12];

    float* out      = (float*)d_out;
    float* attn_out = out + (size_t)NM * NE;

    float *px, *ptmp, *ptmp2;
    __nv_bfloat16 *pxh, *pxl, *pqkvh, *pqkvl, *pch, *pcl, *phh, *phl, *pah, *pal;
    __nv_bfloat16 *pwqkvh, *pwqkvl, *pwoh, *pwol, *pw1h, *pw1l, *pw2h, *pw2l;
    cudaGetSymbolAddress((void**)&px,    g_x);
    cudaGetSymbolAddress((void**)&ptmp,  g_tmp);
    cudaGetSymbolAddress((void**)&ptmp2, g_tmp2);
    cudaGetSymbolAddress((void**)&pxh,   g_xh);
    cudaGetSymbolAddress((void**)&pxl,   g_xl);
    cudaGetSymbolAddress((void**)&pqkvh, g_qkvh);
    cudaGetSymbolAddress((void**)&pqkvl, g_qkvl);
    cudaGetSymbolAddress((void**)&pch,   g_ch);
    cudaGetSymbolAddress((void**)&pcl,   g_cl);
    cudaGetSymbolAddress((void**)&phh,   g_hh);
    cudaGetSymbolAddress((void**)&phl,   g_hl);
    cudaGetSymbolAddress((void**)&pah,   g_ah);
    cudaGetSymbolAddress((void**)&pal,   g_al);
    cudaGetSymbolAddress((void**)&pwqkvh, g_wqkvh);
    cudaGetSymbolAddress((void**)&pwqkvl, g_wqkvl);
    cudaGetSymbolAddress((void**)&pwoh,  g_woh);
    cudaGetSymbolAddress((void**)&pwol,  g_wol);
    cudaGetSymbolAddress((void**)&pw1h,  g_w1h);
    cudaGetSymbolAddress((void**)&pw1l,  g_w1l);
    cudaGetSymbolAddress((void**)&pw2h,  g_w2h);
    cudaGetSymbolAddress((void**)&pw2l,  g_w2l);

    const int SM_P  = 2 * (128 + 64) * 80 * 3;       //  92,160
    const int SM_SC = 4 * 128 * 144;                 //  73,728
    const int SM_CX = 2 * CTX_SSTR;                  // 212,992

    cudaFuncSetAttribute((const void*)bf16_gemm<0,false>,
        cudaFuncAttributeMaxDynamicSharedMemorySize, SM_P);
    cudaFuncSetAttribute((const void*)bf16_gemm<1,false>,
        cudaFuncAttributeMaxDynamicSharedMemorySize, SM_P);
    cudaFuncSetAttribute((const void*)bf16_gemm<1,true>,
        cudaFuncAttributeMaxDynamicSharedMemorySize, SM_P);
    cudaFuncSetAttribute((const void*)scores_mma,
        cudaFuncAttributeMaxDynamicSharedMemorySize, SM_SC);
    cudaFuncSetAttribute((const void*)ctx_mma,
        cudaFuncAttributeMaxDynamicSharedMemorySize, SM_CX);

    add_pos_kernel<<<(NM * NE / 4 + 255) / 256, 256>>>(x, tpos, spos);
    pad_kernel<<<(NB * NS + 255) / 256, 256>>>();

    {
        dim3 blk(32, 8);
        transpose_split_ee<<<dim3(NE/32, NE/32, NL*4), blk>>>(
            Wq, Wk, Wv, Wo, pwqkvh, pwqkvl, pwoh, pwol);
        transpose_split_w<<<dim3(DFF/32, NE/32, NL), blk>>>(W1, pw1h, pw1l, NE, DFF);
        transpose_split_w<<<dim3(NE/32, DFF/32, NL), blk>>>(W2, pw2h, pw2l, DFF, NE);
    }

    dim3 gQKV(NQKV / 64, NM / 128, 1);         // (36, 16)
    dim3 gWo(NE / 64, NM / 128, 2);            // (12, 16, 2) split-K merged
    dim3 gFF1(DFF / 64, NM / 128, 1);          // (48, 16)
    dim3 gFF2(NE / 64, NM / 128, 2);           // (12, 16, 2) split-K merged
    dim3 gScores(NS / 128, NS / 128, NB * NH); // (8, 8, 24)
    dim3 gSoft(NS / 8, NB * NH);               // (128, 24) warp-per-row
    dim3 gCtx(NS / 128, NB * NH);              // (8, 24)

    for (int l = 0; l < NL; l++) {
        size_t oE = (size_t)l * NE * NE, oF = (size_t)l * NE * DFF;
        size_t oQ = (size_t)l * NQKV * NE;
        float* attn_l = attn_out + (size_t)l * NB * NH * NS * NS;
        float* xout2 = (l == NL - 1) ? out : nullptr;

        bf16_gemm<1,false><<<gQKV, 128, SM_P>>>(
            pxh, pxl, pwqkvh + oQ, pwqkvl + oQ,
            nullptr, nullptr, pqkvh, pqkvl, NM, NQKV, NE, NE, 0);

        scores_mma<<<gScores, 256, SM_SC>>>(pqkvh, pqkvl, attn_l);
        softmax_kernel<<<gSoft, 256>>>(attn_l, pah, pal);
        ctx_mma<<<gCtx, 256, SM_CX>>>(pah, pal, pqkvh, pqkvl, pch, pcl);

        bf16_gemm<0,false><<<gWo, 128, SM_P>>>(
            pch, pcl, pwoh + oE, pwol + oE, ptmp, ptmp2, nullptr, nullptr,
            NM, NE, NE, 384, 384);
        ln_kernel<<<NM, 256>>>(ptmp, ptmp2, px, nullptr,
                               ln1g + (size_t)l * NE, ln1b + (size_t)l * NE);

        bf16_gemm<1,true><<<gFF1, 128, SM_P>>>(
            pxh, pxl, pw1h + oF, pw1l + oF, nullptr, nullptr, phh, phl,
            NM, DFF, NE, NE, 0);

        bf16_gemm<0,false><<<gFF2, 128, SM_P>>>(
            phh, phl, pw2h + oF, pw2l + oF, ptmp, ptmp2, nullptr, nullptr,
            NM, NE, DFF, 1536, 1536);
        ln_kernel<<<NM, 256>>>(ptmp, ptmp2, px, xout2,
                               ln2g + (size_t)l * NE, ln2b + (size_t)l * NE);
    }
}